// round 9
// baseline (speedup 1.0000x reference)
#include <cuda_runtime.h>
#include <cuda_bf16.h>
#include <math.h>
#include <stdint.h>

#define D 128
#define NN 8192
#define NE 16384
#define NS 4096
#define NG 256
#define OPS 105
#define NSTEPS 12
#define ATS 68
#define NB 128          // persistent grid blocks

typedef unsigned long long ull;

// ---------------- scratch ----------------
__device__ float d_h[NN*D], d_h2[NN*D], d_m[NN*D];
__device__ float d_sg[NS*D], d_se[NS*D], d_s1[NS*D];
__device__ float d_gm[NG*D], d_g1[NG*D];
__device__ int   d_deg[NN], d_off[NN+1], d_cur[NN], d_csr[NE];
__device__ float d_invdeg[NN];
__device__ __nv_bfloat16 d_bwh[7*16384], d_bwl[7*16384];
__device__ unsigned g_cnt=0, g_epoch=0;

// ---------------- helpers ----------------
__device__ __forceinline__ ull pack2(float x){unsigned u=__float_as_uint(x);ull r;asm("mov.b64 %0,{%1,%1};":"=l"(r):"r"(u));return r;}
__device__ __forceinline__ void fma2(ull&a,ull x,ull y){asm("fma.rn.f32x2 %0,%1,%2,%0;":"+l"(a):"l"(x),"l"(y));}
__device__ __forceinline__ float lo32(ull v){return __uint_as_float((unsigned)v);}
__device__ __forceinline__ float hi32(ull v){return __uint_as_float((unsigned)(v>>32));}
__device__ __forceinline__ float lrelu(float v){return v>0.f?v:0.01f*v;}
__device__ __forceinline__ float sigm(float x){float e=__expf(-x);return __fdividef(1.f,1.f+e);}
__device__ __forceinline__ float tanhfast(float x){
    x=fminf(fmaxf(x,-9.f),9.f);
    float t=__expf(2.f*x);
    return __fdividef(t-1.f,t+1.f);
}
__device__ __forceinline__ uint32_t s2u(const void* p){
    uint32_t a; asm("{ .reg .u64 t; cvta.to.shared.u64 t, %1; cvt.u32.u64 %0, t; }":"=r"(a):"l"(p)); return a;
}
__device__ __forceinline__ uint32_t pkbf(float a,float b){
    uint32_t r; asm("cvt.rn.bf16x2.f32 %0, %1, %2;":"=r"(r):"f"(b),"f"(a)); return r;
}
__device__ __forceinline__ float upbf(uint32_t u,int slot){
    return __uint_as_float((slot?(u>>16):(u&0xffffu))<<16);
}

#define CP16(s,g)  asm volatile("cp.async.cg.shared.global [%0], [%1], 16;"::"r"(s),"l"(g):"memory")
#define CPCOMMIT() asm volatile("cp.async.commit_group;":::"memory")
#define CPWAIT()   asm volatile("cp.async.wait_group 0;":::"memory")
#define LDSM4(r0,r1,r2,r3,a) asm volatile( \
    "ldmatrix.sync.aligned.m8n8.x4.shared.b16 {%0,%1,%2,%3},[%4];" \
    :"=r"(r0),"=r"(r1),"=r"(r2),"=r"(r3):"r"(a))
#define MMA(dd,aa,b0,b1) asm volatile( \
    "mma.sync.aligned.m16n8k16.row.col.f32.bf16.bf16.f32 {%0,%1,%2,%3},{%4,%5,%6,%7},{%8,%9},{%0,%1,%2,%3};" \
    : "+f"((dd)[0]),"+f"((dd)[1]),"+f"((dd)[2]),"+f"((dd)[3]) \
    : "r"((aa)[0]),"r"((aa)[1]),"r"((aa)[2]),"r"((aa)[3]),"r"(b0),"r"(b1))

// ---------------- CSR build ----------------
__global__ void k_zero(){int i=blockIdx.x*blockDim.x+threadIdx.x;if(i<NN)d_deg[i]=0;}
__global__ void k_count(const int* __restrict__ ei){int e=blockIdx.x*blockDim.x+threadIdx.x;if(e<NE)atomicAdd(&d_deg[ei[NE+e]],1);}
__global__ void k_scan(){
    __shared__ int ws[32];
    int t=threadIdx.x,base=t*8,v[8],pre[8],s=0;
#pragma unroll
    for(int i=0;i<8;i++){v[i]=d_deg[base+i];pre[i]=s;s+=v[i];}
    int lane=t&31,wid=t>>5,x=s;
#pragma unroll
    for(int o=1;o<32;o<<=1){int y=__shfl_up_sync(~0u,x,o);if(lane>=o)x+=y;}
    if(lane==31)ws[wid]=x;
    __syncthreads();
    if(wid==0){int w=ws[lane],xx=w;
#pragma unroll
        for(int o=1;o<32;o<<=1){int y=__shfl_up_sync(~0u,xx,o);if(lane>=o)xx+=y;}
        ws[lane]=xx-w;}
    __syncthreads();
    int obase=ws[wid]+(x-s);
#pragma unroll
    for(int i=0;i<8;i++){int o=obase+pre[i];d_off[base+i]=o;d_cur[base+i]=o;
        d_invdeg[base+i]=v[i]>0?1.0f/(float)v[i]:0.0f;}
    if(t==1023)d_off[NN]=obase+s;
}
__global__ void k_fill(const int* __restrict__ ei){int e=blockIdx.x*blockDim.x+threadIdx.x;
    if(e<NE){int p=atomicAdd(&d_cur[ei[NE+e]],1);d_csr[p]=e;}}
__global__ void k_sortl(){
    int n=blockIdx.x*blockDim.x+threadIdx.x;if(n>=NN)return;
    int a=d_off[n],b=d_off[n+1];
    for(int i=a+1;i<b;i++){int key=d_csr[i],j=i-1;
        while(j>=a&&d_csr[j]>key){d_csr[j+1]=d_csr[j];j--;}d_csr[j+1]=key;}
}

// ---------------- weight prep ----------------
__global__ void k_prepw(const float* __restrict__ root,
                        const float* __restrict__ wih,
                        const float* __restrict__ whh){
    int idx=blockIdx.x*blockDim.x+threadIdx.x;
    if(idx>=7*16384)return;
    int t=idx>>14, rem=idx&16383, n=rem>>7, k=rem&127;
    float v;
    if(t==0)      v=root[k*128+n];
    else if(t<4)  v=wih[((t-1)*128+n)*128+k];
    else          v=whh[((t-4)*128+n)*128+k];
    __nv_bfloat16 hi=__float2bfloat16(v);
    __nv_bfloat16 lo=__float2bfloat16(v-__bfloat162float(hi));
    d_bwh[idx]=hi; d_bwl[idx]=lo;
}

// ---------------- generic fp32 GEMM (prologue/heads) ----------------
__global__ void __launch_bounds__(256)
k_gemm(const float* __restrict__ A,const float* __restrict__ W,
       const float* __restrict__ bias,const float* __restrict__ add,int ldadd,
       float* __restrict__ C,int ldc,int N,int ldw,int transW,int act){
    __shared__ float At[32*ATS];
    __shared__ float Bp[32*128];
    int t=threadIdx.x,rg=t>>5,cg=t&31;
    int row0=blockIdx.x*64,jt=blockIdx.y*128;
    ull acc[4][4];
#pragma unroll
    for(int p=0;p<4;p++)
#pragma unroll
        for(int c=0;c<4;c++)acc[p][c]=0ull;
    for(int kc=0;kc<128;kc+=32){
        { int rl=t&63,kg=t>>6;const float*src=A+(size_t)(row0+rl)*128+kc+kg*8;
          float4 v0=*(const float4*)src,v1=*(const float4*)(src+4);int kb=kg*8;
          At[(kb+0)*ATS+rl]=v0.x;At[(kb+1)*ATS+rl]=v0.y;At[(kb+2)*ATS+rl]=v0.z;At[(kb+3)*ATS+rl]=v0.w;
          At[(kb+4)*ATS+rl]=v1.x;At[(kb+5)*ATS+rl]=v1.y;At[(kb+6)*ATS+rl]=v1.z;At[(kb+7)*ATS+rl]=v1.w;}
        if(transW){
            int j=t>>1,h=t&1;
            if(jt+j<N){const float*src=W+(size_t)(jt+j)*ldw+kc+h*16;
#pragma unroll
                for(int i=0;i<4;i++){float4 v=*(const float4*)(src+i*4);int kk=h*16+i*4;
                    Bp[(kk+0)*128+j]=v.x;Bp[(kk+1)*128+j]=v.y;Bp[(kk+2)*128+j]=v.z;Bp[(kk+3)*128+j]=v.w;}
            }else{
#pragma unroll
                for(int i=0;i<16;i++)Bp[(h*16+i)*128+j]=0.f;}
        }else{
#pragma unroll
            for(int i=0;i<4;i++){int g=i*1024+t*4;*(float4*)(Bp+g)=*(const float4*)(W+kc*128+g);}
        }
        __syncthreads();
        const float*Ab=At+rg*8;const float*Bb=Bp+cg*4;
#pragma unroll 8
        for(int k=0;k<32;k++){
            ulonglong2 A0=*(const ulonglong2*)(Ab+k*ATS);
            ulonglong2 A1=*(const ulonglong2*)(Ab+k*ATS+4);
            float4 b=*(const float4*)(Bb+k*128);
            ull B0=pack2(b.x),B1=pack2(b.y),B2=pack2(b.z),B3=pack2(b.w);
            fma2(acc[0][0],A0.x,B0);fma2(acc[0][1],A0.x,B1);fma2(acc[0][2],A0.x,B2);fma2(acc[0][3],A0.x,B3);
            fma2(acc[1][0],A0.y,B0);fma2(acc[1][1],A0.y,B1);fma2(acc[1][2],A0.y,B2);fma2(acc[1][3],A0.y,B3);
            fma2(acc[2][0],A1.x,B0);fma2(acc[2][1],A1.x,B1);fma2(acc[2][2],A1.x,B2);fma2(acc[2][3],A1.x,B3);
            fma2(acc[3][0],A1.y,B0);fma2(acc[3][1],A1.y,B1);fma2(acc[3][2],A1.y,B2);fma2(acc[3][3],A1.y,B3);
        }
        __syncthreads();
    }
#pragma unroll
    for(int c=0;c<4;c++){
        int j=jt+cg*4+c;if(j>=N)continue;
        float bv=bias?bias[j]:0.f;
#pragma unroll
        for(int p=0;p<4;p++){
            int r=row0+rg*8+2*p;
            float v0=lo32(acc[p][c])+bv,v1=hi32(acc[p][c])+bv;
            if(add){v0+=add[(size_t)r*ldadd+j];v1+=add[(size_t)(r+1)*ldadd+j];}
            if(act){v0=lrelu(v0);v1=lrelu(v1);}
            C[(size_t)r*ldc+j]=v0;C[(size_t)(r+1)*ldc+j]=v1;
        }
    }
}

// ---------------- persistent mma.sync conv steps ----------------
#define SB0H 0
#define SB0L 34816
#define SB1H 69632
#define SB1L 104448
#define SPM  139264     // agg -> m exchange -> gate slots (33792B)
#define SPH  173056     // new-h exchange (33792B)
#define SBI  206848     // biases (896 f32)
#define SMT  210432
#define STRB 272

__device__ __forceinline__ void stageT(uint32_t sH,uint32_t sL,int tile,int tid){
    const char* gh=(const char*)(d_bwh+tile*16384);
    const char* gl=(const char*)(d_bwl+tile*16384);
#pragma unroll
    for(int q=0;q<8;q++){
        int i=tid+q*256, n=i>>4, c=i&15;
        CP16(sH+n*STRB+c*16, gh+n*256+c*16);
        CP16(sL+n*STRB+c*16, gl+n*256+c*16);
    }
    CPCOMMIT();
}

__device__ __forceinline__ void gemm_pass(float acc[8][4],const uint32_t aH[32],const uint32_t aL[32],
                                          uint32_t bh,uint32_t bl,int bt){
#pragma unroll
    for(int kc=0;kc<8;kc++){
#pragma unroll
        for(int jj=0;jj<4;jj++){
            uint32_t h0,h1,h2,h3,l0,l1,l2,l3;
            uint32_t off=jj*4352+kc*32+bt;
            LDSM4(h0,h1,h2,h3,bh+off);
            LDSM4(l0,l1,l2,l3,bl+off);
            MMA(acc[2*jj],  aH+kc*4,h0,h1);
            MMA(acc[2*jj+1],aH+kc*4,h2,h3);
            MMA(acc[2*jj],  aL+kc*4,h0,h1);
            MMA(acc[2*jj+1],aL+kc*4,h2,h3);
            MMA(acc[2*jj],  aH+kc*4,l0,l1);
            MMA(acc[2*jj+1],aH+kc*4,l2,l3);
        }
    }
}
#define ZACC(acc) {_Pragma("unroll") for(int _n=0;_n<8;_n++){_Pragma("unroll") for(int _d=0;_d<4;_d++)(acc)[_n][_d]=0.f;}}

// frag extraction from a [64][132] f32 smem tile
__device__ __forceinline__ void frags_from_tile(const float* P,int rl,int lane,
                                                uint32_t fH[32],uint32_t fL[32]){
#pragma unroll
    for(int kc=0;kc<8;kc++)
#pragma unroll
    for(int j=0;j<4;j++){
        int row=rl+(j&1)*8;
        int col=kc*16+(j>>1)*8+(lane&3)*2;
        float2 v=*(const float2*)(P+row*132+col);
        uint32_t ph=pkbf(v.x,v.y);
        fH[kc*4+j]=ph;
        fL[kc*4+j]=pkbf(v.x-upbf(ph,0),v.y-upbf(ph,1));
    }
}

__device__ __forceinline__ void gridbar(unsigned ep_tgt){
    __syncthreads();
    if(threadIdx.x==0){
        __threadfence();
        unsigned old=atomicAdd(&g_cnt,1u);
        if(old==NB-1u){ g_cnt=0u; __threadfence(); atomicAdd(&g_epoch,1u); }
        else { while((int)(*(volatile unsigned*)&g_epoch - ep_tgt) < 0){} }
        __threadfence();
    }
    __syncthreads();
}

__global__ void __launch_bounds__(256,1)
k_steps(const int* __restrict__ ei, const int* __restrict__ ea,
        const float* __restrict__ embBond,
        const float* __restrict__ cbias,
        const float* __restrict__ bih, const float* __restrict__ bhh){
    extern __shared__ char smem[];
    uint32_t sb=s2u(smem);
    float* Pm=(float*)(smem+SPM);
    float* Pg=(float*)(smem+SPM);
    float* Ph=(float*)(smem+SPH);
    float* sbias=(float*)(smem+SBI);
    __shared__ unsigned s_ep0;
    int tid=threadIdx.x, w=tid>>5, lane=tid&31;
    int row0=blockIdx.x*64;
    int wr=w&3, nt0=(w>>2)*8;
    int bt=nt0*2176+((lane>>3)>>1)*2176+(lane&7)*STRB+((lane>>3)&1)*16;
    int rl=16*wr+(lane>>2);

    if(tid==0)s_ep0=*(volatile unsigned*)&g_epoch;
    for(int i=tid;i<384;i+=256){sbias[i]=bih[i];sbias[384+i]=bhh[i];}
    if(tid<128)sbias[768+tid]=cbias[tid];
    __syncthreads();
    unsigned ep0=s_ep0;

    uint32_t A0=sb+SB0H, A1=sb+SB0L, B0=sb+SB1H, B1=sb+SB1L;
    stageT(A0,A1,0,tid);            // rootT

    // step-0 h fragments from global d_h
    uint32_t hAh[32],hAl[32];
    {
        int ra=row0+rl;
#pragma unroll
        for(int kc=0;kc<8;kc++)
#pragma unroll
        for(int j=0;j<4;j++){
            int row=ra+(j&1)*8;
            int col=kc*16+(j>>1)*8+(lane&3)*2;
            float2 v=*(const float2*)(d_h+(size_t)row*128+col);
            uint32_t ph=pkbf(v.x,v.y);
            hAh[kc*4+j]=ph;
            hAl[kc*4+j]=pkbf(v.x-upbf(ph,0),v.y-upbf(ph,1));
        }
    }

    for(int s=0;s<NSTEPS;s++){
        const float* hcur=(s&1)?d_h2:d_h;
        float* hnext=(s&1)?d_h:d_h2;

        // ---- edge aggregation -> Pm (smem agg), overlaps rootT cp.async ----
#pragma unroll 1
        for(int q=0;q<8;q++){
            int n=row0+8*w+q;
            int s0=d_off[n],s1=d_off[n+1];
            float4 acc4=make_float4(0.f,0.f,0.f,0.f);
            for(int i=s0;i<s1;i++){
                int e=d_csr[i];
                int sr=ei[e],a0=ea[2*e],a1=ea[2*e+1];
                float4 hv=*(const float4*)(hcur+(size_t)sr*D+lane*4);
                float4 b0=*(const float4*)(embBond+(size_t)a0*D+lane*4);
                float p=hv.x*b0.x+hv.y*b0.y+hv.z*b0.z+hv.w*b0.w;
#pragma unroll
                for(int o=16;o>0;o>>=1)p+=__shfl_xor_sync(~0u,p,o);
                float4 b1=*(const float4*)(embBond+(size_t)a1*D+lane*4);
                acc4.x+=p*b1.x;acc4.y+=p*b1.y;acc4.z+=p*b1.z;acc4.w+=p*b1.w;
            }
            float iv=d_invdeg[n];
            acc4.x*=iv;acc4.y*=iv;acc4.z*=iv;acc4.w*=iv;
            *(float4*)(Pm+(8*w+q)*132+lane*4)=acc4;
        }

        float acc[8][4];
        // ---- P1: conv = lrelu(h@root + agg + cbias) ----
        CPWAIT(); __syncthreads();
        stageT(B0,B1,1,tid);                 // wih_r
        ZACC(acc);
        gemm_pass(acc,hAh,hAl,A0,A1,bt);
        {
#pragma unroll
            for(int n=0;n<8;n++){
                int colg=(nt0+n)*8+(lane&3)*2;
                float2 a0=*(const float2*)(Pm+rl*132+colg);
                float2 a1=*(const float2*)(Pm+(rl+8)*132+colg);
                float b0v=sbias[768+colg],b1v=sbias[768+colg+1];
                float2 m0=make_float2(lrelu(acc[n][0]+a0.x+b0v),lrelu(acc[n][1]+a0.y+b1v));
                float2 m1=make_float2(lrelu(acc[n][2]+a1.x+b0v),lrelu(acc[n][3]+a1.y+b1v));
                *(float2*)(Pm+rl*132+colg)=m0;
                *(float2*)(Pm+(rl+8)*132+colg)=m1;
            }
        }
        __syncthreads();
        uint32_t mAh[32],mAl[32];
        frags_from_tile(Pm,rl,lane,mAh,mAl);

        // ---- P2: m@wih_r ----
        CPWAIT(); __syncthreads();
        stageT(A0,A1,4,tid);                 // whh_r
        ZACC(acc);
        gemm_pass(acc,mAh,mAl,B0,B1,bt);
        // ---- P3: + h@whh_r -> r gate ----
        CPWAIT(); __syncthreads();
        stageT(B0,B1,6,tid);                 // whh_n
        gemm_pass(acc,hAh,hAl,A0,A1,bt);
#pragma unroll
        for(int n=0;n<8;n++)
#pragma unroll
        for(int dg=0;dg<4;dg++){
            int col=(nt0+n)*8+(lane&3)*2+(dg&1);
            Pg[(n*4+dg)*256+tid]=sigm(acc[n][dg]+sbias[col]+sbias[384+col]);
        }
        // ---- P4: h@whh_n -> P = r*(hn+bhh_n) ----
        CPWAIT(); __syncthreads();
        stageT(A0,A1,3,tid);                 // wih_n
        ZACC(acc);
        gemm_pass(acc,hAh,hAl,B0,B1,bt);
#pragma unroll
        for(int n=0;n<8;n++)
#pragma unroll
        for(int dg=0;dg<4;dg++){
            int col=(nt0+n)*8+(lane&3)*2+(dg&1);
            int i=(n*4+dg)*256+tid;
            Pg[i]=Pg[i]*(acc[n][dg]+sbias[640+col]);
        }
        // ---- P5: m@wih_n -> P = tanh(in+bih_n+P) ----
        CPWAIT(); __syncthreads();
        stageT(B0,B1,2,tid);                 // wih_z
        ZACC(acc);
        gemm_pass(acc,mAh,mAl,A0,A1,bt);
#pragma unroll
        for(int n=0;n<8;n++)
#pragma unroll
        for(int dg=0;dg<4;dg++){
            int col=(nt0+n)*8+(lane&3)*2+(dg&1);
            int i=(n*4+dg)*256+tid;
            Pg[i]=tanhfast(acc[n][dg]+sbias[256+col]+Pg[i]);
        }
        // ---- P6: m@wih_z ----
        CPWAIT(); __syncthreads();
        stageT(A0,A1,5,tid);                 // whh_z
        ZACC(acc);
        gemm_pass(acc,mAh,mAl,B0,B1,bt);
        // ---- P7: + h@whh_z -> z gate + update ----
        CPWAIT(); __syncthreads();
        stageT(B0,B1,0,tid);                 // rootT for next step
        gemm_pass(acc,hAh,hAl,A0,A1,bt);
        {
            int rbase=row0+rl;
#pragma unroll
            for(int n=0;n<8;n++){
                int nt=nt0+n, kc=nt>>1;
                float o[4];
#pragma unroll
                for(int dg=0;dg<4;dg++){
                    int col=nt*8+(lane&3)*2+(dg&1);
                    int j=((nt&1)<<1)|(dg>>1);
                    float hv=upbf(hAh[kc*4+j],dg&1)+upbf(hAl[kc*4+j],dg&1);
                    float z=sigm(acc[n][dg]+sbias[128+col]+sbias[512+col]);
                    float nv=Pg[(n*4+dg)*256+tid];
                    o[dg]=(1.f-z)*nv+z*hv;
                }
                int c0=nt*8+(lane&3)*2;
                *(float2*)(hnext+(size_t)rbase*D+c0)    =make_float2(o[0],o[1]);
                *(float2*)(hnext+(size_t)(rbase+8)*D+c0)=make_float2(o[2],o[3]);
                *(float2*)(Ph+rl*132+c0)    =make_float2(o[0],o[1]);
                *(float2*)(Ph+(rl+8)*132+c0)=make_float2(o[2],o[3]);
            }
        }
        __syncthreads();
        frags_from_tile(Ph,rl,lane,hAh,hAl);   // new h fragments from smem

        gridbar(ep0+(unsigned)s+1u);
        // swap panel buffers (rootT now in B)
        uint32_t t0=A0;A0=B0;B0=t0; uint32_t t1=A1;A1=B1;B1=t1;
    }
}

// ---------------- row gather ----------------
__global__ void k_gather(float* __restrict__ dst,const float* __restrict__ src,
                         const int* __restrict__ idx,int n){
    int t=blockIdx.x*blockDim.x+threadIdx.x;
    int row=t>>5,l=t&31;if(row>=n)return;
    *(float4*)(dst+(size_t)row*128+l*4)=*(const float4*)(src+(size_t)idx[row]*128+l*4);
}

// ---------------- global mean pool ----------------
__global__ void k_pool(const int* __restrict__ nb){
    int g=blockIdx.x,c=threadIdx.x;
    int lo=0,hi=NN;while(lo<hi){int m=(lo+hi)>>1;if(nb[m]<g)lo=m+1;else hi=m;}
    int s=lo;lo=0;hi=NN;while(lo<hi){int m=(lo+hi)>>1;if(nb[m]<=g)lo=m+1;else hi=m;}
    int e=lo;float sum=0.f;
    for(int r=s;r<e;r++)sum+=d_h[(size_t)r*128+c];
    d_gm[g*128+c]=sum/fmaxf((float)(e-s),1.f);
}

// ---------------- stop head ----------------
__global__ void k_stop(const float* __restrict__ w2,const float* __restrict__ b2,
                       float* __restrict__ out){
    int w=(blockIdx.x*blockDim.x+threadIdx.x)>>5,l=threadIdx.x&31;
    if(w>=NG)return;
    float4 g=*(const float4*)(d_g1+(size_t)w*128+l*4);
    float4 ww=*(const float4*)(w2+l*4);
    float p=g.x*ww.x+g.y*ww.y+g.z*ww.z+g.w*ww.w;
#pragma unroll
    for(int o=16;o>0;o>>=1)p+=__shfl_xor_sync(~0u,p,o);
    if(l==0)out[NS*OPS+w]=p+b2[0];
}

// ---------------- launch ----------------
extern "C" void kernel_launch(void* const* d_in,const int* in_sizes,int n_in,
                              void* d_out,int out_size){
    const int* x   =(const int*)d_in[0];
    const int* st  =(const int*)d_in[1];
    const int* ea  =(const int*)d_in[2];
    const int* ei  =(const int*)d_in[3];
    const int* sni =(const int*)d_in[4];
    const int* nb  =(const int*)d_in[5];
    const float* embB=(const float*)d_in[6];
    const float* embS=(const float*)d_in[7];
    const float* embBond=(const float*)d_in[8];
    const float* b2e_w1=(const float*)d_in[9],  *b2e_b1=(const float*)d_in[10];
    const float* b2e_w2=(const float*)d_in[11], *b2e_b2=(const float*)d_in[12];
    const float* conv_root=(const float*)d_in[13], *conv_bias=(const float*)d_in[14];
    const float* w_ih=(const float*)d_in[15], *w_hh=(const float*)d_in[16];
    const float* b_ih=(const float*)d_in[17], *b_hh=(const float*)d_in[18];
    const float* s2p_w1=(const float*)d_in[19], *s2p_b1=(const float*)d_in[20];
    const float* s2p_w2=(const float*)d_in[21], *s2p_b2=(const float*)d_in[22];
    const float* s2p_w3=(const float*)d_in[23], *s2p_b3=(const float*)d_in[24];
    const float* g2p_w1=(const float*)d_in[25], *g2p_b1=(const float*)d_in[26];
    const float* g2p_w2=(const float*)d_in[27], *g2p_b2=(const float*)d_in[28];
    float* out=(float*)d_out;

    void* p;
    cudaGetSymbolAddress(&p,d_h);   float* ph =(float*)p;
    cudaGetSymbolAddress(&p,d_m);   float* pm =(float*)p;
    cudaGetSymbolAddress(&p,d_h2);  float* ph2=(float*)p;
    cudaGetSymbolAddress(&p,d_sg);  float* psg=(float*)p;
    cudaGetSymbolAddress(&p,d_se);  float* pse=(float*)p;
    cudaGetSymbolAddress(&p,d_s1);  float* ps1=(float*)p;
    cudaGetSymbolAddress(&p,d_gm);  float* pgm=(float*)p;
    cudaGetSymbolAddress(&p,d_g1);  float* pg1=(float*)p;

    static int attr_set=0;
    if(!attr_set){
        cudaFuncSetAttribute(k_steps,cudaFuncAttributeMaxDynamicSharedMemorySize,SMT);
        attr_set=1;
    }

    // CSR build + weight prep
    k_zero <<<32,256>>>();
    k_count<<<64,256>>>(ei);
    k_scan <<<1,1024>>>();
    k_fill <<<64,256>>>(ei);
    k_sortl<<<32,256>>>();
    k_prepw<<<448,256>>>(conv_root,w_ih,w_hh);

    // block2emb
    k_gather<<<NN*32/256,256>>>(pm,embB,x,NN);
    k_gemm<<<dim3(NN/64,1),256>>>(pm,  b2e_w1,b2e_b1,nullptr,0,ph2,128,128,128,1,1);
    k_gemm<<<dim3(NN/64,1),256>>>(ph2, b2e_w2,b2e_b2,nullptr,0,ph, 128,128,128,1,0);

    // 12 persistent tensor-core conv steps (ends in d_h)
    k_steps<<<NB,256,SMT>>>(ei,ea,embBond,conv_bias,b_ih,b_hh);

    // stem head
    k_gather<<<NS*32/256,256>>>(psg,ph,sni,NS);
    k_gather<<<NS*32/256,256>>>(pse,embS,st,NS);
    k_gemm<<<dim3(NS/64,1),256>>>(psg,s2p_w1,    nullptr,nullptr,0,ps1,128,128,256,1,0);
    k_gemm<<<dim3(NS/64,1),256>>>(pse,s2p_w1+128,s2p_b1, ps1,128,  ps1,128,128,256,1,1);
    k_gemm<<<dim3(NS/64,1),256>>>(ps1,s2p_w2,s2p_b2,nullptr,0,pm, 128,128,128,1,1);
    k_gemm<<<dim3(NS/64,1),256>>>(pm, s2p_w3,s2p_b3,nullptr,0,out,105,105,128,1,0);

    // stop head
    k_pool<<<NG,128>>>(nb);
    k_gemm<<<dim3(NG/64,1),256>>>(pgm,g2p_w1,g2p_b1,nullptr,0,pg1,128,128,128,1,1);
    k_stop<<<NG/8,256>>>(g2p_w2,g2p_b2,out);
}

// round 10
// speedup vs baseline: 1.0295x; 1.0295x over previous
#include <cuda_runtime.h>
#include <cuda_bf16.h>
#include <math.h>
#include <stdint.h>

#define D 128
#define NN 8192
#define NE 16384
#define NS 4096
#define NG 256
#define OPS 105
#define NSTEPS 12
#define ATS 68

typedef unsigned long long ull;

// ---------------- scratch ----------------
__device__ float d_h[NN*D], d_h2[NN*D], d_m[NN*D];
__device__ float d_sg[NS*D], d_se[NS*D], d_s1[NS*D];
__device__ float d_gm[NG*D], d_g1[NG*D];
__device__ int   d_deg[NN], d_off[NN+1], d_cur[NN], d_csr[NE];
__device__ float d_invdeg[NN];
__device__ __nv_bfloat16 d_bwh[7*16384], d_bwl[7*16384];
__device__ unsigned g_cnt=0, g_epoch=0;

// ---------------- helpers ----------------
__device__ __forceinline__ ull pack2(float x){unsigned u=__float_as_uint(x);ull r;asm("mov.b64 %0,{%1,%1};":"=l"(r):"r"(u));return r;}
__device__ __forceinline__ void fma2(ull&a,ull x,ull y){asm("fma.rn.f32x2 %0,%1,%2,%0;":"+l"(a):"l"(x),"l"(y));}
__device__ __forceinline__ float lo32(ull v){return __uint_as_float((unsigned)v);}
__device__ __forceinline__ float hi32(ull v){return __uint_as_float((unsigned)(v>>32));}
__device__ __forceinline__ float lrelu(float v){return v>0.f?v:0.01f*v;}
__device__ __forceinline__ float sigm(float x){float e=__expf(-x);return __fdividef(1.f,1.f+e);}
__device__ __forceinline__ float tanhfast(float x){
    x=fminf(fmaxf(x,-9.f),9.f);
    float t=__expf(2.f*x);
    return __fdividef(t-1.f,t+1.f);
}
__device__ __forceinline__ uint32_t s2u(const void* p){
    uint32_t a; asm("{ .reg .u64 t; cvta.to.shared.u64 t, %1; cvt.u32.u64 %0, t; }":"=r"(a):"l"(p)); return a;
}
__device__ __forceinline__ uint32_t pkbf(float a,float b){
    uint32_t r; asm("cvt.rn.bf16x2.f32 %0, %1, %2;":"=r"(r):"f"(b),"f"(a)); return r;
}
__device__ __forceinline__ float upbf(uint32_t u,int slot){
    return __uint_as_float((slot?(u>>16):(u&0xffffu))<<16);
}

#define CP16(s,g)  asm volatile("cp.async.cg.shared.global [%0], [%1], 16;"::"r"(s),"l"(g):"memory")
#define CPCOMMIT() asm volatile("cp.async.commit_group;":::"memory")
#define CPWAIT()   asm volatile("cp.async.wait_group 0;":::"memory")
#define LDSM4(r0,r1,r2,r3,a) asm volatile( \
    "ldmatrix.sync.aligned.m8n8.x4.shared.b16 {%0,%1,%2,%3},[%4];" \
    :"=r"(r0),"=r"(r1),"=r"(r2),"=r"(r3):"r"(a))
#define MMA(dd,aa,b0,b1) asm volatile( \
    "mma.sync.aligned.m16n8k16.row.col.f32.bf16.bf16.f32 {%0,%1,%2,%3},{%4,%5,%6,%7},{%8,%9},{%0,%1,%2,%3};" \
    : "+f"((dd)[0]),"+f"((dd)[1]),"+f"((dd)[2]),"+f"((dd)[3]) \
    : "r"((aa)[0]),"r"((aa)[1]),"r"((aa)[2]),"r"((aa)[3]),"r"(b0),"r"(b1))

// ---------------- fused prologue #1: deg zero + weight prep + emb gather ---
__global__ void k_prep0(const int* __restrict__ x,const float* __restrict__ embB,
                        const float* __restrict__ root,const float* __restrict__ wih,
                        const float* __restrict__ whh,float* __restrict__ dst){
    int t=blockIdx.x*blockDim.x+threadIdx.x;    // 1024 x 256 = NN*32
    int row=t>>5,l=t&31;
    *(float4*)(dst+(size_t)row*128+l*4)=*(const float4*)(embB+(size_t)x[row]*128+l*4);
    if(t<NN)d_deg[t]=0;
    if(t<7*16384){
        int tt=t>>14, rem=t&16383, n=rem>>7, k=rem&127;
        float v;
        if(tt==0)      v=root[k*128+n];
        else if(tt<4)  v=wih[((tt-1)*128+n)*128+k];
        else           v=whh[((tt-4)*128+n)*128+k];
        __nv_bfloat16 hi=__float2bfloat16(v);
        __nv_bfloat16 lo=__float2bfloat16(v-__bfloat162float(hi));
        d_bwh[t]=hi; d_bwl[t]=lo;
    }
}

// ---------------- fused prologue #2: CSR count/scan/fill/sort -------------
#define CSRB 32
__device__ __forceinline__ void gridbar32(unsigned tgt){
    __syncthreads();
    if(threadIdx.x==0){
        __threadfence();
        unsigned old=atomicAdd(&g_cnt,1u);
        if(old==CSRB-1u){ g_cnt=0u; __threadfence(); atomicAdd(&g_epoch,1u); }
        else { while((int)(*(volatile unsigned*)&g_epoch - tgt) < 0){} }
        __threadfence();
    }
    __syncthreads();
}
__global__ void __launch_bounds__(1024)
k_csr(const int* __restrict__ ei){
    __shared__ unsigned s_ep0;
    if(threadIdx.x==0)s_ep0=*(volatile unsigned*)&g_epoch;
    __syncthreads();
    unsigned ep0=s_ep0;
    int gt=blockIdx.x*1024+threadIdx.x;
    if(gt<NE)atomicAdd(&d_deg[ei[NE+gt]],1);
    gridbar32(ep0+1u);
    if(blockIdx.x==0){
        __shared__ int ws[32];
        int t=threadIdx.x,base=t*8,v[8],pre[8],s=0;
#pragma unroll
        for(int i=0;i<8;i++){v[i]=d_deg[base+i];pre[i]=s;s+=v[i];}
        int lane=t&31,wid=t>>5,xx=s;
#pragma unroll
        for(int o=1;o<32;o<<=1){int y=__shfl_up_sync(~0u,xx,o);if(lane>=o)xx+=y;}
        if(lane==31)ws[wid]=xx;
        __syncthreads();
        if(wid==0){int w0=ws[lane],x2=w0;
#pragma unroll
            for(int o=1;o<32;o<<=1){int y=__shfl_up_sync(~0u,x2,o);if(lane>=o)x2+=y;}
            ws[lane]=x2-w0;}
        __syncthreads();
        int obase=ws[wid]+(xx-s);
#pragma unroll
        for(int i=0;i<8;i++){int o=obase+pre[i];d_off[base+i]=o;d_cur[base+i]=o;
            d_invdeg[base+i]=v[i]>0?1.0f/(float)v[i]:0.0f;}
        if(t==1023)d_off[NN]=obase+s;
    }
    gridbar32(ep0+2u);
    if(gt<NE){int p=atomicAdd(&d_cur[ei[NE+gt]],1);d_csr[p]=gt;}
    gridbar32(ep0+3u);
    if(gt<NN){
        int a=d_off[gt],b=d_off[gt+1];
        for(int i=a+1;i<b;i++){int key=d_csr[i],j=i-1;
            while(j>=a&&d_csr[j]>key){d_csr[j+1]=d_csr[j];j--;}d_csr[j+1]=key;}
    }
}

// ---------------- generic fp32 GEMM (prologue/heads) ----------------
__global__ void __launch_bounds__(256)
k_gemm(const float* __restrict__ A,const float* __restrict__ W,
       const float* __restrict__ bias,const float* __restrict__ add,int ldadd,
       float* __restrict__ C,int ldc,int N,int ldw,int transW,int act){
    __shared__ float At[32*ATS];
    __shared__ float Bp[32*128];
    int t=threadIdx.x,rg=t>>5,cg=t&31;
    int row0=blockIdx.x*64,jt=blockIdx.y*128;
    ull acc[4][4];
#pragma unroll
    for(int p=0;p<4;p++)
#pragma unroll
        for(int c=0;c<4;c++)acc[p][c]=0ull;
    for(int kc=0;kc<128;kc+=32){
        { int rl=t&63,kg=t>>6;const float*src=A+(size_t)(row0+rl)*128+kc+kg*8;
          float4 v0=*(const float4*)src,v1=*(const float4*)(src+4);int kb=kg*8;
          At[(kb+0)*ATS+rl]=v0.x;At[(kb+1)*ATS+rl]=v0.y;At[(kb+2)*ATS+rl]=v0.z;At[(kb+3)*ATS+rl]=v0.w;
          At[(kb+4)*ATS+rl]=v1.x;At[(kb+5)*ATS+rl]=v1.y;At[(kb+6)*ATS+rl]=v1.z;At[(kb+7)*ATS+rl]=v1.w;}
        if(transW){
            int j=t>>1,h=t&1;
            if(jt+j<N){const float*src=W+(size_t)(jt+j)*ldw+kc+h*16;
#pragma unroll
                for(int i=0;i<4;i++){float4 v=*(const float4*)(src+i*4);int kk=h*16+i*4;
                    Bp[(kk+0)*128+j]=v.x;Bp[(kk+1)*128+j]=v.y;Bp[(kk+2)*128+j]=v.z;Bp[(kk+3)*128+j]=v.w;}
            }else{
#pragma unroll
                for(int i=0;i<16;i++)Bp[(h*16+i)*128+j]=0.f;}
        }else{
#pragma unroll
            for(int i=0;i<4;i++){int g=i*1024+t*4;*(float4*)(Bp+g)=*(const float4*)(W+kc*128+g);}
        }
        __syncthreads();
        const float*Ab=At+rg*8;const float*Bb=Bp+cg*4;
#pragma unroll 8
        for(int k=0;k<32;k++){
            ulonglong2 A0=*(const ulonglong2*)(Ab+k*ATS);
            ulonglong2 A1=*(const ulonglong2*)(Ab+k*ATS+4);
            float4 b=*(const float4*)(Bb+k*128);
            ull B0=pack2(b.x),B1=pack2(b.y),B2=pack2(b.z),B3=pack2(b.w);
            fma2(acc[0][0],A0.x,B0);fma2(acc[0][1],A0.x,B1);fma2(acc[0][2],A0.x,B2);fma2(acc[0][3],A0.x,B3);
            fma2(acc[1][0],A0.y,B0);fma2(acc[1][1],A0.y,B1);fma2(acc[1][2],A0.y,B2);fma2(acc[1][3],A0.y,B3);
            fma2(acc[2][0],A1.x,B0);fma2(acc[2][1],A1.x,B1);fma2(acc[2][2],A1.x,B2);fma2(acc[2][3],A1.x,B3);
            fma2(acc[3][0],A1.y,B0);fma2(acc[3][1],A1.y,B1);fma2(acc[3][2],A1.y,B2);fma2(acc[3][3],A1.y,B3);
        }
        __syncthreads();
    }
#pragma unroll
    for(int c=0;c<4;c++){
        int j=jt+cg*4+c;if(j>=N)continue;
        float bv=bias?bias[j]:0.f;
#pragma unroll
        for(int p=0;p<4;p++){
            int r=row0+rg*8+2*p;
            float v0=lo32(acc[p][c])+bv,v1=hi32(acc[p][c])+bv;
            if(add){v0+=add[(size_t)r*ldadd+j];v1+=add[(size_t)(r+1)*ldadd+j];}
            if(act){v0=lrelu(v0);v1=lrelu(v1);}
            C[(size_t)r*ldc+j]=v0;C[(size_t)(r+1)*ldc+j]=v1;
        }
    }
}

// ---------------- mma.sync fused conv step (R8 structure + smem agg) -------
#define SB0H 0
#define SB0L 34816
#define SB1H 69632
#define SB1L 104448
#define SPM  139264     // agg -> m exchange -> gate slots
#define SBI  173056     // biases 896 f32
#define SMT  176640
#define STRB 272

__device__ __forceinline__ void stageT(uint32_t sH,uint32_t sL,int tile,int tid){
    const char* gh=(const char*)(d_bwh+tile*16384);
    const char* gl=(const char*)(d_bwl+tile*16384);
#pragma unroll
    for(int q=0;q<8;q++){
        int i=tid+q*256, n=i>>4, c=i&15;
        CP16(sH+n*STRB+c*16, gh+n*256+c*16);
        CP16(sL+n*STRB+c*16, gl+n*256+c*16);
    }
    CPCOMMIT();
}

__device__ __forceinline__ void gemm_pass(float acc[8][4],const uint32_t aH[32],const uint32_t aL[32],
                                          uint32_t bh,uint32_t bl,int bt){
#pragma unroll
    for(int kc=0;kc<8;kc++){
#pragma unroll
        for(int jj=0;jj<4;jj++){
            uint32_t h0,h1,h2,h3,l0,l1,l2,l3;
            uint32_t off=jj*4352+kc*32+bt;
            LDSM4(h0,h1,h2,h3,bh+off);
            LDSM4(l0,l1,l2,l3,bl+off);
            MMA(acc[2*jj],  aH+kc*4,h0,h1);
            MMA(acc[2*jj+1],aH+kc*4,h2,h3);
            MMA(acc[2*jj],  aL+kc*4,h0,h1);
            MMA(acc[2*jj+1],aL+kc*4,h2,h3);
            MMA(acc[2*jj],  aH+kc*4,l0,l1);
            MMA(acc[2*jj+1],aH+kc*4,l2,l3);
        }
    }
}
#define ZACC(acc) {_Pragma("unroll") for(int _n=0;_n<8;_n++){_Pragma("unroll") for(int _d=0;_d<4;_d++)(acc)[_n][_d]=0.f;}}

__global__ void __launch_bounds__(256,1)
k_step_mma(const float* __restrict__ hin, float* __restrict__ hout,
           const int* __restrict__ ei, const int* __restrict__ ea,
           const float* __restrict__ embBond,
           const float* __restrict__ cbias,
           const float* __restrict__ bih, const float* __restrict__ bhh){
    extern __shared__ char smem[];
    uint32_t sb=s2u(smem);
    float* Pm=(float*)(smem+SPM);
    float* Pg=(float*)(smem+SPM);
    float* sbias=(float*)(smem+SBI);
    int tid=threadIdx.x, w=tid>>5, lane=tid&31;
    int row0=blockIdx.x*64;
    int wr=w&3, nt0=(w>>2)*8;
    int bt=nt0*2176+((lane>>3)>>1)*2176+(lane&7)*STRB+((lane>>3)&1)*16;
    int rl=16*wr+(lane>>2);

    for(int i=tid;i<384;i+=256){sbias[i]=bih[i];sbias[384+i]=bhh[i];}
    if(tid<128)sbias[768+tid]=cbias[tid];

    stageT(sb+SB0H,sb+SB0L,0,tid);   // rootT

    // ---- h A-fragments (hi/lo) from global ----
    uint32_t hAh[32],hAl[32];
    {
        int ra=row0+rl;
#pragma unroll
        for(int kc=0;kc<8;kc++)
#pragma unroll
        for(int j=0;j<4;j++){
            int row=ra+(j&1)*8;
            int col=kc*16+(j>>1)*8+(lane&3)*2;
            float2 v=*(const float2*)(hin+(size_t)row*128+col);
            uint32_t ph=pkbf(v.x,v.y);
            hAh[kc*4+j]=ph;
            hAl[kc*4+j]=pkbf(v.x-upbf(ph,0),v.y-upbf(ph,1));
        }
    }

    // ---- edge aggregation -> Pm (smem) ----
#pragma unroll 1
    for(int q=0;q<8;q++){
        int n=row0+8*w+q;
        int s0=d_off[n],s1=d_off[n+1];
        float4 acc4=make_float4(0.f,0.f,0.f,0.f);
        for(int i=s0;i<s1;i++){
            int e=d_csr[i];
            int s=ei[e],a0=ea[2*e],a1=ea[2*e+1];
            float4 hv=*(const float4*)(hin+(size_t)s*D+lane*4);
            float4 b0=*(const float4*)(embBond+(size_t)a0*D+lane*4);
            float p=hv.x*b0.x+hv.y*b0.y+hv.z*b0.z+hv.w*b0.w;
#pragma unroll
            for(int o=16;o>0;o>>=1)p+=__shfl_xor_sync(~0u,p,o);
            float4 b1=*(const float4*)(embBond+(size_t)a1*D+lane*4);
            acc4.x+=p*b1.x;acc4.y+=p*b1.y;acc4.z+=p*b1.z;acc4.w+=p*b1.w;
        }
        float iv=d_invdeg[n];
        acc4.x*=iv;acc4.y*=iv;acc4.z*=iv;acc4.w*=iv;
        *(float4*)(Pm+(8*w+q)*132+lane*4)=acc4;
    }

    float acc[8][4];
    // ---- conv: m = lrelu(h@root + agg + cbias) ----
    CPWAIT(); __syncthreads();
    stageT(sb+SB1H,sb+SB1L,1,tid);               // wih_r
    ZACC(acc);
    gemm_pass(acc,hAh,hAl,sb+SB0H,sb+SB0L,bt);
    {
#pragma unroll
        for(int n=0;n<8;n++){
            int colg=(nt0+n)*8+(lane&3)*2;
            float2 a0=*(const float2*)(Pm+rl*132+colg);
            float2 a1=*(const float2*)(Pm+(rl+8)*132+colg);
            float b0v=sbias[768+colg],b1v=sbias[768+colg+1];
            float2 m0=make_float2(lrelu(acc[n][0]+a0.x+b0v),lrelu(acc[n][1]+a0.y+b1v));
            float2 m1=make_float2(lrelu(acc[n][2]+a1.x+b0v),lrelu(acc[n][3]+a1.y+b1v));
            *(float2*)(Pm+rl*132+colg)=m0;
            *(float2*)(Pm+(rl+8)*132+colg)=m1;
        }
    }
    __syncthreads();
    // ---- m A-fragments from exchange ----
    uint32_t mAh[32],mAl[32];
#pragma unroll
    for(int kc=0;kc<8;kc++)
#pragma unroll
    for(int j=0;j<4;j++){
        int row=rl+(j&1)*8;
        int col=kc*16+(j>>1)*8+(lane&3)*2;
        float2 v=*(const float2*)(Pm+row*132+col);
        uint32_t ph=pkbf(v.x,v.y);
        mAh[kc*4+j]=ph;
        mAl[kc*4+j]=pkbf(v.x-upbf(ph,0),v.y-upbf(ph,1));
    }

    // ---- r gate: acc = m@wih_r + h@whh_r ----
    CPWAIT(); __syncthreads();
    stageT(sb+SB0H,sb+SB0L,4,tid);               // whh_r
    ZACC(acc);
    gemm_pass(acc,mAh,mAl,sb+SB1H,sb+SB1L,bt);
    CPWAIT(); __syncthreads();
    stageT(sb+SB1H,sb+SB1L,6,tid);               // whh_n
    gemm_pass(acc,hAh,hAl,sb+SB0H,sb+SB0L,bt);
#pragma unroll
    for(int n=0;n<8;n++)
#pragma unroll
    for(int dg=0;dg<4;dg++){
        int col=(nt0+n)*8+(lane&3)*2+(dg&1);
        Pg[(n*4+dg)*256+tid]=sigm(acc[n][dg]+sbias[col]+sbias[384+col]);
    }
    // ---- hn: acc = h@whh_n;  P = r*(hn + bhh_n) ----
    CPWAIT(); __syncthreads();
    stageT(sb+SB0H,sb+SB0L,3,tid);               // wih_n
    ZACC(acc);
    gemm_pass(acc,hAh,hAl,sb+SB1H,sb+SB1L,bt);
#pragma unroll
    for(int n=0;n<8;n++)
#pragma unroll
    for(int dg=0;dg<4;dg++){
        int col=(nt0+n)*8+(lane&3)*2+(dg&1);
        int i=(n*4+dg)*256+tid;
        Pg[i]=Pg[i]*(acc[n][dg]+sbias[640+col]);
    }
    // ---- in: acc = m@wih_n;  P = tanh(in + bih_n + P) ----
    CPWAIT(); __syncthreads();
    stageT(sb+SB1H,sb+SB1L,2,tid);               // wih_z
    ZACC(acc);
    gemm_pass(acc,mAh,mAl,sb+SB0H,sb+SB0L,bt);
#pragma unroll
    for(int n=0;n<8;n++)
#pragma unroll
    for(int dg=0;dg<4;dg++){
        int col=(nt0+n)*8+(lane&3)*2+(dg&1);
        int i=(n*4+dg)*256+tid;
        Pg[i]=tanhfast(acc[n][dg]+sbias[256+col]+Pg[i]);
    }
    // ---- z gate + update ----
    CPWAIT(); __syncthreads();
    stageT(sb+SB0H,sb+SB0L,5,tid);               // whh_z
    ZACC(acc);
    gemm_pass(acc,mAh,mAl,sb+SB1H,sb+SB1L,bt);
    CPWAIT(); __syncthreads();
    gemm_pass(acc,hAh,hAl,sb+SB0H,sb+SB0L,bt);
    {
        int rbase=row0+rl;
#pragma unroll
        for(int n=0;n<8;n++){
            int nt=nt0+n, kc=nt>>1;
            float o[4];
#pragma unroll
            for(int dg=0;dg<4;dg++){
                int col=nt*8+(lane&3)*2+(dg&1);
                int j=((nt&1)<<1)|(dg>>1);
                float hv=upbf(hAh[kc*4+j],dg&1)+upbf(hAl[kc*4+j],dg&1);
                float z=sigm(acc[n][dg]+sbias[128+col]+sbias[512+col]);
                float nv=Pg[(n*4+dg)*256+tid];
                o[dg]=(1.f-z)*nv+z*hv;
            }
            int c0=nt*8+(lane&3)*2;
            *(float2*)(hout+(size_t)rbase*D+c0)    =make_float2(o[0],o[1]);
            *(float2*)(hout+(size_t)(rbase+8)*D+c0)=make_float2(o[2],o[3]);
        }
    }
}

// ---------------- row gather ----------------
__global__ void k_gather(float* __restrict__ dst,const float* __restrict__ src,
                         const int* __restrict__ idx,int n){
    int t=blockIdx.x*blockDim.x+threadIdx.x;
    int row=t>>5,l=t&31;if(row>=n)return;
    *(float4*)(dst+(size_t)row*128+l*4)=*(const float4*)(src+(size_t)idx[row]*128+l*4);
}

// ---------------- global mean pool ----------------
__global__ void k_pool(const int* __restrict__ nb){
    int g=blockIdx.x,c=threadIdx.x;
    int lo=0,hi=NN;while(lo<hi){int m=(lo+hi)>>1;if(nb[m]<g)lo=m+1;else hi=m;}
    int s=lo;lo=0;hi=NN;while(lo<hi){int m=(lo+hi)>>1;if(nb[m]<=g)lo=m+1;else hi=m;}
    int e=lo;float sum=0.f;
    for(int r=s;r<e;r++)sum+=d_h[(size_t)r*128+c];
    d_gm[g*128+c]=sum/fmaxf((float)(e-s),1.f);
}

// ---------------- stop head ----------------
__global__ void k_stop(const float* __restrict__ w2,const float* __restrict__ b2,
                       float* __restrict__ out){
    int w=(blockIdx.x*blockDim.x+threadIdx.x)>>5,l=threadIdx.x&31;
    if(w>=NG)return;
    float4 g=*(const float4*)(d_g1+(size_t)w*128+l*4);
    float4 ww=*(const float4*)(w2+l*4);
    float p=g.x*ww.x+g.y*ww.y+g.z*ww.z+g.w*ww.w;
#pragma unroll
    for(int o=16;o>0;o>>=1)p+=__shfl_xor_sync(~0u,p,o);
    if(l==0)out[NS*OPS+w]=p+b2[0];
}

// ---------------- launch ----------------
extern "C" void kernel_launch(void* const* d_in,const int* in_sizes,int n_in,
                              void* d_out,int out_size){
    const int* x   =(const int*)d_in[0];
    const int* st  =(const int*)d_in[1];
    const int* ea  =(const int*)d_in[2];
    const int* ei  =(const int*)d_in[3];
    const int* sni =(const int*)d_in[4];
    const int* nb  =(const int*)d_in[5];
    const float* embB=(const float*)d_in[6];
    const float* embS=(const float*)d_in[7];
    const float* embBond=(const float*)d_in[8];
    const float* b2e_w1=(const float*)d_in[9],  *b2e_b1=(const float*)d_in[10];
    const float* b2e_w2=(const float*)d_in[11], *b2e_b2=(const float*)d_in[12];
    const float* conv_root=(const float*)d_in[13], *conv_bias=(const float*)d_in[14];
    const float* w_ih=(const float*)d_in[15], *w_hh=(const float*)d_in[16];
    const float* b_ih=(const float*)d_in[17], *b_hh=(const float*)d_in[18];
    const float* s2p_w1=(const float*)d_in[19], *s2p_b1=(const float*)d_in[20];
    const float* s2p_w2=(const float*)d_in[21], *s2p_b2=(const float*)d_in[22];
    const float* s2p_w3=(const float*)d_in[23], *s2p_b3=(const float*)d_in[24];
    const float* g2p_w1=(const float*)d_in[25], *g2p_b1=(const float*)d_in[26];
    const float* g2p_w2=(const float*)d_in[27], *g2p_b2=(const float*)d_in[28];
    float* out=(float*)d_out;

    void* p;
    cudaGetSymbolAddress(&p,d_h);   float* ph =(float*)p;
    cudaGetSymbolAddress(&p,d_h2);  float* ph2=(float*)p;
    cudaGetSymbolAddress(&p,d_m);   float* pm =(float*)p;
    cudaGetSymbolAddress(&p,d_sg);  float* psg=(float*)p;
    cudaGetSymbolAddress(&p,d_se);  float* pse=(float*)p;
    cudaGetSymbolAddress(&p,d_s1);  float* ps1=(float*)p;
    cudaGetSymbolAddress(&p,d_gm);  float* pgm=(float*)p;
    cudaGetSymbolAddress(&p,d_g1);  float* pg1=(float*)p;

    static int attr_set=0;
    if(!attr_set){
        cudaFuncSetAttribute(k_step_mma,cudaFuncAttributeMaxDynamicSharedMemorySize,SMT);
        attr_set=1;
    }

    // launch 1: deg zero + weight prep + emb gather (fused)
    k_prep0<<<1024,256>>>(x,embB,conv_root,w_ih,w_hh,pm);
    // launch 2: CSR count/scan/fill/sort (fused, internal grid barriers)
    k_csr<<<CSRB,1024>>>(ei);
    // launches 3-4: block2emb
    k_gemm<<<dim3(NN/64,1),256>>>(pm,  b2e_w1,b2e_b1,nullptr,0,ph2,128,128,128,1,1);
    k_gemm<<<dim3(NN/64,1),256>>>(ph2, b2e_w2,b2e_b2,nullptr,0,ph, 128,128,128,1,0);

    // launches 5-16: conv steps (launch #6 = steady-state step -> ncu target)
    for(int s=0;s<NSTEPS;s++){
        const float* hi=(s&1)?ph2:ph;
        float* ho=(s&1)?ph:ph2;
        k_step_mma<<<NN/64,256,SMT>>>(hi,ho,ei,ea,embBond,conv_bias,b_ih,b_hh);
    }

    // stem head
    k_gather<<<NS*32/256,256>>>(psg,ph,sni,NS);
    k_gather<<<NS*32/256,256>>>(pse,embS,st,NS);
    k_gemm<<<dim3(NS/64,1),256>>>(psg,s2p_w1,    nullptr,nullptr,0,ps1,128,128,256,1,0);
    k_gemm<<<dim3(NS/64,1),256>>>(pse,s2p_w1+128,s2p_b1, ps1,128,  ps1,128,128,256,1,1);
    k_gemm<<<dim3(NS/64,1),256>>>(ps1,s2p_w2,s2p_b2,nullptr,0,pm, 128,128,128,1,1);
    k_gemm<<<dim3(NS/64,1),256>>>(pm, s2p_w3,s2p_b3,nullptr,0,out,105,105,128,1,0);

    // stop head
    k_pool<<<NG,128>>>(nb);
    k_gemm<<<dim3(NG/64,1),256>>>(pgm,g2p_w1,g2p_b1,nullptr,0,pg1,128,128,128,1,1);
    k_stop<<<NG/8,256>>>(g2p_w2,g2p_b2,out);
}

// round 12
// speedup vs baseline: 1.0601x; 1.0297x over previous
#include <cuda_runtime.h>
#include <cuda_bf16.h>
#include <math.h>
#include <stdint.h>

#define D 128
#define NN 8192
#define NE 16384
#define NS 4096
#define NG 256
#define OPS 105
#define NSTEPS 12
#define ATS 68

typedef unsigned long long ull;

// ---------------- scratch ----------------
__device__ float d_h[NN*D], d_h2[NN*D], d_agg[NN*D], d_m[NN*D];
__device__ float d_sg[NS*D], d_se[NS*D], d_s1[NS*D];
__device__ float d_gm[NG*D], d_g1[NG*D];
__device__ int   d_deg[NN], d_off[NN+1], d_cur[NN], d_csr[NE];
__device__ float d_invdeg[NN];
__device__ __nv_bfloat16 d_bwh[7*16384], d_bwl[7*16384];
__device__ unsigned g_cnt=0, g_epoch=0;

// ---------------- helpers ----------------
__device__ __forceinline__ ull pack2(float x){unsigned u=__float_as_uint(x);ull r;asm("mov.b64 %0,{%1,%1};":"=l"(r):"r"(u));return r;}
__device__ __forceinline__ void fma2(ull&a,ull x,ull y){asm("fma.rn.f32x2 %0,%1,%2,%0;":"+l"(a):"l"(x),"l"(y));}
__device__ __forceinline__ float lo32(ull v){return __uint_as_float((unsigned)v);}
__device__ __forceinline__ float hi32(ull v){return __uint_as_float((unsigned)(v>>32));}
__device__ __forceinline__ float lrelu(float v){return v>0.f?v:0.01f*v;}
__device__ __forceinline__ float sigm(float x){float e=__expf(-x);return __fdividef(1.f,1.f+e);}
__device__ __forceinline__ float tanhfast(float x){
    x=fminf(fmaxf(x,-9.f),9.f);
    float t=__expf(2.f*x);
    return __fdividef(t-1.f,t+1.f);
}
__device__ __forceinline__ uint32_t s2u(const void* p){
    uint32_t a; asm("{ .reg .u64 t; cvta.to.shared.u64 t, %1; cvt.u32.u64 %0, t; }":"=r"(a):"l"(p)); return a;
}
__device__ __forceinline__ uint32_t pkbf(float a,float b){
    uint32_t r; asm("cvt.rn.bf16x2.f32 %0, %1, %2;":"=r"(r):"f"(b),"f"(a)); return r;
}
__device__ __forceinline__ float upbf(uint32_t u,int slot){
    return __uint_as_float((slot?(u>>16):(u&0xffffu))<<16);
}

#define CP16(s,g)  asm volatile("cp.async.cg.shared.global [%0], [%1], 16;"::"r"(s),"l"(g):"memory")
#define CPCOMMIT() asm volatile("cp.async.commit_group;":::"memory")
#define CPWAIT()   asm volatile("cp.async.wait_group 0;":::"memory")
#define LDSM4(r0,r1,r2,r3,a) asm volatile( \
    "ldmatrix.sync.aligned.m8n8.x4.shared.b16 {%0,%1,%2,%3},[%4];" \
    :"=r"(r0),"=r"(r1),"=r"(r2),"=r"(r3):"r"(a))
#define MMA(dd,aa,b0,b1) asm volatile( \
    "mma.sync.aligned.m16n8k16.row.col.f32.bf16.bf16.f32 {%0,%1,%2,%3},{%4,%5,%6,%7},{%8,%9},{%0,%1,%2,%3};" \
    : "+f"((dd)[0]),"+f"((dd)[1]),"+f"((dd)[2]),"+f"((dd)[3]) \
    : "r"((aa)[0]),"r"((aa)[1]),"r"((aa)[2]),"r"((aa)[3]),"r"(b0),"r"(b1))

// ---------------- prologue #1: weight prep + deg zero ----------------
__global__ void k_prep0(const float* __restrict__ root,const float* __restrict__ wih,
                        const float* __restrict__ whh){
    int t=blockIdx.x*blockDim.x+threadIdx.x;    // 448 x 256
    if(t<NN)d_deg[t]=0;
    if(t<7*16384){
        int tt=t>>14, rem=t&16383, n=rem>>7, k=rem&127;
        float v;
        if(tt==0)      v=root[k*128+n];
        else if(tt<4)  v=wih[((tt-1)*128+n)*128+k];
        else           v=whh[((tt-4)*128+n)*128+k];
        __nv_bfloat16 hi=__float2bfloat16(v);
        __nv_bfloat16 lo=__float2bfloat16(v-__bfloat162float(hi));
        d_bwh[t]=hi; d_bwl[t]=lo;
    }
}

// ---------------- prologue #2: fused CSR ----------------
#define CSRB 32
__device__ __forceinline__ void gridbar32(unsigned tgt){
    __syncthreads();
    if(threadIdx.x==0){
        __threadfence();
        unsigned old=atomicAdd(&g_cnt,1u);
        if(old==CSRB-1u){ g_cnt=0u; __threadfence(); atomicAdd(&g_epoch,1u); }
        else { while((int)(*(volatile unsigned*)&g_epoch - tgt) < 0){} }
        __threadfence();
    }
    __syncthreads();
}
__global__ void __launch_bounds__(1024)
k_csr(const int* __restrict__ ei){
    __shared__ unsigned s_ep0;
    if(threadIdx.x==0)s_ep0=*(volatile unsigned*)&g_epoch;
    __syncthreads();
    unsigned ep0=s_ep0;
    int gt=blockIdx.x*1024+threadIdx.x;
    if(gt<NE)atomicAdd(&d_deg[ei[NE+gt]],1);
    gridbar32(ep0+1u);
    if(blockIdx.x==0){
        __shared__ int ws[32];
        int t=threadIdx.x,base=t*8,v[8],pre[8],s=0;
#pragma unroll
        for(int i=0;i<8;i++){v[i]=d_deg[base+i];pre[i]=s;s+=v[i];}
        int lane=t&31,wid=t>>5,xx=s;
#pragma unroll
        for(int o=1;o<32;o<<=1){int y=__shfl_up_sync(~0u,xx,o);if(lane>=o)xx+=y;}
        if(lane==31)ws[wid]=xx;
        __syncthreads();
        if(wid==0){int w0=ws[lane],x2=w0;
#pragma unroll
            for(int o=1;o<32;o<<=1){int y=__shfl_up_sync(~0u,x2,o);if(lane>=o)x2+=y;}
            ws[lane]=x2-w0;}
        __syncthreads();
        int obase=ws[wid]+(xx-s);
#pragma unroll
        for(int i=0;i<8;i++){int o=obase+pre[i];d_off[base+i]=o;d_cur[base+i]=o;
            d_invdeg[base+i]=v[i]>0?1.0f/(float)v[i]:0.0f;}
        if(t==1023)d_off[NN]=obase+s;
    }
    gridbar32(ep0+2u);
    if(gt<NE){int p=atomicAdd(&d_cur[ei[NE+gt]],1);d_csr[p]=gt;}
    gridbar32(ep0+3u);
    if(gt<NN){
        int a=d_off[gt],b=d_off[gt+1];
        for(int i=a+1;i<b;i++){int key=d_csr[i],j=i-1;
            while(j>=a&&d_csr[j]>key){d_csr[j+1]=d_csr[j];j--;}d_csr[j+1]=key;}
    }
}

// ---------------- prologue #3: fused block2emb (both layers) ---------------
__global__ void __launch_bounds__(256)
k_b2e(const int* __restrict__ x,const float* __restrict__ embB,
      const float* __restrict__ w1,const float* __restrict__ b1,
      const float* __restrict__ w2,const float* __restrict__ b2){
    __shared__ float At[32*ATS];
    __shared__ float Mt[128*ATS];
    __shared__ float Bp[32*128];
    int t=threadIdx.x,rg=t>>5,cg=t&31;
    int row0=blockIdx.x*64;
    int xi=x[row0+(t&63)];
    ull acc[4][4];
#pragma unroll
    for(int p=0;p<4;p++)
#pragma unroll
        for(int c=0;c<4;c++)acc[p][c]=0ull;
    for(int kc=0;kc<128;kc+=32){
        { int rl=t&63,kg=t>>6;const float*src=embB+(size_t)xi*128+kc+kg*8;
          float4 v0=*(const float4*)src,v1=*(const float4*)(src+4);int kb=kg*8;
          At[(kb+0)*ATS+rl]=v0.x;At[(kb+1)*ATS+rl]=v0.y;At[(kb+2)*ATS+rl]=v0.z;At[(kb+3)*ATS+rl]=v0.w;
          At[(kb+4)*ATS+rl]=v1.x;At[(kb+5)*ATS+rl]=v1.y;At[(kb+6)*ATS+rl]=v1.z;At[(kb+7)*ATS+rl]=v1.w;}
        { int j=t>>1,h=t&1;const float*src=w1+(size_t)j*128+kc+h*16;
#pragma unroll
          for(int i=0;i<4;i++){float4 v=*(const float4*)(src+i*4);int kk=h*16+i*4;
              Bp[(kk+0)*128+j]=v.x;Bp[(kk+1)*128+j]=v.y;Bp[(kk+2)*128+j]=v.z;Bp[(kk+3)*128+j]=v.w;}}
        __syncthreads();
        const float*Ab=At+rg*8;const float*Bb=Bp+cg*4;
#pragma unroll 8
        for(int k=0;k<32;k++){
            ulonglong2 A0=*(const ulonglong2*)(Ab+k*ATS);
            ulonglong2 A1=*(const ulonglong2*)(Ab+k*ATS+4);
            float4 b=*(const float4*)(Bb+k*128);
            ull B0=pack2(b.x),B1=pack2(b.y),B2=pack2(b.z),B3=pack2(b.w);
            fma2(acc[0][0],A0.x,B0);fma2(acc[0][1],A0.x,B1);fma2(acc[0][2],A0.x,B2);fma2(acc[0][3],A0.x,B3);
            fma2(acc[1][0],A0.y,B0);fma2(acc[1][1],A0.y,B1);fma2(acc[1][2],A0.y,B2);fma2(acc[1][3],A0.y,B3);
            fma2(acc[2][0],A1.x,B0);fma2(acc[2][1],A1.x,B1);fma2(acc[2][2],A1.x,B2);fma2(acc[2][3],A1.x,B3);
            fma2(acc[3][0],A1.y,B0);fma2(acc[3][1],A1.y,B1);fma2(acc[3][2],A1.y,B2);fma2(acc[3][3],A1.y,B3);
        }
        __syncthreads();
    }
    // epilogue 1 -> Mt (transposed [k][row])
#pragma unroll
    for(int c=0;c<4;c++){
        int j=cg*4+c;float bv=b1[j];
#pragma unroll
        for(int p=0;p<4;p++){
            int r=rg*8+2*p;
            Mt[j*ATS+r]  =lrelu(lo32(acc[p][c])+bv);
            Mt[j*ATS+r+1]=lrelu(hi32(acc[p][c])+bv);
        }
    }
    __syncthreads();
    // layer 2
#pragma unroll
    for(int p=0;p<4;p++)
#pragma unroll
        for(int c=0;c<4;c++)acc[p][c]=0ull;
    for(int kc=0;kc<128;kc+=32){
        { int j=t>>1,h=t&1;const float*src=w2+(size_t)j*128+kc+h*16;
#pragma unroll
          for(int i=0;i<4;i++){float4 v=*(const float4*)(src+i*4);int kk=h*16+i*4;
              Bp[(kk+0)*128+j]=v.x;Bp[(kk+1)*128+j]=v.y;Bp[(kk+2)*128+j]=v.z;Bp[(kk+3)*128+j]=v.w;}}
        __syncthreads();
        const float*Ab=Mt+kc*ATS+rg*8;const float*Bb=Bp+cg*4;
#pragma unroll 8
        for(int k=0;k<32;k++){
            ulonglong2 A0=*(const ulonglong2*)(Ab+k*ATS);
            ulonglong2 A1=*(const ulonglong2*)(Ab+k*ATS+4);
            float4 b=*(const float4*)(Bb+k*128);
            ull B0=pack2(b.x),B1=pack2(b.y),B2=pack2(b.z),B3=pack2(b.w);
            fma2(acc[0][0],A0.x,B0);fma2(acc[0][1],A0.x,B1);fma2(acc[0][2],A0.x,B2);fma2(acc[0][3],A0.x,B3);
            fma2(acc[1][0],A0.y,B0);fma2(acc[1][1],A0.y,B1);fma2(acc[1][2],A0.y,B2);fma2(acc[1][3],A0.y,B3);
            fma2(acc[2][0],A1.x,B0);fma2(acc[2][1],A1.x,B1);fma2(acc[2][2],A1.x,B2);fma2(acc[2][3],A1.x,B3);
            fma2(acc[3][0],A1.y,B0);fma2(acc[3][1],A1.y,B1);fma2(acc[3][2],A1.y,B2);fma2(acc[3][3],A1.y,B3);
        }
        __syncthreads();
    }
#pragma unroll
    for(int c=0;c<4;c++){
        int j=cg*4+c;float bv=b2[j];
#pragma unroll
        for(int p=0;p<4;p++){
            int r=row0+rg*8+2*p;
            d_h[(size_t)r*128+j]=lo32(acc[p][c])+bv;
            d_h[(size_t)(r+1)*128+j]=hi32(acc[p][c])+bv;
        }
    }
}

// ---------------- generic fp32 GEMM (heads) ----------------
__global__ void __launch_bounds__(256)
k_gemm(const float* __restrict__ A,const float* __restrict__ W,
       const float* __restrict__ bias,const float* __restrict__ add,int ldadd,
       float* __restrict__ C,int ldc,int N,int ldw,int transW,int act){
    __shared__ float At[32*ATS];
    __shared__ float Bp[32*128];
    int t=threadIdx.x,rg=t>>5,cg=t&31;
    int row0=blockIdx.x*64,jt=blockIdx.y*128;
    ull acc[4][4];
#pragma unroll
    for(int p=0;p<4;p++)
#pragma unroll
        for(int c=0;c<4;c++)acc[p][c]=0ull;
    for(int kc=0;kc<128;kc+=32){
        { int rl=t&63,kg=t>>6;const float*src=A+(size_t)(row0+rl)*128+kc+kg*8;
          float4 v0=*(const float4*)src,v1=*(const float4*)(src+4);int kb=kg*8;
          At[(kb+0)*ATS+rl]=v0.x;At[(kb+1)*ATS+rl]=v0.y;At[(kb+2)*ATS+rl]=v0.z;At[(kb+3)*ATS+rl]=v0.w;
          At[(kb+4)*ATS+rl]=v1.x;At[(kb+5)*ATS+rl]=v1.y;At[(kb+6)*ATS+rl]=v1.z;At[(kb+7)*ATS+rl]=v1.w;}
        if(transW){
            int j=t>>1,h=t&1;
            if(jt+j<N){const float*src=W+(size_t)(jt+j)*ldw+kc+h*16;
#pragma unroll
                for(int i=0;i<4;i++){float4 v=*(const float4*)(src+i*4);int kk=h*16+i*4;
                    Bp[(kk+0)*128+j]=v.x;Bp[(kk+1)*128+j]=v.y;Bp[(kk+2)*128+j]=v.z;Bp[(kk+3)*128+j]=v.w;}
            }else{
#pragma unroll
                for(int i=0;i<16;i++)Bp[(h*16+i)*128+j]=0.f;}
        }else{
#pragma unroll
            for(int i=0;i<4;i++){int g=i*1024+t*4;*(float4*)(Bp+g)=*(const float4*)(W+kc*128+g);}
        }
        __syncthreads();
        const float*Ab=At+rg*8;const float*Bb=Bp+cg*4;
#pragma unroll 8
        for(int k=0;k<32;k++){
            ulonglong2 A0=*(const ulonglong2*)(Ab+k*ATS);
            ulonglong2 A1=*(const ulonglong2*)(Ab+k*ATS+4);
            float4 b=*(const float4*)(Bb+k*128);
            ull B0=pack2(b.x),B1=pack2(b.y),B2=pack2(b.z),B3=pack2(b.w);
            fma2(acc[0][0],A0.x,B0);fma2(acc[0][1],A0.x,B1);fma2(acc[0][2],A0.x,B2);fma2(acc[0][3],A0.x,B3);
            fma2(acc[1][0],A0.y,B0);fma2(acc[1][1],A0.y,B1);fma2(acc[1][2],A0.y,B2);fma2(acc[1][3],A0.y,B3);
            fma2(acc[2][0],A1.x,B0);fma2(acc[2][1],A1.x,B1);fma2(acc[2][2],A1.x,B2);fma2(acc[2][3],A1.x,B3);
            fma2(acc[3][0],A1.y,B0);fma2(acc[3][1],A1.y,B1);fma2(acc[3][2],A1.y,B2);fma2(acc[3][3],A1.y,B3);
        }
        __syncthreads();
    }
#pragma unroll
    for(int c=0;c<4;c++){
        int j=jt+cg*4+c;if(j>=N)continue;
        float bv=bias?bias[j]:0.f;
#pragma unroll
        for(int p=0;p<4;p++){
            int r=row0+rg*8+2*p;
            float v0=lo32(acc[p][c])+bv,v1=hi32(acc[p][c])+bv;
            if(add){v0+=add[(size_t)r*ldadd+j];v1+=add[(size_t)(r+1)*ldadd+j];}
            if(act){v0=lrelu(v0);v1=lrelu(v1);}
            C[(size_t)r*ldc+j]=v0;C[(size_t)(r+1)*ldc+j]=v1;
        }
    }
}

// ---------------- mma.sync fused conv step (R8-exact) ----------------
#define SB0H 0
#define SB0L 34816
#define SB1H 69632
#define SB1L 104448
#define SPM  139264
#define SBI  173056
#define SMT  176640
#define STRB 272

__device__ __forceinline__ void stageT(uint32_t sH,uint32_t sL,int tile,int tid){
    const char* gh=(const char*)(d_bwh+tile*16384);
    const char* gl=(const char*)(d_bwl+tile*16384);
#pragma unroll
    for(int q=0;q<8;q++){
        int i=tid+q*256, n=i>>4, c=i&15;
        CP16(sH+n*STRB+c*16, gh+n*256+c*16);
        CP16(sL+n*STRB+c*16, gl+n*256+c*16);
    }
    CPCOMMIT();
}

__device__ __forceinline__ void gemm_pass(float acc[8][4],const uint32_t aH[32],const uint32_t aL[32],
                                          uint32_t bh,uint32_t bl,int bt){
#pragma unroll
    for(int kc=0;kc<8;kc++){
#pragma unroll
        for(int jj=0;jj<4;jj++){
            uint32_t h0,h1,h2,h3,l0,l1,l2,l3;
            uint32_t off=jj*4352+kc*32+bt;
            LDSM4(h0,h1,h2,h3,bh+off);
            LDSM4(l0,l1,l2,l3,bl+off);
            MMA(acc[2*jj],  aH+kc*4,h0,h1);
            MMA(acc[2*jj+1],aH+kc*4,h2,h3);
            MMA(acc[2*jj],  aL+kc*4,h0,h1);
            MMA(acc[2*jj+1],aL+kc*4,h2,h3);
            MMA(acc[2*jj],  aH+kc*4,l0,l1);
            MMA(acc[2*jj+1],aH+kc*4,l2,l3);
        }
    }
}
#define ZACC(acc) {_Pragma("unroll") for(int _n=0;_n<8;_n++){_Pragma("unroll") for(int _d=0;_d<4;_d++)(acc)[_n][_d]=0.f;}}

__global__ void __launch_bounds__(256,1)
k_step_mma(const float* __restrict__ hin, float* __restrict__ hout,
           const int* __restrict__ ei, const int* __restrict__ ea,
           const float* __restrict__ embBond,
           const float* __restrict__ cbias,
           const float* __restrict__ bih, const float* __restrict__ bhh){
    extern __shared__ char smem[];
    uint32_t sb=s2u(smem);
    float* Pm=(float*)(smem+SPM);
    float* Pg=(float*)(smem+SPM);
    float* sbias=(float*)(smem+SBI);
    int tid=threadIdx.x, w=tid>>5, lane=tid&31;
    int row0=blockIdx.x*64;
    int wr=w&3, nt0=(w>>2)*8;
    int bt=nt0*2176+((lane>>3)>>1)*2176+(lane&7)*STRB+((lane>>3)&1)*16;
    int rl=16*wr+(lane>>2);

    for(int i=tid;i<384;i+=256){sbias[i]=bih[i];sbias[384+i]=bhh[i];}
    if(tid<128)sbias[768+tid]=cbias[tid];

    stageT(sb+SB0H,sb+SB0L,0,tid);   // rootT

    uint32_t hAh[32],hAl[32];
    {
        int ra=row0+rl;
#pragma unroll
        for(int kc=0;kc<8;kc++)
#pragma unroll
        for(int j=0;j<4;j++){
            int row=ra+(j&1)*8;
            int col=kc*16+(j>>1)*8+(lane&3)*2;
            float2 v=*(const float2*)(hin+(size_t)row*128+col);
            uint32_t ph=pkbf(v.x,v.y);
            hAh[kc*4+j]=ph;
            hAl[kc*4+j]=pkbf(v.x-upbf(ph,0),v.y-upbf(ph,1));
        }
    }

    // ---- edge aggregation -> d_agg (global, overlaps staging) ----
#pragma unroll 1
    for(int q=0;q<8;q++){
        int n=row0+8*w+q;
        int s0=d_off[n],s1=d_off[n+1];
        float4 acc4=make_float4(0.f,0.f,0.f,0.f);
        for(int i=s0;i<s1;i++){
            int e=d_csr[i];
            int s=ei[e],a0=ea[2*e],a1=ea[2*e+1];
            float4 hv=*(const float4*)(hin+(size_t)s*D+lane*4);
            float4 b0=*(const float4*)(embBond+(size_t)a0*D+lane*4);
            float p=hv.x*b0.x+hv.y*b0.y+hv.z*b0.z+hv.w*b0.w;
#pragma unroll
            for(int o=16;o>0;o>>=1)p+=__shfl_xor_sync(~0u,p,o);
            float4 b1=*(const float4*)(embBond+(size_t)a1*D+lane*4);
            acc4.x+=p*b1.x;acc4.y+=p*b1.y;acc4.z+=p*b1.z;acc4.w+=p*b1.w;
        }
        float iv=d_invdeg[n];
        acc4.x*=iv;acc4.y*=iv;acc4.z*=iv;acc4.w*=iv;
        *(float4*)(d_agg+(size_t)n*D+lane*4)=acc4;
    }

    float acc[8][4];
    // ---- conv ----
    CPWAIT(); __syncthreads();
    stageT(sb+SB1H,sb+SB1L,1,tid);               // wih_r
    ZACC(acc);
    gemm_pass(acc,hAh,hAl,sb+SB0H,sb+SB0L,bt);
    {
#pragma unroll
        for(int n=0;n<8;n++){
            int colg=(nt0+n)*8+(lane&3)*2;
            float2 a0=*(const float2*)(d_agg+(size_t)(row0+rl)*D+colg);
            float2 a1=*(const float2*)(d_agg+(size_t)(row0+rl+8)*D+colg);
            float b0v=sbias[768+colg],b1v=sbias[768+colg+1];
            float2 m0=make_float2(lrelu(acc[n][0]+a0.x+b0v),lrelu(acc[n][1]+a0.y+b1v));
            float2 m1=make_float2(lrelu(acc[n][2]+a1.x+b0v),lrelu(acc[n][3]+a1.y+b1v));
            *(float2*)(Pm+rl*132+colg)=m0;
            *(float2*)(Pm+(rl+8)*132+colg)=m1;
        }
    }
    __syncthreads();
    uint32_t mAh[32],mAl[32];
#pragma unroll
    for(int kc=0;kc<8;kc++)
#pragma unroll
    for(int j=0;j<4;j++){
        int row=rl+(j&1)*8;
        int col=kc*16+(j>>1)*8+(lane&3)*2;
        float2 v=*(const float2*)(Pm+row*132+col);
        uint32_t ph=pkbf(v.x,v.y);
        mAh[kc*4+j]=ph;
        mAl[kc*4+j]=pkbf(v.x-upbf(ph,0),v.y-upbf(ph,1));
    }

    // ---- r gate ----
    CPWAIT(); __syncthreads();
    stageT(sb+SB0H,sb+SB0L,4,tid);               // whh_r
    ZACC(acc);
    gemm_pass(acc,mAh,mAl,sb+SB1H,sb+SB1L,bt);
    CPWAIT(); __syncthreads();
    stageT(sb+SB1H,sb+SB1L,6,tid);               // whh_n
    gemm_pass(acc,hAh,hAl,sb+SB0H,sb+SB0L,bt);
#pragma unroll
    for(int n=0;n<8;n++)
#pragma unroll
    for(int dg=0;dg<4;dg++){
        int col=(nt0+n)*8+(lane&3)*2+(dg&1);
        Pg[(n*4+dg)*256+tid]=sigm(acc[n][dg]+sbias[col]+sbias[384+col]);
    }
    // ---- hn ----
    CPWAIT(); __syncthreads();
    stageT(sb+SB0H,sb+SB0L,3,tid);               // wih_n
    ZACC(acc);
    gemm_pass(acc,hAh,hAl,sb+SB1H,sb+SB1L,bt);
#pragma unroll
    for(int n=0;n<8;n++)
#pragma unroll
    for(int dg=0;dg<4;dg++){
        int col=(nt0+n)*8+(lane&3)*2+(dg&1);
        int i=(n*4+dg)*256+tid;
        Pg[i]=Pg[i]*(acc[n][dg]+sbias[640+col]);
    }
    // ---- in ----
    CPWAIT(); __syncthreads();
    stageT(sb+SB1H,sb+SB1L,2,tid);               // wih_z
    ZACC(acc);
    gemm_pass(acc,mAh,mAl,sb+SB0H,sb+SB0L,bt);
#pragma unroll
    for(int n=0;n<8;n++)
#pragma unroll
    for(int dg=0;dg<4;dg++){
        int col=(nt0+n)*8+(lane&3)*2+(dg&1);
        int i=(n*4+dg)*256+tid;
        Pg[i]=tanhfast(acc[n][dg]+sbias[256+col]+Pg[i]);
    }
    // ---- z gate + update ----
    CPWAIT(); __syncthreads();
    stageT(sb+SB0H,sb+SB0L,5,tid);               // whh_z
    ZACC(acc);
    gemm_pass(acc,mAh,mAl,sb+SB1H,sb+SB1L,bt);
    CPWAIT(); __syncthreads();
    gemm_pass(acc,hAh,hAl,sb+SB0H,sb+SB0L,bt);
    {
        int rbase=row0+rl;
#pragma unroll
        for(int n=0;n<8;n++){
            int nt=nt0+n, kc=nt>>1;
            float o[4];
#pragma unroll
            for(int dg=0;dg<4;dg++){
                int col=nt*8+(lane&3)*2+(dg&1);
                int j=((nt&1)<<1)|(dg>>1);
                float hv=upbf(hAh[kc*4+j],dg&1)+upbf(hAl[kc*4+j],dg&1);
                float z=sigm(acc[n][dg]+sbias[128+col]+sbias[512+col]);
                float nv=Pg[(n*4+dg)*256+tid];
                o[dg]=(1.f-z)*nv+z*hv;
            }
            int c0=nt*8+(lane&3)*2;
            *(float2*)(hout+(size_t)rbase*D+c0)    =make_float2(o[0],o[1]);
            *(float2*)(hout+(size_t)(rbase+8)*D+c0)=make_float2(o[2],o[3]);
        }
    }
}

// ---------------- row gather ----------------
__global__ void k_gather(float* __restrict__ dst,const float* __restrict__ src,
                         const int* __restrict__ idx,int n){
    int t=blockIdx.x*blockDim.x+threadIdx.x;
    int row=t>>5,l=t&31;if(row>=n)return;
    *(float4*)(dst+(size_t)row*128+l*4)=*(const float4*)(src+(size_t)idx[row]*128+l*4);
}

// ---------------- global mean pool ----------------
__global__ void k_pool(const int* __restrict__ nb){
    int g=blockIdx.x,c=threadIdx.x;
    int lo=0,hi=NN;while(lo<hi){int m=(lo+hi)>>1;if(nb[m]<g)lo=m+1;else hi=m;}
    int s=lo;lo=0;hi=NN;while(lo<hi){int m=(lo+hi)>>1;if(nb[m]<=g)lo=m+1;else hi=m;}
    int e=lo;float sum=0.f;
    for(int r=s;r<e;r++)sum+=d_h[(size_t)r*128+c];
    d_gm[g*128+c]=sum/fmaxf((float)(e-s),1.f);
}

// ---------------- stop head ----------------
__global__ void k_stop(const float* __restrict__ w2,const float* __restrict__ b2,
                       float* __restrict__ out){
    int w=(blockIdx.x*blockDim.x+threadIdx.x)>>5,l=threadIdx.x&31;
    if(w>=NG)return;
    float4 g=*(const float4*)(d_g1+(size_t)w*128+l*4);
    float4 ww=*(const float4*)(w2+l*4);
    float p=g.x*ww.x+g.y*ww.y+g.z*ww.z+g.w*ww.w;
#pragma unroll
    for(int o=16;o>0;o>>=1)p+=__shfl_xor_sync(~0u,p,o);
    if(l==0)out[NS*OPS+w]=p+b2[0];
}

// ---------------- launch ----------------
extern "C" void kernel_launch(void* const* d_in,const int* in_sizes,int n_in,
                              void* d_out,int out_size){
    const int* x   =(const int*)d_in[0];
    const int* st  =(const int*)d_in[1];
    const int* ea  =(const int*)d_in[2];
    const int* ei  =(const int*)d_in[3];
    const int* sni =(const int*)d_in[4];
    const int* nb  =(const int*)d_in[5];
    const float* embB=(const float*)d_in[6];
    const float* embS=(const float*)d_in[7];
    const float* embBond=(const float*)d_in[8];
    const float* b2e_w1=(const float*)d_in[9],  *b2e_b1=(const float*)d_in[10];
    const float* b2e_w2=(const float*)d_in[11], *b2e_b2=(const float*)d_in[12];
    const float* conv_root=(const float*)d_in[13], *conv_bias=(const float*)d_in[14];
    const float* w_ih=(const float*)d_in[15], *w_hh=(const float*)d_in[16];
    const float* b_ih=(const float*)d_in[17], *b_hh=(const float*)d_in[18];
    const float* s2p_w1=(const float*)d_in[19], *s2p_b1=(const float*)d_in[20];
    const float* s2p_w2=(const float*)d_in[21], *s2p_b2=(const float*)d_in[22];
    const float* s2p_w3=(const float*)d_in[23], *s2p_b3=(const float*)d_in[24];
    const float* g2p_w1=(const float*)d_in[25], *g2p_b1=(const float*)d_in[26];
    const float* g2p_w2=(const float*)d_in[27], *g2p_b2=(const float*)d_in[28];
    float* out=(float*)d_out;

    void* p;
    cudaGetSymbolAddress(&p,d_h);   float* ph =(float*)p;
    cudaGetSymbolAddress(&p,d_h2);  float* ph2=(float*)p;
    cudaGetSymbolAddress(&p,d_m);   float* pm =(float*)p;
    cudaGetSymbolAddress(&p,d_sg);  float* psg=(float*)p;
    cudaGetSymbolAddress(&p,d_se);  float* pse=(float*)p;
    cudaGetSymbolAddress(&p,d_s1);  float* ps1=(float*)p;
    cudaGetSymbolAddress(&p,d_gm);  float* pgm=(float*)p;
    cudaGetSymbolAddress(&p,d_g1);  float* pg1=(float*)p;

    static int attr_set=0;
    if(!attr_set){
        cudaFuncSetAttribute(k_step_mma,cudaFuncAttributeMaxDynamicSharedMemorySize,SMT);
        attr_set=1;
    }

    // 3 prologue launches -> step #1 lands at ncu slot 6 (harness offset 2)
    k_prep0<<<448,256>>>(conv_root,w_ih,w_hh);
    k_csr  <<<CSRB,1024>>>(ei);
    k_b2e  <<<NN/64,256>>>(x,embB,b2e_w1,b2e_b1,b2e_w2,b2e_b2);

    for(int s=0;s<NSTEPS;s++){
        const float* hi=(s&1)?ph2:ph;
        float* ho=(s&1)?ph:ph2;
        k_step_mma<<<NN/64,256,SMT>>>(hi,ho,ei,ea,embBond,conv_bias,b_ih,b_hh);
    }

    // stem head
    k_gather<<<NS*32/256,256>>>(psg,ph,sni,NS);
    k_gather<<<NS*32/256,256>>>(pse,embS,st,NS);
    k_gemm<<<dim3(NS/64,1),256>>>(psg,s2p_w1,    nullptr,nullptr,0,ps1,128,128,256,1,0);
    k_gemm<<<dim3(NS/64,1),256>>>(pse,s2p_w1+128,s2p_b1, ps1,128,  ps1,128,128,256,1,1);
    k_gemm<<<dim3(NS/64,1),256>>>(ps1,s2p_w2,s2p_b2,nullptr,0,pm, 128,128,128,1,1);
    k_gemm<<<dim3(NS/64,1),256>>>(pm, s2p_w3,s2p_b3,nullptr,0,out,105,105,128,1,0);

    // stop head
    k_pool<<<NG,128>>>(nb);
    k_gemm<<<dim3(NG/64,1),256>>>(pgm,g2p_w1,g2p_b1,nullptr,0,pg1,128,128,128,1,1);
    k_stop<<<NG/8,256>>>(g2p_w2,g2p_b2,out);
}

// round 13
// speedup vs baseline: 1.1173x; 1.0539x over previous
#include <cuda_runtime.h>
#include <cuda_bf16.h>
#include <math.h>
#include <stdint.h>

#define D 128
#define NN 8192
#define NE 16384
#define NS 4096
#define NG 256
#define OPS 105
#define NSTEPS 12
#define ATS 68

typedef unsigned long long ull;

// ---------------- scratch ----------------
__device__ float d_h[NN*D], d_h2[NN*D], d_agg[NN*D], d_m[NN*D];
__device__ float d_sg[NS*D], d_se[NS*D], d_s1[NS*D];
__device__ float d_gm[NG*D], d_g1[NG*D];
__device__ int   d_deg[NN], d_off[NN+1], d_cur[NN], d_csr[NE];
__device__ float d_invdeg[NN];
__device__ __nv_bfloat16 d_bwh[7*16384], d_bwl[7*16384];
__device__ unsigned g_cnt=0, g_epoch=0;

// ---------------- helpers ----------------
__device__ __forceinline__ ull pack2(float x){unsigned u=__float_as_uint(x);ull r;asm("mov.b64 %0,{%1,%1};":"=l"(r):"r"(u));return r;}
__device__ __forceinline__ void fma2(ull&a,ull x,ull y){asm("fma.rn.f32x2 %0,%1,%2,%0;":"+l"(a):"l"(x),"l"(y));}
__device__ __forceinline__ float lo32(ull v){return __uint_as_float((unsigned)v);}
__device__ __forceinline__ float hi32(ull v){return __uint_as_float((unsigned)(v>>32));}
__device__ __forceinline__ float lrelu(float v){return v>0.f?v:0.01f*v;}
__device__ __forceinline__ float sigm(float x){float e=__expf(-x);return __fdividef(1.f,1.f+e);}
__device__ __forceinline__ float tanhfast(float x){
    x=fminf(fmaxf(x,-9.f),9.f);
    float t=__expf(2.f*x);
    return __fdividef(t-1.f,t+1.f);
}
__device__ __forceinline__ uint32_t s2u(const void* p){
    uint32_t a; asm("{ .reg .u64 t; cvta.to.shared.u64 t, %1; cvt.u32.u64 %0, t; }":"=r"(a):"l"(p)); return a;
}
__device__ __forceinline__ uint32_t pkbf(float a,float b){
    uint32_t r; asm("cvt.rn.bf16x2.f32 %0, %1, %2;":"=r"(r):"f"(b),"f"(a)); return r;
}
__device__ __forceinline__ float upbf(uint32_t u,int slot){
    return __uint_as_float((slot?(u>>16):(u&0xffffu))<<16);
}

#define CP16(s,g)  asm volatile("cp.async.cg.shared.global [%0], [%1], 16;"::"r"(s),"l"(g):"memory")
#define CPCOMMIT() asm volatile("cp.async.commit_group;":::"memory")
#define CPWAIT()   asm volatile("cp.async.wait_group 0;":::"memory")
#define LDSM4(r0,r1,r2,r3,a) asm volatile( \
    "ldmatrix.sync.aligned.m8n8.x4.shared.b16 {%0,%1,%2,%3},[%4];" \
    :"=r"(r0),"=r"(r1),"=r"(r2),"=r"(r3):"r"(a))
#define MMA(dd,aa,b0,b1) asm volatile( \
    "mma.sync.aligned.m16n8k16.row.col.f32.bf16.bf16.f32 {%0,%1,%2,%3},{%4,%5,%6,%7},{%8,%9},{%0,%1,%2,%3};" \
    : "+f"((dd)[0]),"+f"((dd)[1]),"+f"((dd)[2]),"+f"((dd)[3]) \
    : "r"((aa)[0]),"r"((aa)[1]),"r"((aa)[2]),"r"((aa)[3]),"r"(b0),"r"(b1))

// ---------------- prologue #1: weight prep + deg zero ----------------
__global__ void k_prep0(const float* __restrict__ root,const float* __restrict__ wih,
                        const float* __restrict__ whh){
    int t=blockIdx.x*blockDim.x+threadIdx.x;    // 448 x 256
    if(t<NN)d_deg[t]=0;
    if(t<7*16384){
        int tt=t>>14, rem=t&16383, n=rem>>7, k=rem&127;
        float v;
        if(tt==0)      v=root[k*128+n];
        else if(tt<4)  v=wih[((tt-1)*128+n)*128+k];
        else           v=whh[((tt-4)*128+n)*128+k];
        __nv_bfloat16 hi=__float2bfloat16(v);
        __nv_bfloat16 lo=__float2bfloat16(v-__bfloat162float(hi));
        d_bwh[t]=hi; d_bwl[t]=lo;
    }
}

// ---------------- prologue #2: fused CSR ----------------
#define CSRB 32
__device__ __forceinline__ void gridbar32(unsigned tgt){
    __syncthreads();
    if(threadIdx.x==0){
        __threadfence();
        unsigned old=atomicAdd(&g_cnt,1u);
        if(old==CSRB-1u){ g_cnt=0u; __threadfence(); atomicAdd(&g_epoch,1u); }
        else { while((int)(*(volatile unsigned*)&g_epoch - tgt) < 0){} }
        __threadfence();
    }
    __syncthreads();
}
__global__ void __launch_bounds__(1024)
k_csr(const int* __restrict__ ei){
    __shared__ unsigned s_ep0;
    if(threadIdx.x==0)s_ep0=*(volatile unsigned*)&g_epoch;
    __syncthreads();
    unsigned ep0=s_ep0;
    int gt=blockIdx.x*1024+threadIdx.x;
    if(gt<NE)atomicAdd(&d_deg[ei[NE+gt]],1);
    gridbar32(ep0+1u);
    if(blockIdx.x==0){
        __shared__ int ws[32];
        int t=threadIdx.x,base=t*8,v[8],pre[8],s=0;
#pragma unroll
        for(int i=0;i<8;i++){v[i]=d_deg[base+i];pre[i]=s;s+=v[i];}
        int lane=t&31,wid=t>>5,xx=s;
#pragma unroll
        for(int o=1;o<32;o<<=1){int y=__shfl_up_sync(~0u,xx,o);if(lane>=o)xx+=y;}
        if(lane==31)ws[wid]=xx;
        __syncthreads();
        if(wid==0){int w0=ws[lane],x2=w0;
#pragma unroll
            for(int o=1;o<32;o<<=1){int y=__shfl_up_sync(~0u,x2,o);if(lane>=o)x2+=y;}
            ws[lane]=x2-w0;}
        __syncthreads();
        int obase=ws[wid]+(xx-s);
#pragma unroll
        for(int i=0;i<8;i++){int o=obase+pre[i];d_off[base+i]=o;d_cur[base+i]=o;
            d_invdeg[base+i]=v[i]>0?1.0f/(float)v[i]:0.0f;}
        if(t==1023)d_off[NN]=obase+s;
    }
    gridbar32(ep0+2u);
    if(gt<NE){int p=atomicAdd(&d_cur[ei[NE+gt]],1);d_csr[p]=gt;}
    gridbar32(ep0+3u);
    if(gt<NN){
        int a=d_off[gt],b=d_off[gt+1];
        for(int i=a+1;i<b;i++){int key=d_csr[i],j=i-1;
            while(j>=a&&d_csr[j]>key){d_csr[j+1]=d_csr[j];j--;}d_csr[j+1]=key;}
    }
}

// ---------------- prologue #3: fused block2emb (both layers) ---------------
__global__ void __launch_bounds__(256)
k_b2e(const int* __restrict__ x,const float* __restrict__ embB,
      const float* __restrict__ w1,const float* __restrict__ b1,
      const float* __restrict__ w2,const float* __restrict__ b2){
    __shared__ float At[32*ATS];
    __shared__ float Mt[128*ATS];
    __shared__ float Bp[32*128];
    int t=threadIdx.x,rg=t>>5,cg=t&31;
    int row0=blockIdx.x*64;
    int xi=x[row0+(t&63)];
    ull acc[4][4];
#pragma unroll
    for(int p=0;p<4;p++)
#pragma unroll
        for(int c=0;c<4;c++)acc[p][c]=0ull;
    for(int kc=0;kc<128;kc+=32){
        { int rl=t&63,kg=t>>6;const float*src=embB+(size_t)xi*128+kc+kg*8;
          float4 v0=*(const float4*)src,v1=*(const float4*)(src+4);int kb=kg*8;
          At[(kb+0)*ATS+rl]=v0.x;At[(kb+1)*ATS+rl]=v0.y;At[(kb+2)*ATS+rl]=v0.z;At[(kb+3)*ATS+rl]=v0.w;
          At[(kb+4)*ATS+rl]=v1.x;At[(kb+5)*ATS+rl]=v1.y;At[(kb+6)*ATS+rl]=v1.z;At[(kb+7)*ATS+rl]=v1.w;}
        { int j=t>>1,h=t&1;const float*src=w1+(size_t)j*128+kc+h*16;
#pragma unroll
          for(int i=0;i<4;i++){float4 v=*(const float4*)(src+i*4);int kk=h*16+i*4;
              Bp[(kk+0)*128+j]=v.x;Bp[(kk+1)*128+j]=v.y;Bp[(kk+2)*128+j]=v.z;Bp[(kk+3)*128+j]=v.w;}}
        __syncthreads();
        const float*Ab=At+rg*8;const float*Bb=Bp+cg*4;
#pragma unroll 8
        for(int k=0;k<32;k++){
            ulonglong2 A0=*(const ulonglong2*)(Ab+k*ATS);
            ulonglong2 A1=*(const ulonglong2*)(Ab+k*ATS+4);
            float4 b=*(const float4*)(Bb+k*128);
            ull B0=pack2(b.x),B1=pack2(b.y),B2=pack2(b.z),B3=pack2(b.w);
            fma2(acc[0][0],A0.x,B0);fma2(acc[0][1],A0.x,B1);fma2(acc[0][2],A0.x,B2);fma2(acc[0][3],A0.x,B3);
            fma2(acc[1][0],A0.y,B0);fma2(acc[1][1],A0.y,B1);fma2(acc[1][2],A0.y,B2);fma2(acc[1][3],A0.y,B3);
            fma2(acc[2][0],A1.x,B0);fma2(acc[2][1],A1.x,B1);fma2(acc[2][2],A1.x,B2);fma2(acc[2][3],A1.x,B3);
            fma2(acc[3][0],A1.y,B0);fma2(acc[3][1],A1.y,B1);fma2(acc[3][2],A1.y,B2);fma2(acc[3][3],A1.y,B3);
        }
        __syncthreads();
    }
#pragma unroll
    for(int c=0;c<4;c++){
        int j=cg*4+c;float bv=b1[j];
#pragma unroll
        for(int p=0;p<4;p++){
            int r=rg*8+2*p;
            Mt[j*ATS+r]  =lrelu(lo32(acc[p][c])+bv);
            Mt[j*ATS+r+1]=lrelu(hi32(acc[p][c])+bv);
        }
    }
    __syncthreads();
#pragma unroll
    for(int p=0;p<4;p++)
#pragma unroll
        for(int c=0;c<4;c++)acc[p][c]=0ull;
    for(int kc=0;kc<128;kc+=32){
        { int j=t>>1,h=t&1;const float*src=w2+(size_t)j*128+kc+h*16;
#pragma unroll
          for(int i=0;i<4;i++){float4 v=*(const float4*)(src+i*4);int kk=h*16+i*4;
              Bp[(kk+0)*128+j]=v.x;Bp[(kk+1)*128+j]=v.y;Bp[(kk+2)*128+j]=v.z;Bp[(kk+3)*128+j]=v.w;}}
        __syncthreads();
        const float*Ab=Mt+kc*ATS+rg*8;const float*Bb=Bp+cg*4;
#pragma unroll 8
        for(int k=0;k<32;k++){
            ulonglong2 A0=*(const ulonglong2*)(Ab+k*ATS);
            ulonglong2 A1=*(const ulonglong2*)(Ab+k*ATS+4);
            float4 b=*(const float4*)(Bb+k*128);
            ull B0=pack2(b.x),B1=pack2(b.y),B2=pack2(b.z),B3=pack2(b.w);
            fma2(acc[0][0],A0.x,B0);fma2(acc[0][1],A0.x,B1);fma2(acc[0][2],A0.x,B2);fma2(acc[0][3],A0.x,B3);
            fma2(acc[1][0],A0.y,B0);fma2(acc[1][1],A0.y,B1);fma2(acc[1][2],A0.y,B2);fma2(acc[1][3],A0.y,B3);
            fma2(acc[2][0],A1.x,B0);fma2(acc[2][1],A1.x,B1);fma2(acc[2][2],A1.x,B2);fma2(acc[2][3],A1.x,B3);
            fma2(acc[3][0],A1.y,B0);fma2(acc[3][1],A1.y,B1);fma2(acc[3][2],A1.y,B2);fma2(acc[3][3],A1.y,B3);
        }
        __syncthreads();
    }
#pragma unroll
    for(int c=0;c<4;c++){
        int j=cg*4+c;float bv=b2[j];
#pragma unroll
        for(int p=0;p<4;p++){
            int r=row0+rg*8+2*p;
            d_h[(size_t)r*128+j]=lo32(acc[p][c])+bv;
            d_h[(size_t)(r+1)*128+j]=hi32(acc[p][c])+bv;
        }
    }
}

// ---------------- generic fp32 GEMM (heads) ----------------
__global__ void __launch_bounds__(256)
k_gemm(const float* __restrict__ A,const float* __restrict__ W,
       const float* __restrict__ bias,const float* __restrict__ add,int ldadd,
       float* __restrict__ C,int ldc,int N,int ldw,int transW,int act){
    __shared__ float At[32*ATS];
    __shared__ float Bp[32*128];
    int t=threadIdx.x,rg=t>>5,cg=t&31;
    int row0=blockIdx.x*64,jt=blockIdx.y*128;
    ull acc[4][4];
#pragma unroll
    for(int p=0;p<4;p++)
#pragma unroll
        for(int c=0;c<4;c++)acc[p][c]=0ull;
    for(int kc=0;kc<128;kc+=32){
        { int rl=t&63,kg=t>>6;const float*src=A+(size_t)(row0+rl)*128+kc+kg*8;
          float4 v0=*(const float4*)src,v1=*(const float4*)(src+4);int kb=kg*8;
          At[(kb+0)*ATS+rl]=v0.x;At[(kb+1)*ATS+rl]=v0.y;At[(kb+2)*ATS+rl]=v0.z;At[(kb+3)*ATS+rl]=v0.w;
          At[(kb+4)*ATS+rl]=v1.x;At[(kb+5)*ATS+rl]=v1.y;At[(kb+6)*ATS+rl]=v1.z;At[(kb+7)*ATS+rl]=v1.w;}
        if(transW){
            int j=t>>1,h=t&1;
            if(jt+j<N){const float*src=W+(size_t)(jt+j)*ldw+kc+h*16;
#pragma unroll
                for(int i=0;i<4;i++){float4 v=*(const float4*)(src+i*4);int kk=h*16+i*4;
                    Bp[(kk+0)*128+j]=v.x;Bp[(kk+1)*128+j]=v.y;Bp[(kk+2)*128+j]=v.z;Bp[(kk+3)*128+j]=v.w;}
            }else{
#pragma unroll
                for(int i=0;i<16;i++)Bp[(h*16+i)*128+j]=0.f;}
        }else{
#pragma unroll
            for(int i=0;i<4;i++){int g=i*1024+t*4;*(float4*)(Bp+g)=*(const float4*)(W+kc*128+g);}
        }
        __syncthreads();
        const float*Ab=At+rg*8;const float*Bb=Bp+cg*4;
#pragma unroll 8
        for(int k=0;k<32;k++){
            ulonglong2 A0=*(const ulonglong2*)(Ab+k*ATS);
            ulonglong2 A1=*(const ulonglong2*)(Ab+k*ATS+4);
            float4 b=*(const float4*)(Bb+k*128);
            ull B0=pack2(b.x),B1=pack2(b.y),B2=pack2(b.z),B3=pack2(b.w);
            fma2(acc[0][0],A0.x,B0);fma2(acc[0][1],A0.x,B1);fma2(acc[0][2],A0.x,B2);fma2(acc[0][3],A0.x,B3);
            fma2(acc[1][0],A0.y,B0);fma2(acc[1][1],A0.y,B1);fma2(acc[1][2],A0.y,B2);fma2(acc[1][3],A0.y,B3);
            fma2(acc[2][0],A1.x,B0);fma2(acc[2][1],A1.x,B1);fma2(acc[2][2],A1.x,B2);fma2(acc[2][3],A1.x,B3);
            fma2(acc[3][0],A1.y,B0);fma2(acc[3][1],A1.y,B1);fma2(acc[3][2],A1.y,B2);fma2(acc[3][3],A1.y,B3);
        }
        __syncthreads();
    }
#pragma unroll
    for(int c=0;c<4;c++){
        int j=jt+cg*4+c;if(j>=N)continue;
        float bv=bias?bias[j]:0.f;
#pragma unroll
        for(int p=0;p<4;p++){
            int r=row0+rg*8+2*p;
            float v0=lo32(acc[p][c])+bv,v1=hi32(acc[p][c])+bv;
            if(add){v0+=add[(size_t)r*ldadd+j];v1+=add[(size_t)(r+1)*ldadd+j];}
            if(act){v0=lrelu(v0);v1=lrelu(v1);}
            C[(size_t)r*ldc+j]=v0;C[(size_t)(r+1)*ldc+j]=v1;
        }
    }
}

// ---------------- mma.sync fused conv step: 512 thr, n32/warp, m via LDSM --
#define SB0H 0
#define SB0L 34816
#define SB1H 69632
#define SB1L 104448
#define SMH  139264
#define SML  156672
#define SPG  174080
#define SBI  206848
#define SMT  210432
#define STRB 272
#define NTH  512

__device__ __forceinline__ void stageT(uint32_t sH,uint32_t sL,int tile,int tid){
    const char* gh=(const char*)(d_bwh+tile*16384);
    const char* gl=(const char*)(d_bwl+tile*16384);
#pragma unroll
    for(int q=0;q<4;q++){
        int i=tid+q*NTH, n=i>>4, c=i&15;
        CP16(sH+n*STRB+c*16, gh+n*256+c*16);
        CP16(sL+n*STRB+c*16, gl+n*256+c*16);
    }
    CPCOMMIT();
}

// acc += (A regs) @ B(hi/lo)   — A = h fragments in registers
__device__ __forceinline__ void gemm_h(float acc[4][4],const uint32_t aH[32],const uint32_t aL[32],
                                       uint32_t bh,uint32_t bl,int bt){
#pragma unroll
    for(int kc=0;kc<8;kc++){
#pragma unroll
        for(int jj=0;jj<2;jj++){
            uint32_t h0,h1,h2,h3,l0,l1,l2,l3;
            uint32_t off=jj*4352+kc*32+bt;
            LDSM4(h0,h1,h2,h3,bh+off);
            LDSM4(l0,l1,l2,l3,bl+off);
            MMA(acc[2*jj],  aH+kc*4,h0,h1);
            MMA(acc[2*jj+1],aH+kc*4,h2,h3);
            MMA(acc[2*jj],  aL+kc*4,h0,h1);
            MMA(acc[2*jj+1],aL+kc*4,h2,h3);
            MMA(acc[2*jj],  aH+kc*4,l0,l1);
            MMA(acc[2*jj+1],aH+kc*4,l2,l3);
        }
    }
}
// acc += (A from smem m-tiles via ldmatrix) @ B(hi/lo)
__device__ __forceinline__ void gemm_m(float acc[4][4],uint32_t atH,uint32_t atL,
                                       uint32_t bh,uint32_t bl,int bt){
#pragma unroll
    for(int kc=0;kc<8;kc++){
        uint32_t aH[4],aL[4];
        LDSM4(aH[0],aH[1],aH[2],aH[3],atH+kc*32);
        LDSM4(aL[0],aL[1],aL[2],aL[3],atL+kc*32);
#pragma unroll
        for(int jj=0;jj<2;jj++){
            uint32_t h0,h1,h2,h3,l0,l1,l2,l3;
            uint32_t off=jj*4352+kc*32+bt;
            LDSM4(h0,h1,h2,h3,bh+off);
            LDSM4(l0,l1,l2,l3,bl+off);
            MMA(acc[2*jj],  aH,h0,h1);
            MMA(acc[2*jj+1],aH,h2,h3);
            MMA(acc[2*jj],  aL,h0,h1);
            MMA(acc[2*jj+1],aL,h2,h3);
            MMA(acc[2*jj],  aH,l0,l1);
            MMA(acc[2*jj+1],aH,l2,l3);
        }
    }
}
#define ZACC4(acc) {_Pragma("unroll") for(int _n=0;_n<4;_n++){_Pragma("unroll") for(int _d=0;_d<4;_d++)(acc)[_n][_d]=0.f;}}

__global__ void __launch_bounds__(NTH,1)
k_step_mma(const float* __restrict__ hin, float* __restrict__ hout,
           const int* __restrict__ ei, const int* __restrict__ ea,
           const float* __restrict__ embBond,
           const float* __restrict__ cbias,
           const float* __restrict__ bih, const float* __restrict__ bhh){
    extern __shared__ char smem[];
    uint32_t sb=s2u(smem);
    float* Pg=(float*)(smem+SPG);
    float* sbias=(float*)(smem+SBI);
    int tid=threadIdx.x, w=tid>>5, lane=tid&31;
    int row0=blockIdx.x*64;
    int wr=w&3, cg=w>>2, nt0=cg*4;
    int bt=nt0*2176+((lane>>3)>>1)*2176+(lane&7)*STRB+((lane>>3)&1)*16;
    int rl=16*wr+(lane>>2);
    uint32_t atoff=(uint32_t)(16*wr+((lane>>3)&1)*8+(lane&7))*STRB+(uint32_t)(lane>>4)*16;
    uint32_t atH=sb+SMH+atoff, atL=sb+SML+atoff;

    for(int i=tid;i<384;i+=NTH){sbias[i]=bih[i];sbias[384+i]=bhh[i];}
    if(tid<128)sbias[768+tid]=cbias[tid];

    stageT(sb+SB0H,sb+SB0L,0,tid);   // rootT

    // ---- h A-fragments (hi/lo) from global ----
    uint32_t hAh[32],hAl[32];
    {
        int ra=row0+rl;
#pragma unroll
        for(int kc=0;kc<8;kc++)
#pragma unroll
        for(int j=0;j<4;j++){
            int row=ra+(j&1)*8;
            int col=kc*16+(j>>1)*8+(lane&3)*2;
            float2 v=*(const float2*)(hin+(size_t)row*128+col);
            uint32_t ph=pkbf(v.x,v.y);
            hAh[kc*4+j]=ph;
            hAl[kc*4+j]=pkbf(v.x-upbf(ph,0),v.y-upbf(ph,1));
        }
    }

    // ---- edge aggregation -> d_agg (4 nodes/warp) ----
#pragma unroll 1
    for(int q=0;q<4;q++){
        int n=row0+4*w+q;
        int s0=d_off[n],s1=d_off[n+1];
        float4 acc4=make_float4(0.f,0.f,0.f,0.f);
        for(int i=s0;i<s1;i++){
            int e=d_csr[i];
            int s=ei[e],a0=ea[2*e],a1=ea[2*e+1];
            float4 hv=*(const float4*)(hin+(size_t)s*D+lane*4);
            float4 b0=*(const float4*)(embBond+(size_t)a0*D+lane*4);
            float p=hv.x*b0.x+hv.y*b0.y+hv.z*b0.z+hv.w*b0.w;
#pragma unroll
            for(int o=16;o>0;o>>=1)p+=__shfl_xor_sync(~0u,p,o);
            float4 b1=*(const float4*)(embBond+(size_t)a1*D+lane*4);
            acc4.x+=p*b1.x;acc4.y+=p*b1.y;acc4.z+=p*b1.z;acc4.w+=p*b1.w;
        }
        float iv=d_invdeg[n];
        acc4.x*=iv;acc4.y*=iv;acc4.z*=iv;acc4.w*=iv;
        *(float4*)(d_agg+(size_t)n*D+lane*4)=acc4;
    }

    float acc[4][4];
    // ---- P1: conv = lrelu(h@root + agg + cbias) -> m tiles (bf16 hi/lo) ----
    CPWAIT(); __syncthreads();
    stageT(sb+SB1H,sb+SB1L,1,tid);               // wih_r
    ZACC4(acc);
    gemm_h(acc,hAh,hAl,sb+SB0H,sb+SB0L,bt);
    {
#pragma unroll
        for(int n=0;n<4;n++){
            int colg=(nt0+n)*8+(lane&3)*2;
            float2 a0=*(const float2*)(d_agg+(size_t)(row0+rl)*D+colg);
            float2 a1=*(const float2*)(d_agg+(size_t)(row0+rl+8)*D+colg);
            float b0v=sbias[768+colg],b1v=sbias[768+colg+1];
            float m00=lrelu(acc[n][0]+a0.x+b0v), m01=lrelu(acc[n][1]+a0.y+b1v);
            float m10=lrelu(acc[n][2]+a1.x+b0v), m11=lrelu(acc[n][3]+a1.y+b1v);
            uint32_t p0=pkbf(m00,m01), p1=pkbf(m10,m11);
            uint32_t q0=pkbf(m00-upbf(p0,0),m01-upbf(p0,1));
            uint32_t q1=pkbf(m10-upbf(p1,0),m11-upbf(p1,1));
            *(uint32_t*)(smem+SMH+rl*STRB+colg*2)=p0;
            *(uint32_t*)(smem+SMH+(rl+8)*STRB+colg*2)=p1;
            *(uint32_t*)(smem+SML+rl*STRB+colg*2)=q0;
            *(uint32_t*)(smem+SML+(rl+8)*STRB+colg*2)=q1;
        }
    }
    // ---- P2: m@wih_r ----
    CPWAIT(); __syncthreads();
    stageT(sb+SB0H,sb+SB0L,4,tid);               // whh_r
    ZACC4(acc);
    gemm_m(acc,atH,atL,sb+SB1H,sb+SB1L,bt);
    // ---- P3: + h@whh_r -> r gate ----
    CPWAIT(); __syncthreads();
    stageT(sb+SB1H,sb+SB1L,6,tid);               // whh_n
    gemm_h(acc,hAh,hAl,sb+SB0H,sb+SB0L,bt);
#pragma unroll
    for(int n=0;n<4;n++)
#pragma unroll
    for(int dg=0;dg<4;dg++){
        int col=(nt0+n)*8+(lane&3)*2+(dg&1);
        Pg[(n*4+dg)*NTH+tid]=sigm(acc[n][dg]+sbias[col]+sbias[384+col]);
    }
    // ---- P4: h@whh_n -> P = r*(hn+bhh_n) ----
    CPWAIT(); __syncthreads();
    stageT(sb+SB0H,sb+SB0L,3,tid);               // wih_n
    ZACC4(acc);
    gemm_h(acc,hAh,hAl,sb+SB1H,sb+SB1L,bt);
#pragma unroll
    for(int n=0;n<4;n++)
#pragma unroll
    for(int dg=0;dg<4;dg++){
        int col=(nt0+n)*8+(lane&3)*2+(dg&1);
        int i=(n*4+dg)*NTH+tid;
        Pg[i]=Pg[i]*(acc[n][dg]+sbias[640+col]);
    }
    // ---- P5: m@wih_n -> P = tanh(in+bih_n+P) ----
    CPWAIT(); __syncthreads();
    stageT(sb+SB1H,sb+SB1L,2,tid);               // wih_z
    ZACC4(acc);
    gemm_m(acc,atH,atL,sb+SB0H,sb+SB0L,bt);
#pragma unroll
    for(int n=0;n<4;n++)
#pragma unroll
    for(int dg=0;dg<4;dg++){
        int col=(nt0+n)*8+(lane&3)*2+(dg&1);
        int i=(n*4+dg)*NTH+tid;
        Pg[i]=tanhfast(acc[n][dg]+sbias[256+col]+Pg[i]);
    }
    // ---- P6: m@wih_z ----
    CPWAIT(); __syncthreads();
    stageT(sb+SB0H,sb+SB0L,5,tid);               // whh_z
    ZACC4(acc);
    gemm_m(acc,atH,atL,sb+SB1H,sb+SB1L,bt);
    // ---- P7: + h@whh_z -> z gate + update ----
    CPWAIT(); __syncthreads();
    gemm_h(acc,hAh,hAl,sb+SB0H,sb+SB0L,bt);
    {
        int rbase=row0+rl;
#pragma unroll
        for(int n=0;n<4;n++){
            int nt=nt0+n, kc=nt>>1;
            float o[4];
#pragma unroll
            for(int dg=0;dg<4;dg++){
                int col=nt*8+(lane&3)*2+(dg&1);
                int j=((nt&1)<<1)|(dg>>1);
                float hv=upbf(hAh[kc*4+j],dg&1)+upbf(hAl[kc*4+j],dg&1);
                float z=sigm(acc[n][dg]+sbias[128+col]+sbias[512+col]);
                float nv=Pg[(n*4+dg)*NTH+tid];
                o[dg]=(1.f-z)*nv+z*hv;
            }
            int c0=nt*8+(lane&3)*2;
            *(float2*)(hout+(size_t)rbase*D+c0)    =make_float2(o[0],o[1]);
            *(float2*)(hout+(size_t)(rbase+8)*D+c0)=make_float2(o[2],o[3]);
        }
    }
}

// ---------------- row gather ----------------
__global__ void k_gather(float* __restrict__ dst,const float* __restrict__ src,
                         const int* __restrict__ idx,int n){
    int t=blockIdx.x*blockDim.x+threadIdx.x;
    int row=t>>5,l=t&31;if(row>=n)return;
    *(float4*)(dst+(size_t)row*128+l*4)=*(const float4*)(src+(size_t)idx[row]*128+l*4);
}

// ---------------- global mean pool ----------------
__global__ void k_pool(const int* __restrict__ nb){
    int g=blockIdx.x,c=threadIdx.x;
    int lo=0,hi=NN;while(lo<hi){int m=(lo+hi)>>1;if(nb[m]<g)lo=m+1;else hi=m;}
    int s=lo;lo=0;hi=NN;while(lo<hi){int m=(lo+hi)>>1;if(nb[m]<=g)lo=m+1;else hi=m;}
    int e=lo;float sum=0.f;
    for(int r=s;r<e;r++)sum+=d_h[(size_t)r*128+c];
    d_gm[g*128+c]=sum/fmaxf((float)(e-s),1.f);
}

// ---------------- stop head ----------------
__global__ void k_stop(const float* __restrict__ w2,const float* __restrict__ b2,
                       float* __restrict__ out){
    int w=(blockIdx.x*blockDim.x+threadIdx.x)>>5,l=threadIdx.x&31;
    if(w>=NG)return;
    float4 g=*(const float4*)(d_g1+(size_t)w*128+l*4);
    float4 ww=*(const float4*)(w2+l*4);
    float p=g.x*ww.x+g.y*ww.y+g.z*ww.z+g.w*ww.w;
#pragma unroll
    for(int o=16;o>0;o>>=1)p+=__shfl_xor_sync(~0u,p,o);
    if(l==0)out[NS*OPS+w]=p+b2[0];
}

// ---------------- launch ----------------
extern "C" void kernel_launch(void* const* d_in,const int* in_sizes,int n_in,
                              void* d_out,int out_size){
    const int* x   =(const int*)d_in[0];
    const int* st  =(const int*)d_in[1];
    const int* ea  =(const int*)d_in[2];
    const int* ei  =(const int*)d_in[3];
    const int* sni =(const int*)d_in[4];
    const int* nb  =(const int*)d_in[5];
    const float* embB=(const float*)d_in[6];
    const float* embS=(const float*)d_in[7];
    const float* embBond=(const float*)d_in[8];
    const float* b2e_w1=(const float*)d_in[9],  *b2e_b1=(const float*)d_in[10];
    const float* b2e_w2=(const float*)d_in[11], *b2e_b2=(const float*)d_in[12];
    const float* conv_root=(const float*)d_in[13], *conv_bias=(const float*)d_in[14];
    const float* w_ih=(const float*)d_in[15], *w_hh=(const float*)d_in[16];
    const float* b_ih=(const float*)d_in[17], *b_hh=(const float*)d_in[18];
    const float* s2p_w1=(const float*)d_in[19], *s2p_b1=(const float*)d_in[20];
    const float* s2p_w2=(const float*)d_in[21], *s2p_b2=(const float*)d_in[22];
    const float* s2p_w3=(const float*)d_in[23], *s2p_b3=(const float*)d_in[24];
    const float* g2p_w1=(const float*)d_in[25], *g2p_b1=(const float*)d_in[26];
    const float* g2p_w2=(const float*)d_in[27], *g2p_b2=(const float*)d_in[28];
    float* out=(float*)d_out;

    void* p;
    cudaGetSymbolAddress(&p,d_h);   float* ph =(float*)p;
    cudaGetSymbolAddress(&p,d_h2);  float* ph2=(float*)p;
    cudaGetSymbolAddress(&p,d_m);   float* pm =(float*)p;
    cudaGetSymbolAddress(&p,d_sg);  float* psg=(float*)p;
    cudaGetSymbolAddress(&p,d_se);  float* pse=(float*)p;
    cudaGetSymbolAddress(&p,d_s1);  float* ps1=(float*)p;
    cudaGetSymbolAddress(&p,d_gm);  float* pgm=(float*)p;
    cudaGetSymbolAddress(&p,d_g1);  float* pg1=(float*)p;

    static int attr_set=0;
    if(!attr_set){
        cudaFuncSetAttribute(k_step_mma,cudaFuncAttributeMaxDynamicSharedMemorySize,SMT);
        attr_set=1;
    }

    // 3 prologue launches -> step #1 stays at ncu slot 6
    k_prep0<<<448,256>>>(conv_root,w_ih,w_hh);
    k_csr  <<<CSRB,1024>>>(ei);
    k_b2e  <<<NN/64,256>>>(x,embB,b2e_w1,b2e_b1,b2e_w2,b2e_b2);

    for(int s=0;s<NSTEPS;s++){
        const float* hi=(s&1)?ph2:ph;
        float* ho=(s&1)?ph:ph2;
        k_step_mma<<<NN/64,NTH,SMT>>>(hi,ho,ei,ea,embBond,conv_bias,b_ih,b_hh);
    }

    // stem head
    k_gather<<<NS*32/256,256>>>(psg,ph,sni,NS);
    k_gather<<<NS*32/256,256>>>(pse,embS,st,NS);
    k_gemm<<<dim3(NS/64,1),256>>>(psg,s2p_w1,    nullptr,nullptr,0,ps1,128,128,256,1,0);
    k_gemm<<<dim3(NS/64,1),256>>>(pse,s2p_w1+128,s2p_b1, ps1,128,  ps1,128,128,256,1,1);
    k_gemm<<<dim3(NS/64,1),256>>>(ps1,s2p_w2,s2p_b2,nullptr,0,pm, 128,128,128,1,1);
    k_gemm<<<dim3(NS/64,1),256>>>(pm, s2p_w3,s2p_b3,nullptr,0,out,105,105,128,1,0);

    // stop head
    k_pool<<<NG,128>>>(nb);
    k_gemm<<<dim3(NG/64,1),256>>>(pgm,g2p_w1,g2p_b1,nullptr,0,pg1,128,128,128,1,1);
    k_stop<<<NG/8,256>>>(g2p_w2,g2p_b2,out);
}

// round 14
// speedup vs baseline: 1.1535x; 1.0324x over previous
#include <cuda_runtime.h>
#include <cuda_bf16.h>
#include <math.h>
#include <stdint.h>

#define D 128
#define NN 8192
#define NE 16384
#define NS 4096
#define NG 256
#define OPS 105
#define NSTEPS 12
#define ATS 68

typedef unsigned long long ull;

// ---------------- scratch ----------------
__device__ float d_h[NN*D], d_h2[NN*D], d_agg[NN*D], d_m[NN*D];
__device__ float d_sg[NS*D], d_se[NS*D], d_s1[NS*D];
__device__ float d_gm[NG*D], d_g1[NG*D];
__device__ int   d_deg[NN], d_off[NN+1], d_cur[NN], d_csr[NE];
__device__ float d_invdeg[NN];
__device__ __nv_bfloat16 d_bwh[7*16384], d_bwl[7*16384];
__device__ unsigned g_cnt=0, g_epoch=0;

// ---------------- helpers ----------------
__device__ __forceinline__ ull pack2(float x){unsigned u=__float_as_uint(x);ull r;asm("mov.b64 %0,{%1,%1};":"=l"(r):"r"(u));return r;}
__device__ __forceinline__ void fma2(ull&a,ull x,ull y){asm("fma.rn.f32x2 %0,%1,%2,%0;":"+l"(a):"l"(x),"l"(y));}
__device__ __forceinline__ float lo32(ull v){return __uint_as_float((unsigned)v);}
__device__ __forceinline__ float hi32(ull v){return __uint_as_float((unsigned)(v>>32));}
__device__ __forceinline__ float lrelu(float v){return v>0.f?v:0.01f*v;}
__device__ __forceinline__ float sigm(float x){float e=__expf(-x);return __fdividef(1.f,1.f+e);}
__device__ __forceinline__ float tanhfast(float x){
    x=fminf(fmaxf(x,-9.f),9.f);
    float t=__expf(2.f*x);
    return __fdividef(t-1.f,t+1.f);
}
__device__ __forceinline__ uint32_t s2u(const void* p){
    uint32_t a; asm("{ .reg .u64 t; cvta.to.shared.u64 t, %1; cvt.u32.u64 %0, t; }":"=r"(a):"l"(p)); return a;
}
__device__ __forceinline__ uint32_t pkbf(float a,float b){
    uint32_t r; asm("cvt.rn.bf16x2.f32 %0, %1, %2;":"=r"(r):"f"(b),"f"(a)); return r;
}
__device__ __forceinline__ float upbf(uint32_t u,int slot){
    return __uint_as_float((slot?(u>>16):(u&0xffffu))<<16);
}

#define CP16(s,g)  asm volatile("cp.async.cg.shared.global [%0], [%1], 16;"::"r"(s),"l"(g):"memory")
#define CPCOMMIT() asm volatile("cp.async.commit_group;":::"memory")
#define CPWAIT()   asm volatile("cp.async.wait_group 0;":::"memory")
#define LDSM4(r0,r1,r2,r3,a) asm volatile( \
    "ldmatrix.sync.aligned.m8n8.x4.shared.b16 {%0,%1,%2,%3},[%4];" \
    :"=r"(r0),"=r"(r1),"=r"(r2),"=r"(r3):"r"(a))
#define MMA(dd,aa,b0,b1) asm volatile( \
    "mma.sync.aligned.m16n8k16.row.col.f32.bf16.bf16.f32 {%0,%1,%2,%3},{%4,%5,%6,%7},{%8,%9},{%0,%1,%2,%3};" \
    : "+f"((dd)[0]),"+f"((dd)[1]),"+f"((dd)[2]),"+f"((dd)[3]) \
    : "r"((aa)[0]),"r"((aa)[1]),"r"((aa)[2]),"r"((aa)[3]),"r"(b0),"r"(b1))

// ---------------- prologue #1: weight prep + deg zero ----------------
__global__ void k_prep0(const float* __restrict__ root,const float* __restrict__ wih,
                        const float* __restrict__ whh){
    int t=blockIdx.x*blockDim.x+threadIdx.x;    // 448 x 256
    if(t<NN)d_deg[t]=0;
    if(t<7*16384){
        int tt=t>>14, rem=t&16383, n=rem>>7, k=rem&127;
        float v;
        if(tt==0)      v=root[k*128+n];
        else if(tt<4)  v=wih[((tt-1)*128+n)*128+k];
        else           v=whh[((tt-4)*128+n)*128+k];
        __nv_bfloat16 hi=__float2bfloat16(v);
        __nv_bfloat16 lo=__float2bfloat16(v-__bfloat162float(hi));
        d_bwh[t]=hi; d_bwl[t]=lo;
    }
}

// ---------------- prologue #2: fused CSR ----------------
#define CSRB 32
__device__ __forceinline__ void gridbar32(unsigned tgt){
    __syncthreads();
    if(threadIdx.x==0){
        __threadfence();
        unsigned old=atomicAdd(&g_cnt,1u);
        if(old==CSRB-1u){ g_cnt=0u; __threadfence(); atomicAdd(&g_epoch,1u); }
        else { while((int)(*(volatile unsigned*)&g_epoch - tgt) < 0){} }
        __threadfence();
    }
    __syncthreads();
}
__global__ void __launch_bounds__(1024)
k_csr(const int* __restrict__ ei){
    __shared__ unsigned s_ep0;
    if(threadIdx.x==0)s_ep0=*(volatile unsigned*)&g_epoch;
    __syncthreads();
    unsigned ep0=s_ep0;
    int gt=blockIdx.x*1024+threadIdx.x;
    if(gt<NE)atomicAdd(&d_deg[ei[NE+gt]],1);
    gridbar32(ep0+1u);
    if(blockIdx.x==0){
        __shared__ int ws[32];
        int t=threadIdx.x,base=t*8,v[8],pre[8],s=0;
#pragma unroll
        for(int i=0;i<8;i++){v[i]=d_deg[base+i];pre[i]=s;s+=v[i];}
        int lane=t&31,wid=t>>5,xx=s;
#pragma unroll
        for(int o=1;o<32;o<<=1){int y=__shfl_up_sync(~0u,xx,o);if(lane>=o)xx+=y;}
        if(lane==31)ws[wid]=xx;
        __syncthreads();
        if(wid==0){int w0=ws[lane],x2=w0;
#pragma unroll
            for(int o=1;o<32;o<<=1){int y=__shfl_up_sync(~0u,x2,o);if(lane>=o)x2+=y;}
            ws[lane]=x2-w0;}
        __syncthreads();
        int obase=ws[wid]+(xx-s);
#pragma unroll
        for(int i=0;i<8;i++){int o=obase+pre[i];d_off[base+i]=o;d_cur[base+i]=o;
            d_invdeg[base+i]=v[i]>0?1.0f/(float)v[i]:0.0f;}
        if(t==1023)d_off[NN]=obase+s;
    }
    gridbar32(ep0+2u);
    if(gt<NE){int p=atomicAdd(&d_cur[ei[NE+gt]],1);d_csr[p]=gt;}
    gridbar32(ep0+3u);
    if(gt<NN){
        int a=d_off[gt],b=d_off[gt+1];
        for(int i=a+1;i<b;i++){int key=d_csr[i],j=i-1;
            while(j>=a&&d_csr[j]>key){d_csr[j+1]=d_csr[j];j--;}d_csr[j+1]=key;}
    }
}

// ---------------- prologue #3: fused block2emb (both layers) ---------------
__global__ void __launch_bounds__(256)
k_b2e(const int* __restrict__ x,const float* __restrict__ embB,
      const float* __restrict__ w1,const float* __restrict__ b1,
      const float* __restrict__ w2,const float* __restrict__ b2){
    __shared__ float At[32*ATS];
    __shared__ float Mt[128*ATS];
    __shared__ float Bp[32*128];
    int t=threadIdx.x,rg=t>>5,cg=t&31;
    int row0=blockIdx.x*64;
    int xi=x[row0+(t&63)];
    ull acc[4][4];
#pragma unroll
    for(int p=0;p<4;p++)
#pragma unroll
        for(int c=0;c<4;c++)acc[p][c]=0ull;
    for(int kc=0;kc<128;kc+=32){
        { int rl=t&63,kg=t>>6;const float*src=embB+(size_t)xi*128+kc+kg*8;
          float4 v0=*(const float4*)src,v1=*(const float4*)(src+4);int kb=kg*8;
          At[(kb+0)*ATS+rl]=v0.x;At[(kb+1)*ATS+rl]=v0.y;At[(kb+2)*ATS+rl]=v0.z;At[(kb+3)*ATS+rl]=v0.w;
          At[(kb+4)*ATS+rl]=v1.x;At[(kb+5)*ATS+rl]=v1.y;At[(kb+6)*ATS+rl]=v1.z;At[(kb+7)*ATS+rl]=v1.w;}
        { int j=t>>1,h=t&1;const float*src=w1+(size_t)j*128+kc+h*16;
#pragma unroll
          for(int i=0;i<4;i++){float4 v=*(const float4*)(src+i*4);int kk=h*16+i*4;
              Bp[(kk+0)*128+j]=v.x;Bp[(kk+1)*128+j]=v.y;Bp[(kk+2)*128+j]=v.z;Bp[(kk+3)*128+j]=v.w;}}
        __syncthreads();
        const float*Ab=At+rg*8;const float*Bb=Bp+cg*4;
#pragma unroll 8
        for(int k=0;k<32;k++){
            ulonglong2 A0=*(const ulonglong2*)(Ab+k*ATS);
            ulonglong2 A1=*(const ulonglong2*)(Ab+k*ATS+4);
            float4 b=*(const float4*)(Bb+k*128);
            ull B0=pack2(b.x),B1=pack2(b.y),B2=pack2(b.z),B3=pack2(b.w);
            fma2(acc[0][0],A0.x,B0);fma2(acc[0][1],A0.x,B1);fma2(acc[0][2],A0.x,B2);fma2(acc[0][3],A0.x,B3);
            fma2(acc[1][0],A0.y,B0);fma2(acc[1][1],A0.y,B1);fma2(acc[1][2],A0.y,B2);fma2(acc[1][3],A0.y,B3);
            fma2(acc[2][0],A1.x,B0);fma2(acc[2][1],A1.x,B1);fma2(acc[2][2],A1.x,B2);fma2(acc[2][3],A1.x,B3);
            fma2(acc[3][0],A1.y,B0);fma2(acc[3][1],A1.y,B1);fma2(acc[3][2],A1.y,B2);fma2(acc[3][3],A1.y,B3);
        }
        __syncthreads();
    }
#pragma unroll
    for(int c=0;c<4;c++){
        int j=cg*4+c;float bv=b1[j];
#pragma unroll
        for(int p=0;p<4;p++){
            int r=rg*8+2*p;
            Mt[j*ATS+r]  =lrelu(lo32(acc[p][c])+bv);
            Mt[j*ATS+r+1]=lrelu(hi32(acc[p][c])+bv);
        }
    }
    __syncthreads();
#pragma unroll
    for(int p=0;p<4;p++)
#pragma unroll
        for(int c=0;c<4;c++)acc[p][c]=0ull;
    for(int kc=0;kc<128;kc+=32){
        { int j=t>>1,h=t&1;const float*src=w2+(size_t)j*128+kc+h*16;
#pragma unroll
          for(int i=0;i<4;i++){float4 v=*(const float4*)(src+i*4);int kk=h*16+i*4;
              Bp[(kk+0)*128+j]=v.x;Bp[(kk+1)*128+j]=v.y;Bp[(kk+2)*128+j]=v.z;Bp[(kk+3)*128+j]=v.w;}}
        __syncthreads();
        const float*Ab=Mt+kc*ATS+rg*8;const float*Bb=Bp+cg*4;
#pragma unroll 8
        for(int k=0;k<32;k++){
            ulonglong2 A0=*(const ulonglong2*)(Ab+k*ATS);
            ulonglong2 A1=*(const ulonglong2*)(Ab+k*ATS+4);
            float4 b=*(const float4*)(Bb+k*128);
            ull B0=pack2(b.x),B1=pack2(b.y),B2=pack2(b.z),B3=pack2(b.w);
            fma2(acc[0][0],A0.x,B0);fma2(acc[0][1],A0.x,B1);fma2(acc[0][2],A0.x,B2);fma2(acc[0][3],A0.x,B3);
            fma2(acc[1][0],A0.y,B0);fma2(acc[1][1],A0.y,B1);fma2(acc[1][2],A0.y,B2);fma2(acc[1][3],A0.y,B3);
            fma2(acc[2][0],A1.x,B0);fma2(acc[2][1],A1.x,B1);fma2(acc[2][2],A1.x,B2);fma2(acc[2][3],A1.x,B3);
            fma2(acc[3][0],A1.y,B0);fma2(acc[3][1],A1.y,B1);fma2(acc[3][2],A1.y,B2);fma2(acc[3][3],A1.y,B3);
        }
        __syncthreads();
    }
#pragma unroll
    for(int c=0;c<4;c++){
        int j=cg*4+c;float bv=b2[j];
#pragma unroll
        for(int p=0;p<4;p++){
            int r=row0+rg*8+2*p;
            d_h[(size_t)r*128+j]=lo32(acc[p][c])+bv;
            d_h[(size_t)(r+1)*128+j]=hi32(acc[p][c])+bv;
        }
    }
}

// ---------------- generic fp32 GEMM (heads) ----------------
__global__ void __launch_bounds__(256)
k_gemm(const float* __restrict__ A,const float* __restrict__ W,
       const float* __restrict__ bias,const float* __restrict__ add,int ldadd,
       float* __restrict__ C,int ldc,int N,int ldw,int transW,int act){
    __shared__ float At[32*ATS];
    __shared__ float Bp[32*128];
    int t=threadIdx.x,rg=t>>5,cg=t&31;
    int row0=blockIdx.x*64,jt=blockIdx.y*128;
    ull acc[4][4];
#pragma unroll
    for(int p=0;p<4;p++)
#pragma unroll
        for(int c=0;c<4;c++)acc[p][c]=0ull;
    for(int kc=0;kc<128;kc+=32){
        { int rl=t&63,kg=t>>6;const float*src=A+(size_t)(row0+rl)*128+kc+kg*8;
          float4 v0=*(const float4*)src,v1=*(const float4*)(src+4);int kb=kg*8;
          At[(kb+0)*ATS+rl]=v0.x;At[(kb+1)*ATS+rl]=v0.y;At[(kb+2)*ATS+rl]=v0.z;At[(kb+3)*ATS+rl]=v0.w;
          At[(kb+4)*ATS+rl]=v1.x;At[(kb+5)*ATS+rl]=v1.y;At[(kb+6)*ATS+rl]=v1.z;At[(kb+7)*ATS+rl]=v1.w;}
        if(transW){
            int j=t>>1,h=t&1;
            if(jt+j<N){const float*src=W+(size_t)(jt+j)*ldw+kc+h*16;
#pragma unroll
                for(int i=0;i<4;i++){float4 v=*(const float4*)(src+i*4);int kk=h*16+i*4;
                    Bp[(kk+0)*128+j]=v.x;Bp[(kk+1)*128+j]=v.y;Bp[(kk+2)*128+j]=v.z;Bp[(kk+3)*128+j]=v.w;}
            }else{
#pragma unroll
                for(int i=0;i<16;i++)Bp[(h*16+i)*128+j]=0.f;}
        }else{
#pragma unroll
            for(int i=0;i<4;i++){int g=i*1024+t*4;*(float4*)(Bp+g)=*(const float4*)(W+kc*128+g);}
        }
        __syncthreads();
        const float*Ab=At+rg*8;const float*Bb=Bp+cg*4;
#pragma unroll 8
        for(int k=0;k<32;k++){
            ulonglong2 A0=*(const ulonglong2*)(Ab+k*ATS);
            ulonglong2 A1=*(const ulonglong2*)(Ab+k*ATS+4);
            float4 b=*(const float4*)(Bb+k*128);
            ull B0=pack2(b.x),B1=pack2(b.y),B2=pack2(b.z),B3=pack2(b.w);
            fma2(acc[0][0],A0.x,B0);fma2(acc[0][1],A0.x,B1);fma2(acc[0][2],A0.x,B2);fma2(acc[0][3],A0.x,B3);
            fma2(acc[1][0],A0.y,B0);fma2(acc[1][1],A0.y,B1);fma2(acc[1][2],A0.y,B2);fma2(acc[1][3],A0.y,B3);
            fma2(acc[2][0],A1.x,B0);fma2(acc[2][1],A1.x,B1);fma2(acc[2][2],A1.x,B2);fma2(acc[2][3],A1.x,B3);
            fma2(acc[3][0],A1.y,B0);fma2(acc[3][1],A1.y,B1);fma2(acc[3][2],A1.y,B2);fma2(acc[3][3],A1.y,B3);
        }
        __syncthreads();
    }
#pragma unroll
    for(int c=0;c<4;c++){
        int j=jt+cg*4+c;if(j>=N)continue;
        float bv=bias?bias[j]:0.f;
#pragma unroll
        for(int p=0;p<4;p++){
            int r=row0+rg*8+2*p;
            float v0=lo32(acc[p][c])+bv,v1=hi32(acc[p][c])+bv;
            if(add){v0+=add[(size_t)r*ldadd+j];v1+=add[(size_t)(r+1)*ldadd+j];}
            if(act){v0=lrelu(v0);v1=lrelu(v1);}
            C[(size_t)r*ldc+j]=v0;C[(size_t)(r+1)*ldc+j]=v1;
        }
    }
}

// ---------------- mma.sync fused conv step: all A operands via smem tiles --
#define SB0H 0
#define SB0L 34816
#define SB1H 69632
#define SB1L 104448
#define SHH  139264
#define SHL  156672
#define SMH  174080
#define SML  191488
#define SBI  208896
#define SMT  212480
#define STRB 272
#define NTH  512

__device__ __forceinline__ void stageT(uint32_t sH,uint32_t sL,int tile,int tid){
    const char* gh=(const char*)(d_bwh+tile*16384);
    const char* gl=(const char*)(d_bwl+tile*16384);
#pragma unroll
    for(int q=0;q<4;q++){
        int i=tid+q*NTH, n=i>>4, c=i&15;
        CP16(sH+n*STRB+c*16, gh+n*256+c*16);
        CP16(sL+n*STRB+c*16, gl+n*256+c*16);
    }
    CPCOMMIT();
}

// acc += (A from smem tile via ldmatrix) @ B(hi/lo)
__device__ __forceinline__ void gemm_s(float acc[4][4],uint32_t atH,uint32_t atL,
                                       uint32_t bh,uint32_t bl,int bt){
#pragma unroll
    for(int kc=0;kc<8;kc++){
        uint32_t aH[4],aL[4];
        LDSM4(aH[0],aH[1],aH[2],aH[3],atH+kc*32);
        LDSM4(aL[0],aL[1],aL[2],aL[3],atL+kc*32);
#pragma unroll
        for(int jj=0;jj<2;jj++){
            uint32_t h0,h1,h2,h3,l0,l1,l2,l3;
            uint32_t off=jj*4352+kc*32+bt;
            LDSM4(h0,h1,h2,h3,bh+off);
            LDSM4(l0,l1,l2,l3,bl+off);
            MMA(acc[2*jj],  aH,h0,h1);
            MMA(acc[2*jj+1],aH,h2,h3);
            MMA(acc[2*jj],  aL,h0,h1);
            MMA(acc[2*jj+1],aL,h2,h3);
            MMA(acc[2*jj],  aH,l0,l1);
            MMA(acc[2*jj+1],aH,l2,l3);
        }
    }
}
#define ZACC4(acc) {_Pragma("unroll") for(int _n=0;_n<4;_n++){_Pragma("unroll") for(int _d=0;_d<4;_d++)(acc)[_n][_d]=0.f;}}

__global__ void __launch_bounds__(NTH,1)
k_step_mma(const float* __restrict__ hin, float* __restrict__ hout,
           const int* __restrict__ ei, const int* __restrict__ ea,
           const float* __restrict__ embBond,
           const float* __restrict__ cbias,
           const float* __restrict__ bih, const float* __restrict__ bhh){
    extern __shared__ char smem[];
    uint32_t sb=s2u(smem);
    float* sbias=(float*)(smem+SBI);
    float* Pgg=d_agg+(size_t)blockIdx.x*8192;   // block-private gate scratch (agg dead after P1)
    int tid=threadIdx.x, w=tid>>5, lane=tid&31;
    int row0=blockIdx.x*64;
    int wr=w&3, cg=w>>2, nt0=cg*4;
    int bt=nt0*2176+((lane>>3)>>1)*2176+(lane&7)*STRB+((lane>>3)&1)*16;
    int rl=16*wr+(lane>>2);
    uint32_t atoff=(uint32_t)(16*wr+((lane>>3)&1)*8+(lane&7))*STRB+(uint32_t)(lane>>4)*16;
    uint32_t ahH=sb+SHH+atoff, ahL=sb+SHL+atoff;
    uint32_t amH=sb+SMH+atoff, amL=sb+SML+atoff;

    for(int i=tid;i<384;i+=NTH){sbias[i]=bih[i];sbias[384+i]=bhh[i];}
    if(tid<128)sbias[768+tid]=cbias[tid];

    stageT(sb+SB0H,sb+SB0L,0,tid);   // rootT

    // ---- build h tile (bf16 hi/lo) from hin — coalesced ----
    {
        int r=tid>>3, c0=(tid&7)*16;
        const float* src=hin+(size_t)(row0+r)*D+c0;
        uint32_t base=(uint32_t)r*STRB+(uint32_t)c0*2;
#pragma unroll
        for(int i=0;i<4;i++){
            float4 v=*(const float4*)(src+i*4);
            uint32_t p0=pkbf(v.x,v.y), p1=pkbf(v.z,v.w);
            uint32_t q0=pkbf(v.x-upbf(p0,0),v.y-upbf(p0,1));
            uint32_t q1=pkbf(v.z-upbf(p1,0),v.w-upbf(p1,1));
            *(uint32_t*)(smem+SHH+base+i*8)  =p0;
            *(uint32_t*)(smem+SHH+base+i*8+4)=p1;
            *(uint32_t*)(smem+SHL+base+i*8)  =q0;
            *(uint32_t*)(smem+SHL+base+i*8+4)=q1;
        }
    }

    // ---- edge aggregation -> d_agg (4 nodes/warp) ----
#pragma unroll 1
    for(int q=0;q<4;q++){
        int n=row0+4*w+q;
        int s0=d_off[n],s1=d_off[n+1];
        float4 acc4=make_float4(0.f,0.f,0.f,0.f);
        for(int i=s0;i<s1;i++){
            int e=d_csr[i];
            int s=ei[e],a0=ea[2*e],a1=ea[2*e+1];
            float4 hv=*(const float4*)(hin+(size_t)s*D+lane*4);
            float4 b0=*(const float4*)(embBond+(size_t)a0*D+lane*4);
            float p=hv.x*b0.x+hv.y*b0.y+hv.z*b0.z+hv.w*b0.w;
#pragma unroll
            for(int o=16;o>0;o>>=1)p+=__shfl_xor_sync(~0u,p,o);
            float4 b1=*(const float4*)(embBond+(size_t)a1*D+lane*4);
            acc4.x+=p*b1.x;acc4.y+=p*b1.y;acc4.z+=p*b1.z;acc4.w+=p*b1.w;
        }
        float iv=d_invdeg[n];
        acc4.x*=iv;acc4.y*=iv;acc4.z*=iv;acc4.w*=iv;
        *(float4*)(d_agg+(size_t)n*D+lane*4)=acc4;
    }

    float acc[4][4];
    // ---- P1: conv = lrelu(h@root + agg + cbias) -> m tiles ----
    CPWAIT(); __syncthreads();
    stageT(sb+SB1H,sb+SB1L,1,tid);               // wih_r
    ZACC4(acc);
    gemm_s(acc,ahH,ahL,sb+SB0H,sb+SB0L,bt);
    {
#pragma unroll
        for(int n=0;n<4;n++){
            int colg=(nt0+n)*8+(lane&3)*2;
            float2 a0=*(const float2*)(d_agg+(size_t)(row0+rl)*D+colg);
            float2 a1=*(const float2*)(d_agg+(size_t)(row0+rl+8)*D+colg);
            float b0v=sbias[768+colg],b1v=sbias[768+colg+1];
            float m00=lrelu(acc[n][0]+a0.x+b0v), m01=lrelu(acc[n][1]+a0.y+b1v);
            float m10=lrelu(acc[n][2]+a1.x+b0v), m11=lrelu(acc[n][3]+a1.y+b1v);
            uint32_t p0=pkbf(m00,m01), p1=pkbf(m10,m11);
            uint32_t q0=pkbf(m00-upbf(p0,0),m01-upbf(p0,1));
            uint32_t q1=pkbf(m10-upbf(p1,0),m11-upbf(p1,1));
            *(uint32_t*)(smem+SMH+rl*STRB+colg*2)=p0;
            *(uint32_t*)(smem+SMH+(rl+8)*STRB+colg*2)=p1;
            *(uint32_t*)(smem+SML+rl*STRB+colg*2)=q0;
            *(uint32_t*)(smem+SML+(rl+8)*STRB+colg*2)=q1;
        }
    }
    // ---- P2: m@wih_r ----
    CPWAIT(); __syncthreads();
    stageT(sb+SB0H,sb+SB0L,4,tid);               // whh_r
    ZACC4(acc);
    gemm_s(acc,amH,amL,sb+SB1H,sb+SB1L,bt);
    // ---- P3: + h@whh_r -> r gate ----
    CPWAIT(); __syncthreads();
    stageT(sb+SB1H,sb+SB1L,6,tid);               // whh_n
    gemm_s(acc,ahH,ahL,sb+SB0H,sb+SB0L,bt);
#pragma unroll
    for(int n=0;n<4;n++)
#pragma unroll
    for(int dg=0;dg<4;dg++){
        int col=(nt0+n)*8+(lane&3)*2+(dg&1);
        Pgg[(n*4+dg)*NTH+tid]=sigm(acc[n][dg]+sbias[col]+sbias[384+col]);
    }
    // ---- P4: h@whh_n -> P = r*(hn+bhh_n) ----
    CPWAIT(); __syncthreads();
    stageT(sb+SB0H,sb+SB0L,3,tid);               // wih_n
    ZACC4(acc);
    gemm_s(acc,ahH,ahL,sb+SB1H,sb+SB1L,bt);
#pragma unroll
    for(int n=0;n<4;n++)
#pragma unroll
    for(int dg=0;dg<4;dg++){
        int col=(nt0+n)*8+(lane&3)*2+(dg&1);
        int i=(n*4+dg)*NTH+tid;
        Pgg[i]=Pgg[i]*(acc[n][dg]+sbias[640+col]);
    }
    // ---- P5: m@wih_n -> P = tanh(in+bih_n+P) ----
    CPWAIT(); __syncthreads();
    stageT(sb+SB1H,sb+SB1L,2,tid);               // wih_z
    ZACC4(acc);
    gemm_s(acc,amH,amL,sb+SB0H,sb+SB0L,bt);
#pragma unroll
    for(int n=0;n<4;n++)
#pragma unroll
    for(int dg=0;dg<4;dg++){
        int col=(nt0+n)*8+(lane&3)*2+(dg&1);
        int i=(n*4+dg)*NTH+tid;
        Pgg[i]=tanhfast(acc[n][dg]+sbias[256+col]+Pgg[i]);
    }
    // ---- P6: m@wih_z ----
    CPWAIT(); __syncthreads();
    stageT(sb+SB0H,sb+SB0L,5,tid);               // whh_z
    ZACC4(acc);
    gemm_s(acc,amH,amL,sb+SB1H,sb+SB1L,bt);
    // ---- P7: + h@whh_z -> z gate + update ----
    CPWAIT(); __syncthreads();
    gemm_s(acc,ahH,ahL,sb+SB0H,sb+SB0L,bt);
    {
        int rbase=row0+rl;
#pragma unroll
        for(int n=0;n<4;n++){
            int nt=nt0+n;
            float o[4];
#pragma unroll
            for(int dg=0;dg<4;dg++){
                int col=nt*8+(lane&3)*2+(dg&1);
                int r2=rl+(dg>>1)*8;
                float hv=__bfloat162float(*(__nv_bfloat16*)(smem+SHH+r2*STRB+col*2))
                        +__bfloat162float(*(__nv_bfloat16*)(smem+SHL+r2*STRB+col*2));
                float z=sigm(acc[n][dg]+sbias[128+col]+sbias[512+col]);
                float nv=Pgg[(n*4+dg)*NTH+tid];
                o[dg]=(1.f-z)*nv+z*hv;
            }
            int c0=nt*8+(lane&3)*2;
            *(float2*)(hout+(size_t)rbase*D+c0)    =make_float2(o[0],o[1]);
            *(float2*)(hout+(size_t)(rbase+8)*D+c0)=make_float2(o[2],o[3]);
        }
    }
}

// ---------------- row gather ----------------
__global__ void k_gather(float* __restrict__ dst,const float* __restrict__ src,
                         const int* __restrict__ idx,int n){
    int t=blockIdx.x*blockDim.x+threadIdx.x;
    int row=t>>5,l=t&31;if(row>=n)return;
    *(float4*)(dst+(size_t)row*128+l*4)=*(const float4*)(src+(size_t)idx[row]*128+l*4);
}

// ---------------- global mean pool ----------------
__global__ void k_pool(const int* __restrict__ nb){
    int g=blockIdx.x,c=threadIdx.x;
    int lo=0,hi=NN;while(lo<hi){int m=(lo+hi)>>1;if(nb[m]<g)lo=m+1;else hi=m;}
    int s=lo;lo=0;hi=NN;while(lo<hi){int m=(lo+hi)>>1;if(nb[m]<=g)lo=m+1;else hi=m;}
    int e=lo;float sum=0.f;
    for(int r=s;r<e;r++)sum+=d_h[(size_t)r*128+c];
    d_gm[g*128+c]=sum/fmaxf((float)(e-s),1.f);
}

// ---------------- stop head ----------------
__global__ void k_stop(const float* __restrict__ w2,const float* __restrict__ b2,
                       float* __restrict__ out){
    int w=(blockIdx.x*blockDim.x+threadIdx.x)>>5,l=threadIdx.x&31;
    if(w>=NG)return;
    float4 g=*(const float4*)(d_g1+(size_t)w*128+l*4);
    float4 ww=*(const float4*)(w2+l*4);
    float p=g.x*ww.x+g.y*ww.y+g.z*ww.z+g.w*ww.w;
#pragma unroll
    for(int o=16;o>0;o>>=1)p+=__shfl_xor_sync(~0u,p,o);
    if(l==0)out[NS*OPS+w]=p+b2[0];
}

// ---------------- launch ----------------
extern "C" void kernel_launch(void* const* d_in,const int* in_sizes,int n_in,
                              void* d_out,int out_size){
    const int* x   =(const int*)d_in[0];
    const int* st  =(const int*)d_in[1];
    const int* ea  =(const int*)d_in[2];
    const int* ei  =(const int*)d_in[3];
    const int* sni =(const int*)d_in[4];
    const int* nb  =(const int*)d_in[5];
    const float* embB=(const float*)d_in[6];
    const float* embS=(const float*)d_in[7];
    const float* embBond=(const float*)d_in[8];
    const float* b2e_w1=(const float*)d_in[9],  *b2e_b1=(const float*)d_in[10];
    const float* b2e_w2=(const float*)d_in[11], *b2e_b2=(const float*)d_in[12];
    const float* conv_root=(const float*)d_in[13], *conv_bias=(const float*)d_in[14];
    const float* w_ih=(const float*)d_in[15], *w_hh=(const float*)d_in[16];
    const float* b_ih=(const float*)d_in[17], *b_hh=(const float*)d_in[18];
    const float* s2p_w1=(const float*)d_in[19], *s2p_b1=(const float*)d_in[20];
    const float* s2p_w2=(const float*)d_in[21], *s2p_b2=(const float*)d_in[22];
    const float* s2p_w3=(const float*)d_in[23], *s2p_b3=(const float*)d_in[24];
    const float* g2p_w1=(const float*)d_in[25], *g2p_b1=(const float*)d_in[26];
    const float* g2p_w2=(const float*)d_in[27], *g2p_b2=(const float*)d_in[28];
    float* out=(float*)d_out;

    void* p;
    cudaGetSymbolAddress(&p,d_h);   float* ph =(float*)p;
    cudaGetSymbolAddress(&p,d_h2);  float* ph2=(float*)p;
    cudaGetSymbolAddress(&p,d_m);   float* pm =(float*)p;
    cudaGetSymbolAddress(&p,d_sg);  float* psg=(float*)p;
    cudaGetSymbolAddress(&p,d_se);  float* pse=(float*)p;
    cudaGetSymbolAddress(&p,d_s1);  float* ps1=(float*)p;
    cudaGetSymbolAddress(&p,d_gm);  float* pgm=(float*)p;
    cudaGetSymbolAddress(&p,d_g1);  float* pg1=(float*)p;

    static int attr_set=0;
    if(!attr_set){
        cudaFuncSetAttribute(k_step_mma,cudaFuncAttributeMaxDynamicSharedMemorySize,SMT);
        attr_set=1;
    }

    // 3 prologue launches -> step #1 stays at ncu slot 6
    k_prep0<<<448,256>>>(conv_root,w_ih,w_hh);
    k_csr  <<<CSRB,1024>>>(ei);
    k_b2e  <<<NN/64,256>>>(x,embB,b2e_w1,b2e_b1,b2e_w2,b2e_b2);

    for(int s=0;s<NSTEPS;s++){
        const float* hi=(s&1)?ph2:ph;
        float* ho=(s&1)?ph:ph2;
        k_step_mma<<<NN/64,NTH,SMT>>>(hi,ho,ei,ea,embBond,conv_bias,b_ih,b_hh);
    }

    // stem head
    k_gather<<<NS*32/256,256>>>(psg,ph,sni,NS);
    k_gather<<<NS*32/256,256>>>(pse,embS,st,NS);
    k_gemm<<<dim3(NS/64,1),256>>>(psg,s2p_w1,    nullptr,nullptr,0,ps1,128,128,256,1,0);
    k_gemm<<<dim3(NS/64,1),256>>>(pse,s2p_w1+128,s2p_b1, ps1,128,  ps1,128,128,256,1,1);
    k_gemm<<<dim3(NS/64,1),256>>>(ps1,s2p_w2,s2p_b2,nullptr,0,pm, 128,128,128,1,1);
    k_gemm<<<dim3(NS/64,1),256>>>(pm, s2p_w3,s2p_b3,nullptr,0,out,105,105,128,1,0);

    // stop head
    k_pool<<<NG,128>>>(nb);
    k_gemm<<<dim3(NG/64,1),256>>>(pgm,g2p_w1,g2p_b1,nullptr,0,pg1,128,128,128,1,1);
    k_stop<<<NG/8,256>>>(g2p_w2,g2p_b2,out);
}

// round 15
// speedup vs baseline: 1.2012x; 1.0414x over previous
#include <cuda_runtime.h>
#include <cuda_bf16.h>
#include <math.h>
#include <stdint.h>

#define D 128
#define NN 8192
#define NE 16384
#define NS 4096
#define NG 256
#define OPS 105
#define NSTEPS 12
#define ATS 68

typedef unsigned long long ull;

// ---------------- scratch ----------------
__device__ float d_h[NN*D], d_h2[NN*D], d_agg[NN*D];
__device__ int   d_deg[NN], d_off[NN+1], d_cur[NN], d_csr[NE];
__device__ float d_invdeg[NN];
__device__ __nv_bfloat16 d_bwh[7*16384], d_bwl[7*16384];
__device__ unsigned g_cnt=0, g_epoch=0;

// ---------------- helpers ----------------
__device__ __forceinline__ ull pack2(float x){unsigned u=__float_as_uint(x);ull r;asm("mov.b64 %0,{%1,%1};":"=l"(r):"r"(u));return r;}
__device__ __forceinline__ void fma2(ull&a,ull x,ull y){asm("fma.rn.f32x2 %0,%1,%2,%0;":"+l"(a):"l"(x),"l"(y));}
__device__ __forceinline__ float lo32(ull v){return __uint_as_float((unsigned)v);}
__device__ __forceinline__ float hi32(ull v){return __uint_as_float((unsigned)(v>>32));}
__device__ __forceinline__ float lrelu(float v){return v>0.f?v:0.01f*v;}
__device__ __forceinline__ float sigm(float x){float e=__expf(-x);return __fdividef(1.f,1.f+e);}
__device__ __forceinline__ float tanhfast(float x){
    x=fminf(fmaxf(x,-9.f),9.f);
    float t=__expf(2.f*x);
    return __fdividef(t-1.f,t+1.f);
}
__device__ __forceinline__ uint32_t s2u(const void* p){
    uint32_t a; asm("{ .reg .u64 t; cvta.to.shared.u64 t, %1; cvt.u32.u64 %0, t; }":"=r"(a):"l"(p)); return a;
}
__device__ __forceinline__ uint32_t pkbf(float a,float b){
    uint32_t r; asm("cvt.rn.bf16x2.f32 %0, %1, %2;":"=r"(r):"f"(b),"f"(a)); return r;
}
__device__ __forceinline__ float upbf(uint32_t u,int slot){
    return __uint_as_float((slot?(u>>16):(u&0xffffu))<<16);
}

#define CP16(s,g)  asm volatile("cp.async.cg.shared.global [%0], [%1], 16;"::"r"(s),"l"(g):"memory")
#define CPCOMMIT() asm volatile("cp.async.commit_group;":::"memory")
#define CPWAIT()   asm volatile("cp.async.wait_group 0;":::"memory")
#define LDSM4(r0,r1,r2,r3,a) asm volatile( \
    "ldmatrix.sync.aligned.m8n8.x4.shared.b16 {%0,%1,%2,%3},[%4];" \
    :"=r"(r0),"=r"(r1),"=r"(r2),"=r"(r3):"r"(a))
#define MMA(dd,aa,b0,b1) asm volatile( \
    "mma.sync.aligned.m16n8k16.row.col.f32.bf16.bf16.f32 {%0,%1,%2,%3},{%4,%5,%6,%7},{%8,%9},{%0,%1,%2,%3};" \
    : "+f"((dd)[0]),"+f"((dd)[1]),"+f"((dd)[2]),"+f"((dd)[3]) \
    : "r"((aa)[0]),"r"((aa)[1]),"r"((aa)[2]),"r"((aa)[3]),"r"(b0),"r"(b1))

// ---------------- prologue #1: weight prep + deg zero ----------------
__global__ void k_prep0(const float* __restrict__ root,const float* __restrict__ wih,
                        const float* __restrict__ whh){
    int t=blockIdx.x*blockDim.x+threadIdx.x;    // 448 x 256
    if(t<NN)d_deg[t]=0;
    if(t<7*16384){
        int tt=t>>14, rem=t&16383, n=rem>>7, k=rem&127;
        float v;
        if(tt==0)      v=root[k*128+n];
        else if(tt<4)  v=wih[((tt-1)*128+n)*128+k];
        else           v=whh[((tt-4)*128+n)*128+k];
        __nv_bfloat16 hi=__float2bfloat16(v);
        __nv_bfloat16 lo=__float2bfloat16(v-__bfloat162float(hi));
        d_bwh[t]=hi; d_bwl[t]=lo;
    }
}

// ---------------- prologue #2: fused CSR ----------------
#define CSRB 32
__device__ __forceinline__ void gridbar32(unsigned tgt){
    __syncthreads();
    if(threadIdx.x==0){
        __threadfence();
        unsigned old=atomicAdd(&g_cnt,1u);
        if(old==CSRB-1u){ g_cnt=0u; __threadfence(); atomicAdd(&g_epoch,1u); }
        else { while((int)(*(volatile unsigned*)&g_epoch - tgt) < 0){} }
        __threadfence();
    }
    __syncthreads();
}
__global__ void __launch_bounds__(1024)
k_csr(const int* __restrict__ ei){
    __shared__ unsigned s_ep0;
    if(threadIdx.x==0)s_ep0=*(volatile unsigned*)&g_epoch;
    __syncthreads();
    unsigned ep0=s_ep0;
    int gt=blockIdx.x*1024+threadIdx.x;
    if(gt<NE)atomicAdd(&d_deg[ei[NE+gt]],1);
    gridbar32(ep0+1u);
    if(blockIdx.x==0){
        __shared__ int ws[32];
        int t=threadIdx.x,base=t*8,v[8],pre[8],s=0;
#pragma unroll
        for(int i=0;i<8;i++){v[i]=d_deg[base+i];pre[i]=s;s+=v[i];}
        int lane=t&31,wid=t>>5,xx=s;
#pragma unroll
        for(int o=1;o<32;o<<=1){int y=__shfl_up_sync(~0u,xx,o);if(lane>=o)xx+=y;}
        if(lane==31)ws[wid]=xx;
        __syncthreads();
        if(wid==0){int w0=ws[lane],x2=w0;
#pragma unroll
            for(int o=1;o<32;o<<=1){int y=__shfl_up_sync(~0u,x2,o);if(lane>=o)x2+=y;}
            ws[lane]=x2-w0;}
        __syncthreads();
        int obase=ws[wid]+(xx-s);
#pragma unroll
        for(int i=0;i<8;i++){int o=obase+pre[i];d_off[base+i]=o;d_cur[base+i]=o;
            d_invdeg[base+i]=v[i]>0?1.0f/(float)v[i]:0.0f;}
        if(t==1023)d_off[NN]=obase+s;
    }
    gridbar32(ep0+2u);
    if(gt<NE){int p=atomicAdd(&d_cur[ei[NE+gt]],1);d_csr[p]=gt;}
    gridbar32(ep0+3u);
    if(gt<NN){
        int a=d_off[gt],b=d_off[gt+1];
        for(int i=a+1;i<b;i++){int key=d_csr[i],j=i-1;
            while(j>=a&&d_csr[j]>key){d_csr[j+1]=d_csr[j];j--;}d_csr[j+1]=key;}
    }
}

// ---------------- shared fp32 GEMM inner loop ----------------
__device__ __forceinline__ void f32gemm32(ull acc[4][4],const float* __restrict__ Ab,
                                          const float* __restrict__ Bb){
#pragma unroll 8
    for(int k=0;k<32;k++){
        ulonglong2 A0=*(const ulonglong2*)(Ab+k*ATS);
        ulonglong2 A1=*(const ulonglong2*)(Ab+k*ATS+4);
        float4 b=*(const float4*)(Bb+k*128);
        ull B0=pack2(b.x),B1=pack2(b.y),B2=pack2(b.z),B3=pack2(b.w);
        fma2(acc[0][0],A0.x,B0);fma2(acc[0][1],A0.x,B1);fma2(acc[0][2],A0.x,B2);fma2(acc[0][3],A0.x,B3);
        fma2(acc[1][0],A0.y,B0);fma2(acc[1][1],A0.y,B1);fma2(acc[1][2],A0.y,B2);fma2(acc[1][3],A0.y,B3);
        fma2(acc[2][0],A1.x,B0);fma2(acc[2][1],A1.x,B1);fma2(acc[2][2],A1.x,B2);fma2(acc[2][3],A1.x,B3);
        fma2(acc[3][0],A1.y,B0);fma2(acc[3][1],A1.y,B1);fma2(acc[3][2],A1.y,B2);fma2(acc[3][3],A1.y,B3);
    }
}
#define ZACCU(acc) {_Pragma("unroll") for(int _p=0;_p<4;_p++){_Pragma("unroll") for(int _c=0;_c<4;_c++)(acc)[_p][_c]=0ull;}}

// ---------------- prologue #3: fused block2emb (both layers) ---------------
__global__ void __launch_bounds__(256)
k_b2e(const int* __restrict__ x,const float* __restrict__ embB,
      const float* __restrict__ w1,const float* __restrict__ b1,
      const float* __restrict__ w2,const float* __restrict__ b2){
    __shared__ float At[32*ATS];
    __shared__ float Mt[128*ATS];
    __shared__ float Bp[32*128];
    int t=threadIdx.x,rg=t>>5,cg=t&31;
    int row0=blockIdx.x*64;
    int xi=x[row0+(t&63)];
    ull acc[4][4];
    ZACCU(acc);
    for(int kc=0;kc<128;kc+=32){
        { int rl=t&63,kg=t>>6;const float*src=embB+(size_t)xi*128+kc+kg*8;
          float4 v0=*(const float4*)src,v1=*(const float4*)(src+4);int kb=kg*8;
          At[(kb+0)*ATS+rl]=v0.x;At[(kb+1)*ATS+rl]=v0.y;At[(kb+2)*ATS+rl]=v0.z;At[(kb+3)*ATS+rl]=v0.w;
          At[(kb+4)*ATS+rl]=v1.x;At[(kb+5)*ATS+rl]=v1.y;At[(kb+6)*ATS+rl]=v1.z;At[(kb+7)*ATS+rl]=v1.w;}
        { int j=t>>1,h=t&1;const float*src=w1+(size_t)j*128+kc+h*16;
#pragma unroll
          for(int i=0;i<4;i++){float4 v=*(const float4*)(src+i*4);int kk=h*16+i*4;
              Bp[(kk+0)*128+j]=v.x;Bp[(kk+1)*128+j]=v.y;Bp[(kk+2)*128+j]=v.z;Bp[(kk+3)*128+j]=v.w;}}
        __syncthreads();
        f32gemm32(acc,At+rg*8,Bp+cg*4);
        __syncthreads();
    }
#pragma unroll
    for(int c=0;c<4;c++){
        int j=cg*4+c;float bv=b1[j];
#pragma unroll
        for(int p=0;p<4;p++){
            int r=rg*8+2*p;
            Mt[j*ATS+r]  =lrelu(lo32(acc[p][c])+bv);
            Mt[j*ATS+r+1]=lrelu(hi32(acc[p][c])+bv);
        }
    }
    __syncthreads();
    ZACCU(acc);
    for(int kc=0;kc<128;kc+=32){
        { int j=t>>1,h=t&1;const float*src=w2+(size_t)j*128+kc+h*16;
#pragma unroll
          for(int i=0;i<4;i++){float4 v=*(const float4*)(src+i*4);int kk=h*16+i*4;
              Bp[(kk+0)*128+j]=v.x;Bp[(kk+1)*128+j]=v.y;Bp[(kk+2)*128+j]=v.z;Bp[(kk+3)*128+j]=v.w;}}
        __syncthreads();
        f32gemm32(acc,Mt+kc*ATS+rg*8,Bp+cg*4);
        __syncthreads();
    }
#pragma unroll
    for(int c=0;c<4;c++){
        int j=cg*4+c;float bv=b2[j];
#pragma unroll
        for(int p=0;p<4;p++){
            int r=row0+rg*8+2*p;
            d_h[(size_t)r*128+j]=lo32(acc[p][c])+bv;
            d_h[(size_t)(r+1)*128+j]=hi32(acc[p][c])+bv;
        }
    }
}

// ---------------- fused stem head: cat-gather + 3-layer MLP ----------------
__global__ void __launch_bounds__(256)
k_stem(const int* __restrict__ sni,const int* __restrict__ st,
       const float* __restrict__ h,const float* __restrict__ embS,
       const float* __restrict__ w1,const float* __restrict__ b1,
       const float* __restrict__ w2,const float* __restrict__ b2,
       const float* __restrict__ w3,const float* __restrict__ b3,
       float* __restrict__ out){
    __shared__ float At[32*ATS];
    __shared__ float Mt[128*ATS];
    __shared__ float Bp[32*128];
    int t=threadIdx.x,rg=t>>5,cg=t&31;
    int row0=blockIdx.x*64;
    int xi=sni[row0+(t&63)];
    int si=st[row0+(t&63)];
    ull acc[4][4];
    ZACCU(acc);
    // layer1: [h[xi] | embS[si]] @ w1^T  (K=256 in two halves, same accumulators)
    for(int half=0;half<2;half++){
        const float* Abase = half? (embS+(size_t)si*128) : (h+(size_t)xi*128);
        int koff=half*128;
        for(int kc=0;kc<128;kc+=32){
            { int rl=t&63,kg=t>>6;const float*src=Abase+kc+kg*8;
              float4 v0=*(const float4*)src,v1=*(const float4*)(src+4);int kb=kg*8;
              At[(kb+0)*ATS+rl]=v0.x;At[(kb+1)*ATS+rl]=v0.y;At[(kb+2)*ATS+rl]=v0.z;At[(kb+3)*ATS+rl]=v0.w;
              At[(kb+4)*ATS+rl]=v1.x;At[(kb+5)*ATS+rl]=v1.y;At[(kb+6)*ATS+rl]=v1.z;At[(kb+7)*ATS+rl]=v1.w;}
            { int j=t>>1,hh=t&1;const float*src=w1+(size_t)j*256+koff+kc+hh*16;
#pragma unroll
              for(int i=0;i<4;i++){float4 v=*(const float4*)(src+i*4);int kk=hh*16+i*4;
                  Bp[(kk+0)*128+j]=v.x;Bp[(kk+1)*128+j]=v.y;Bp[(kk+2)*128+j]=v.z;Bp[(kk+3)*128+j]=v.w;}}
            __syncthreads();
            f32gemm32(acc,At+rg*8,Bp+cg*4);
            __syncthreads();
        }
    }
#pragma unroll
    for(int c=0;c<4;c++){
        int j=cg*4+c;float bv=b1[j];
#pragma unroll
        for(int p=0;p<4;p++){
            int r=rg*8+2*p;
            Mt[j*ATS+r]  =lrelu(lo32(acc[p][c])+bv);
            Mt[j*ATS+r+1]=lrelu(hi32(acc[p][c])+bv);
        }
    }
    __syncthreads();
    // layer2: Mt @ w2^T -> Mt (act)
    ZACCU(acc);
    for(int kc=0;kc<128;kc+=32){
        { int j=t>>1,hh=t&1;const float*src=w2+(size_t)j*128+kc+hh*16;
#pragma unroll
          for(int i=0;i<4;i++){float4 v=*(const float4*)(src+i*4);int kk=hh*16+i*4;
              Bp[(kk+0)*128+j]=v.x;Bp[(kk+1)*128+j]=v.y;Bp[(kk+2)*128+j]=v.z;Bp[(kk+3)*128+j]=v.w;}}
        __syncthreads();
        f32gemm32(acc,Mt+kc*ATS+rg*8,Bp+cg*4);
        __syncthreads();
    }
#pragma unroll
    for(int c=0;c<4;c++){
        int j=cg*4+c;float bv=b2[j];
#pragma unroll
        for(int p=0;p<4;p++){
            int r=rg*8+2*p;
            Mt[j*ATS+r]  =lrelu(lo32(acc[p][c])+bv);
            Mt[j*ATS+r+1]=lrelu(hi32(acc[p][c])+bv);
        }
    }
    __syncthreads();
    // layer3: Mt @ w3^T (N=105, zero-padded)
    ZACCU(acc);
    for(int kc=0;kc<128;kc+=32){
        { int j=t>>1,hh=t&1;
          if(j<OPS){const float*src=w3+(size_t)j*128+kc+hh*16;
#pragma unroll
              for(int i=0;i<4;i++){float4 v=*(const float4*)(src+i*4);int kk=hh*16+i*4;
                  Bp[(kk+0)*128+j]=v.x;Bp[(kk+1)*128+j]=v.y;Bp[(kk+2)*128+j]=v.z;Bp[(kk+3)*128+j]=v.w;}
          }else{
#pragma unroll
              for(int i=0;i<16;i++)Bp[(hh*16+i)*128+j]=0.f;}}
        __syncthreads();
        f32gemm32(acc,Mt+kc*ATS+rg*8,Bp+cg*4);
        __syncthreads();
    }
#pragma unroll
    for(int c=0;c<4;c++){
        int j=cg*4+c;if(j>=OPS)continue;
        float bv=b3[j];
#pragma unroll
        for(int p=0;p<4;p++){
            int r=row0+rg*8+2*p;
            out[(size_t)r*OPS+j]=lo32(acc[p][c])+bv;
            out[(size_t)(r+1)*OPS+j]=hi32(acc[p][c])+bv;
        }
    }
}

// ---------------- fused stop head: pool + MLP + dot ----------------
__global__ void __launch_bounds__(128)
k_stoph(const int* __restrict__ nb,const float* __restrict__ w1,const float* __restrict__ b1,
        const float* __restrict__ w2,const float* __restrict__ b2,float* __restrict__ out){
    __shared__ float gm[128], s1[128];
    int g=blockIdx.x,c=threadIdx.x;
    int lo=0,hi=NN;while(lo<hi){int m=(lo+hi)>>1;if(nb[m]<g)lo=m+1;else hi=m;}
    int s=lo;lo=0;hi=NN;while(lo<hi){int m=(lo+hi)>>1;if(nb[m]<=g)lo=m+1;else hi=m;}
    int e=lo;float sum=0.f;
    for(int r=s;r<e;r++)sum+=d_h[(size_t)r*128+c];
    gm[c]=sum/fmaxf((float)(e-s),1.f);
    __syncthreads();
    float a=b1[c];
    const float* wr=w1+(size_t)c*128;
    for(int k=0;k<128;k++)a+=gm[k]*wr[k];
    s1[c]=lrelu(a)*w2[c];
    __syncthreads();
    if(c<64)s1[c]+=s1[c+64];
    __syncthreads();
    if(c<32){
        float v=s1[c]+s1[c+32];
#pragma unroll
        for(int o=16;o>0;o>>=1)v+=__shfl_xor_sync(~0u,v,o);
        if(c==0)out[(size_t)NS*OPS+g]=v+b2[0];
    }
}

// ---------------- mma.sync fused conv step (R14-exact) ----------------
#define SB0H 0
#define SB0L 34816
#define SB1H 69632
#define SB1L 104448
#define SHH  139264
#define SHL  156672
#define SMH  174080
#define SML  191488
#define SBI  208896
#define SMT  212480
#define STRB 272
#define NTH  512

__device__ __forceinline__ void stageT(uint32_t sH,uint32_t sL,int tile,int tid){
    const char* gh=(const char*)(d_bwh+tile*16384);
    const char* gl=(const char*)(d_bwl+tile*16384);
#pragma unroll
    for(int q=0;q<4;q++){
        int i=tid+q*NTH, n=i>>4, c=i&15;
        CP16(sH+n*STRB+c*16, gh+n*256+c*16);
        CP16(sL+n*STRB+c*16, gl+n*256+c*16);
    }
    CPCOMMIT();
}

__device__ __forceinline__ void gemm_s(float acc[4][4],uint32_t atH,uint32_t atL,
                                       uint32_t bh,uint32_t bl,int bt){
#pragma unroll
    for(int kc=0;kc<8;kc++){
        uint32_t aH[4],aL[4];
        LDSM4(aH[0],aH[1],aH[2],aH[3],atH+kc*32);
        LDSM4(aL[0],aL[1],aL[2],aL[3],atL+kc*32);
#pragma unroll
        for(int jj=0;jj<2;jj++){
            uint32_t h0,h1,h2,h3,l0,l1,l2,l3;
            uint32_t off=jj*4352+kc*32+bt;
            LDSM4(h0,h1,h2,h3,bh+off);
            LDSM4(l0,l1,l2,l3,bl+off);
            MMA(acc[2*jj],  aH,h0,h1);
            MMA(acc[2*jj+1],aH,h2,h3);
            MMA(acc[2*jj],  aL,h0,h1);
            MMA(acc[2*jj+1],aL,h2,h3);
            MMA(acc[2*jj],  aH,l0,l1);
            MMA(acc[2*jj+1],aH,l2,l3);
        }
    }
}
#define ZACC4(acc) {_Pragma("unroll") for(int _n=0;_n<4;_n++){_Pragma("unroll") for(int _d=0;_d<4;_d++)(acc)[_n][_d]=0.f;}}

__global__ void __launch_bounds__(NTH,1)
k_step_mma(const float* __restrict__ hin, float* __restrict__ hout,
           const int* __restrict__ ei, const int* __restrict__ ea,
           const float* __restrict__ embBond,
           const float* __restrict__ cbias,
           const float* __restrict__ bih, const float* __restrict__ bhh){
    extern __shared__ char smem[];
    uint32_t sb=s2u(smem);
    float* sbias=(float*)(smem+SBI);
    float* Pgg=d_agg+(size_t)blockIdx.x*8192;
    int tid=threadIdx.x, w=tid>>5, lane=tid&31;
    int row0=blockIdx.x*64;
    int wr=w&3, cg=w>>2, nt0=cg*4;
    int bt=nt0*2176+((lane>>3)>>1)*2176+(lane&7)*STRB+((lane>>3)&1)*16;
    int rl=16*wr+(lane>>2);
    uint32_t atoff=(uint32_t)(16*wr+((lane>>3)&1)*8+(lane&7))*STRB+(uint32_t)(lane>>4)*16;
    uint32_t ahH=sb+SHH+atoff, ahL=sb+SHL+atoff;
    uint32_t amH=sb+SMH+atoff, amL=sb+SML+atoff;

    for(int i=tid;i<384;i+=NTH){sbias[i]=bih[i];sbias[384+i]=bhh[i];}
    if(tid<128)sbias[768+tid]=cbias[tid];

    stageT(sb+SB0H,sb+SB0L,0,tid);   // rootT

    {
        int r=tid>>3, c0=(tid&7)*16;
        const float* src=hin+(size_t)(row0+r)*D+c0;
        uint32_t base=(uint32_t)r*STRB+(uint32_t)c0*2;
#pragma unroll
        for(int i=0;i<4;i++){
            float4 v=*(const float4*)(src+i*4);
            uint32_t p0=pkbf(v.x,v.y), p1=pkbf(v.z,v.w);
            uint32_t q0=pkbf(v.x-upbf(p0,0),v.y-upbf(p0,1));
            uint32_t q1=pkbf(v.z-upbf(p1,0),v.w-upbf(p1,1));
            *(uint32_t*)(smem+SHH+base+i*8)  =p0;
            *(uint32_t*)(smem+SHH+base+i*8+4)=p1;
            *(uint32_t*)(smem+SHL+base+i*8)  =q0;
            *(uint32_t*)(smem+SHL+base+i*8+4)=q1;
        }
    }

#pragma unroll 1
    for(int q=0;q<4;q++){
        int n=row0+4*w+q;
        int s0=d_off[n],s1=d_off[n+1];
        float4 acc4=make_float4(0.f,0.f,0.f,0.f);
        for(int i=s0;i<s1;i++){
            int e=d_csr[i];
            int s=ei[e],a0=ea[2*e],a1=ea[2*e+1];
            float4 hv=*(const float4*)(hin+(size_t)s*D+lane*4);
            float4 b0=*(const float4*)(embBond+(size_t)a0*D+lane*4);
            float p=hv.x*b0.x+hv.y*b0.y+hv.z*b0.z+hv.w*b0.w;
#pragma unroll
            for(int o=16;o>0;o>>=1)p+=__shfl_xor_sync(~0u,p,o);
            float4 b1=*(const float4*)(embBond+(size_t)a1*D+lane*4);
            acc4.x+=p*b1.x;acc4.y+=p*b1.y;acc4.z+=p*b1.z;acc4.w+=p*b1.w;
        }
        float iv=d_invdeg[n];
        acc4.x*=iv;acc4.y*=iv;acc4.z*=iv;acc4.w*=iv;
        *(float4*)(d_agg+(size_t)n*D+lane*4)=acc4;
    }

    float acc[4][4];
    CPWAIT(); __syncthreads();
    stageT(sb+SB1H,sb+SB1L,1,tid);               // wih_r
    ZACC4(acc);
    gemm_s(acc,ahH,ahL,sb+SB0H,sb+SB0L,bt);
    {
#pragma unroll
        for(int n=0;n<4;n++){
            int colg=(nt0+n)*8+(lane&3)*2;
            float2 a0=*(const float2*)(d_agg+(size_t)(row0+rl)*D+colg);
            float2 a1=*(const float2*)(d_agg+(size_t)(row0+rl+8)*D+colg);
            float b0v=sbias[768+colg],b1v=sbias[768+colg+1];
            float m00=lrelu(acc[n][0]+a0.x+b0v), m01=lrelu(acc[n][1]+a0.y+b1v);
            float m10=lrelu(acc[n][2]+a1.x+b0v), m11=lrelu(acc[n][3]+a1.y+b1v);
            uint32_t p0=pkbf(m00,m01), p1=pkbf(m10,m11);
            uint32_t q0=pkbf(m00-upbf(p0,0),m01-upbf(p0,1));
            uint32_t q1=pkbf(m10-upbf(p1,0),m11-upbf(p1,1));
            *(uint32_t*)(smem+SMH+rl*STRB+colg*2)=p0;
            *(uint32_t*)(smem+SMH+(rl+8)*STRB+colg*2)=p1;
            *(uint32_t*)(smem+SML+rl*STRB+colg*2)=q0;
            *(uint32_t*)(smem+SML+(rl+8)*STRB+colg*2)=q1;
        }
    }
    CPWAIT(); __syncthreads();
    stageT(sb+SB0H,sb+SB0L,4,tid);               // whh_r
    ZACC4(acc);
    gemm_s(acc,amH,amL,sb+SB1H,sb+SB1L,bt);
    CPWAIT(); __syncthreads();
    stageT(sb+SB1H,sb+SB1L,6,tid);               // whh_n
    gemm_s(acc,ahH,ahL,sb+SB0H,sb+SB0L,bt);
#pragma unroll
    for(int n=0;n<4;n++)
#pragma unroll
    for(int dg=0;dg<4;dg++){
        int col=(nt0+n)*8+(lane&3)*2+(dg&1);
        Pgg[(n*4+dg)*NTH+tid]=sigm(acc[n][dg]+sbias[col]+sbias[384+col]);
    }
    CPWAIT(); __syncthreads();
    stageT(sb+SB0H,sb+SB0L,3,tid);               // wih_n
    ZACC4(acc);
    gemm_s(acc,ahH,ahL,sb+SB1H,sb+SB1L,bt);
#pragma unroll
    for(int n=0;n<4;n++)
#pragma unroll
    for(int dg=0;dg<4;dg++){
        int col=(nt0+n)*8+(lane&3)*2+(dg&1);
        int i=(n*4+dg)*NTH+tid;
        Pgg[i]=Pgg[i]*(acc[n][dg]+sbias[640+col]);
    }
    CPWAIT(); __syncthreads();
    stageT(sb+SB1H,sb+SB1L,2,tid);               // wih_z
    ZACC4(acc);
    gemm_s(acc,amH,amL,sb+SB0H,sb+SB0L,bt);
#pragma unroll
    for(int n=0;n<4;n++)
#pragma unroll
    for(int dg=0;dg<4;dg++){
        int col=(nt0+n)*8+(lane&3)*2+(dg&1);
        int i=(n*4+dg)*NTH+tid;
        Pgg[i]=tanhfast(acc[n][dg]+sbias[256+col]+Pgg[i]);
    }
    CPWAIT(); __syncthreads();
    stageT(sb+SB0H,sb+SB0L,5,tid);               // whh_z
    ZACC4(acc);
    gemm_s(acc,amH,amL,sb+SB1H,sb+SB1L,bt);
    CPWAIT(); __syncthreads();
    gemm_s(acc,ahH,ahL,sb+SB0H,sb+SB0L,bt);
    {
        int rbase=row0+rl;
#pragma unroll
        for(int n=0;n<4;n++){
            int nt=nt0+n;
            float o[4];
#pragma unroll
            for(int dg=0;dg<4;dg++){
                int col=nt*8+(lane&3)*2+(dg&1);
                int r2=rl+(dg>>1)*8;
                float hv=__bfloat162float(*(__nv_bfloat16*)(smem+SHH+r2*STRB+col*2))
                        +__bfloat162float(*(__nv_bfloat16*)(smem+SHL+r2*STRB+col*2));
                float z=sigm(acc[n][dg]+sbias[128+col]+sbias[512+col]);
                float nv=Pgg[(n*4+dg)*NTH+tid];
                o[dg]=(1.f-z)*nv+z*hv;
            }
            int c0=nt*8+(lane&3)*2;
            *(float2*)(hout+(size_t)rbase*D+c0)    =make_float2(o[0],o[1]);
            *(float2*)(hout+(size_t)(rbase+8)*D+c0)=make_float2(o[2],o[3]);
        }
    }
}

// ---------------- launch ----------------
extern "C" void kernel_launch(void* const* d_in,const int* in_sizes,int n_in,
                              void* d_out,int out_size){
    const int* x   =(const int*)d_in[0];
    const int* st  =(const int*)d_in[1];
    const int* ea  =(const int*)d_in[2];
    const int* ei  =(const int*)d_in[3];
    const int* sni =(const int*)d_in[4];
    const int* nb  =(const int*)d_in[5];
    const float* embB=(const float*)d_in[6];
    const float* embS=(const float*)d_in[7];
    const float* embBond=(const float*)d_in[8];
    const float* b2e_w1=(const float*)d_in[9],  *b2e_b1=(const float*)d_in[10];
    const float* b2e_w2=(const float*)d_in[11], *b2e_b2=(const float*)d_in[12];
    const float* conv_root=(const float*)d_in[13], *conv_bias=(const float*)d_in[14];
    const float* w_ih=(const float*)d_in[15], *w_hh=(const float*)d_in[16];
    const float* b_ih=(const float*)d_in[17], *b_hh=(const float*)d_in[18];
    const float* s2p_w1=(const float*)d_in[19], *s2p_b1=(const float*)d_in[20];
    const float* s2p_w2=(const float*)d_in[21], *s2p_b2=(const float*)d_in[22];
    const float* s2p_w3=(const float*)d_in[23], *s2p_b3=(const float*)d_in[24];
    const float* g2p_w1=(const float*)d_in[25], *g2p_b1=(const float*)d_in[26];
    const float* g2p_w2=(const float*)d_in[27], *g2p_b2=(const float*)d_in[28];
    float* out=(float*)d_out;

    void* p;
    cudaGetSymbolAddress(&p,d_h);   float* ph =(float*)p;
    cudaGetSymbolAddress(&p,d_h2);  float* ph2=(float*)p;

    static int attr_set=0;
    if(!attr_set){
        cudaFuncSetAttribute(k_step_mma,cudaFuncAttributeMaxDynamicSharedMemorySize,SMT);
        attr_set=1;
    }

    // 3 prologue launches -> step #1 stays at ncu slot 6
    k_prep0<<<448,256>>>(conv_root,w_ih,w_hh);
    k_csr  <<<CSRB,1024>>>(ei);
    k_b2e  <<<NN/64,256>>>(x,embB,b2e_w1,b2e_b1,b2e_w2,b2e_b2);

    for(int s=0;s<NSTEPS;s++){
        const float* hi=(s&1)?ph2:ph;
        float* ho=(s&1)?ph:ph2;
        k_step_mma<<<NN/64,NTH,SMT>>>(hi,ho,ei,ea,embBond,conv_bias,b_ih,b_hh);
    }

    // fused heads
    k_stem <<<NS/64,256>>>(sni,st,ph,embS,s2p_w1,s2p_b1,s2p_w2,s2p_b2,s2p_w3,s2p_b3,out);
    k_stoph<<<NG,128>>>(nb,g2p_w1,g2p_b1,g2p_w2,g2p_b2,out);
}

// round 16
// speedup vs baseline: 1.2704x; 1.0576x over previous
#include <cuda_runtime.h>
#include <cuda_bf16.h>
#include <math.h>
#include <stdint.h>

#define D 128
#define NN 8192
#define NE 16384
#define NS 4096
#define NG 256
#define OPS 105
#define NSTEPS 12
#define ATS 68

typedef unsigned long long ull;

// ---------------- scratch ----------------
__device__ float d_h[NN*D], d_h2[NN*D], d_agg[NN*D];
__device__ int   d_deg[NN], d_off[NN+1], d_cur[NN], d_csr[NE];
__device__ float d_invdeg[NN];
__device__ __nv_bfloat16 d_bwh[7*16384], d_bwl[7*16384];
__device__ unsigned g_cnt=0, g_epoch=0;

// ---------------- helpers ----------------
__device__ __forceinline__ ull pack2(float x){unsigned u=__float_as_uint(x);ull r;asm("mov.b64 %0,{%1,%1};":"=l"(r):"r"(u));return r;}
__device__ __forceinline__ void fma2(ull&a,ull x,ull y){asm("fma.rn.f32x2 %0,%1,%2,%0;":"+l"(a):"l"(x),"l"(y));}
__device__ __forceinline__ float lo32(ull v){return __uint_as_float((unsigned)v);}
__device__ __forceinline__ float hi32(ull v){return __uint_as_float((unsigned)(v>>32));}
__device__ __forceinline__ float lrelu(float v){return v>0.f?v:0.01f*v;}
__device__ __forceinline__ float sigm(float x){float e=__expf(-x);return __fdividef(1.f,1.f+e);}
__device__ __forceinline__ float tanhfast(float x){
    x=fminf(fmaxf(x,-9.f),9.f);
    float t=__expf(2.f*x);
    return __fdividef(t-1.f,t+1.f);
}
__device__ __forceinline__ uint32_t s2u(const void* p){
    uint32_t a; asm("{ .reg .u64 t; cvta.to.shared.u64 t, %1; cvt.u32.u64 %0, t; }":"=r"(a):"l"(p)); return a;
}
__device__ __forceinline__ uint32_t pkbf(float a,float b){
    uint32_t r; asm("cvt.rn.bf16x2.f32 %0, %1, %2;":"=r"(r):"f"(b),"f"(a)); return r;
}
__device__ __forceinline__ float upbf(uint32_t u,int slot){
    return __uint_as_float((slot?(u>>16):(u&0xffffu))<<16);
}

#define CP16(s,g)  asm volatile("cp.async.cg.shared.global [%0], [%1], 16;"::"r"(s),"l"(g):"memory")
#define CPCOMMIT() asm volatile("cp.async.commit_group;":::"memory")
#define CPWAIT()   asm volatile("cp.async.wait_group 0;":::"memory")
#define LDSM4(r0,r1,r2,r3,a) asm volatile( \
    "ldmatrix.sync.aligned.m8n8.x4.shared.b16 {%0,%1,%2,%3},[%4];" \
    :"=r"(r0),"=r"(r1),"=r"(r2),"=r"(r3):"r"(a))
#define MMA(dd,aa,b0,b1) asm volatile( \
    "mma.sync.aligned.m16n8k16.row.col.f32.bf16.bf16.f32 {%0,%1,%2,%3},{%4,%5,%6,%7},{%8,%9},{%0,%1,%2,%3};" \
    : "+f"((dd)[0]),"+f"((dd)[1]),"+f"((dd)[2]),"+f"((dd)[3]) \
    : "r"((aa)[0]),"r"((aa)[1]),"r"((aa)[2]),"r"((aa)[3]),"r"(b0),"r"(b1))

// ---------------- prologue #1: weight prep + deg zero ----------------
__global__ void k_prep0(const float* __restrict__ root,const float* __restrict__ wih,
                        const float* __restrict__ whh){
    int t=blockIdx.x*blockDim.x+threadIdx.x;    // 448 x 256
    if(t<NN)d_deg[t]=0;
    if(t<7*16384){
        int tt=t>>14, rem=t&16383, n=rem>>7, k=rem&127;
        float v;
        if(tt==0)      v=root[k*128+n];
        else if(tt<4)  v=wih[((tt-1)*128+n)*128+k];
        else           v=whh[((tt-4)*128+n)*128+k];
        __nv_bfloat16 hi=__float2bfloat16(v);
        __nv_bfloat16 lo=__float2bfloat16(v-__bfloat162float(hi));
        d_bwh[t]=hi; d_bwl[t]=lo;
    }
}

// ---------------- prologue #2: fused CSR ----------------
#define CSRB 32
__device__ __forceinline__ void gridbar32(unsigned tgt){
    __syncthreads();
    if(threadIdx.x==0){
        __threadfence();
        unsigned old=atomicAdd(&g_cnt,1u);
        if(old==CSRB-1u){ g_cnt=0u; __threadfence(); atomicAdd(&g_epoch,1u); }
        else { while((int)(*(volatile unsigned*)&g_epoch - tgt) < 0){} }
        __threadfence();
    }
    __syncthreads();
}
__global__ void __launch_bounds__(1024)
k_csr(const int* __restrict__ ei){
    __shared__ unsigned s_ep0;
    if(threadIdx.x==0)s_ep0=*(volatile unsigned*)&g_epoch;
    __syncthreads();
    unsigned ep0=s_ep0;
    int gt=blockIdx.x*1024+threadIdx.x;
    if(gt<NE)atomicAdd(&d_deg[ei[NE+gt]],1);
    gridbar32(ep0+1u);
    if(blockIdx.x==0){
        __shared__ int ws[32];
        int t=threadIdx.x,base=t*8,v[8],pre[8],s=0;
#pragma unroll
        for(int i=0;i<8;i++){v[i]=d_deg[base+i];pre[i]=s;s+=v[i];}
        int lane=t&31,wid=t>>5,xx=s;
#pragma unroll
        for(int o=1;o<32;o<<=1){int y=__shfl_up_sync(~0u,xx,o);if(lane>=o)xx+=y;}
        if(lane==31)ws[wid]=xx;
        __syncthreads();
        if(wid==0){int w0=ws[lane],x2=w0;
#pragma unroll
            for(int o=1;o<32;o<<=1){int y=__shfl_up_sync(~0u,x2,o);if(lane>=o)x2+=y;}
            ws[lane]=x2-w0;}
        __syncthreads();
        int obase=ws[wid]+(xx-s);
#pragma unroll
        for(int i=0;i<8;i++){int o=obase+pre[i];d_off[base+i]=o;d_cur[base+i]=o;
            d_invdeg[base+i]=v[i]>0?1.0f/(float)v[i]:0.0f;}
        if(t==1023)d_off[NN]=obase+s;
    }
    gridbar32(ep0+2u);
    if(gt<NE){int p=atomicAdd(&d_cur[ei[NE+gt]],1);d_csr[p]=gt;}
    gridbar32(ep0+3u);
    if(gt<NN){
        int a=d_off[gt],b=d_off[gt+1];
        for(int i=a+1;i<b;i++){int key=d_csr[i],j=i-1;
            while(j>=a&&d_csr[j]>key){d_csr[j+1]=d_csr[j];j--;}d_csr[j+1]=key;}
    }
}

// ---------------- shared fp32 GEMM inner loop ----------------
__device__ __forceinline__ void f32gemm32(ull acc[4][4],const float* __restrict__ Ab,
                                          const float* __restrict__ Bb){
#pragma unroll 8
    for(int k=0;k<32;k++){
        ulonglong2 A0=*(const ulonglong2*)(Ab+k*ATS);
        ulonglong2 A1=*(const ulonglong2*)(Ab+k*ATS+4);
        float4 b=*(const float4*)(Bb+k*128);
        ull B0=pack2(b.x),B1=pack2(b.y),B2=pack2(b.z),B3=pack2(b.w);
        fma2(acc[0][0],A0.x,B0);fma2(acc[0][1],A0.x,B1);fma2(acc[0][2],A0.x,B2);fma2(acc[0][3],A0.x,B3);
        fma2(acc[1][0],A0.y,B0);fma2(acc[1][1],A0.y,B1);fma2(acc[1][2],A0.y,B2);fma2(acc[1][3],A0.y,B3);
        fma2(acc[2][0],A1.x,B0);fma2(acc[2][1],A1.x,B1);fma2(acc[2][2],A1.x,B2);fma2(acc[2][3],A1.x,B3);
        fma2(acc[3][0],A1.y,B0);fma2(acc[3][1],A1.y,B1);fma2(acc[3][2],A1.y,B2);fma2(acc[3][3],A1.y,B3);
    }
}
#define ZACCU(acc) {_Pragma("unroll") for(int _p=0;_p<4;_p++){_Pragma("unroll") for(int _c=0;_c<4;_c++)(acc)[_p][_c]=0ull;}}

// ---------------- prologue #3: fused block2emb (both layers) ---------------
__global__ void __launch_bounds__(256)
k_b2e(const int* __restrict__ x,const float* __restrict__ embB,
      const float* __restrict__ w1,const float* __restrict__ b1,
      const float* __restrict__ w2,const float* __restrict__ b2){
    __shared__ float At[32*ATS];
    __shared__ float Mt[128*ATS];
    __shared__ float Bp[32*128];
    int t=threadIdx.x,rg=t>>5,cg=t&31;
    int row0=blockIdx.x*64;
    int xi=x[row0+(t&63)];
    ull acc[4][4];
    ZACCU(acc);
    for(int kc=0;kc<128;kc+=32){
        { int rl=t&63,kg=t>>6;const float*src=embB+(size_t)xi*128+kc+kg*8;
          float4 v0=*(const float4*)src,v1=*(const float4*)(src+4);int kb=kg*8;
          At[(kb+0)*ATS+rl]=v0.x;At[(kb+1)*ATS+rl]=v0.y;At[(kb+2)*ATS+rl]=v0.z;At[(kb+3)*ATS+rl]=v0.w;
          At[(kb+4)*ATS+rl]=v1.x;At[(kb+5)*ATS+rl]=v1.y;At[(kb+6)*ATS+rl]=v1.z;At[(kb+7)*ATS+rl]=v1.w;}
        { int j=t>>1,h=t&1;const float*src=w1+(size_t)j*128+kc+h*16;
#pragma unroll
          for(int i=0;i<4;i++){float4 v=*(const float4*)(src+i*4);int kk=h*16+i*4;
              Bp[(kk+0)*128+j]=v.x;Bp[(kk+1)*128+j]=v.y;Bp[(kk+2)*128+j]=v.z;Bp[(kk+3)*128+j]=v.w;}}
        __syncthreads();
        f32gemm32(acc,At+rg*8,Bp+cg*4);
        __syncthreads();
    }
#pragma unroll
    for(int c=0;c<4;c++){
        int j=cg*4+c;float bv=b1[j];
#pragma unroll
        for(int p=0;p<4;p++){
            int r=rg*8+2*p;
            Mt[j*ATS+r]  =lrelu(lo32(acc[p][c])+bv);
            Mt[j*ATS+r+1]=lrelu(hi32(acc[p][c])+bv);
        }
    }
    __syncthreads();
    ZACCU(acc);
    for(int kc=0;kc<128;kc+=32){
        { int j=t>>1,h=t&1;const float*src=w2+(size_t)j*128+kc+h*16;
#pragma unroll
          for(int i=0;i<4;i++){float4 v=*(const float4*)(src+i*4);int kk=h*16+i*4;
              Bp[(kk+0)*128+j]=v.x;Bp[(kk+1)*128+j]=v.y;Bp[(kk+2)*128+j]=v.z;Bp[(kk+3)*128+j]=v.w;}}
        __syncthreads();
        f32gemm32(acc,Mt+kc*ATS+rg*8,Bp+cg*4);
        __syncthreads();
    }
#pragma unroll
    for(int c=0;c<4;c++){
        int j=cg*4+c;float bv=b2[j];
#pragma unroll
        for(int p=0;p<4;p++){
            int r=row0+rg*8+2*p;
            d_h[(size_t)r*128+j]=lo32(acc[p][c])+bv;
            d_h[(size_t)(r+1)*128+j]=hi32(acc[p][c])+bv;
        }
    }
}

// ---------------- fused stem head: cat-gather + 3-layer MLP ----------------
__global__ void __launch_bounds__(256)
k_stem(const int* __restrict__ sni,const int* __restrict__ st,
       const float* __restrict__ h,const float* __restrict__ embS,
       const float* __restrict__ w1,const float* __restrict__ b1,
       const float* __restrict__ w2,const float* __restrict__ b2,
       const float* __restrict__ w3,const float* __restrict__ b3,
       float* __restrict__ out){
    __shared__ float At[32*ATS];
    __shared__ float Mt[128*ATS];
    __shared__ float Bp[32*128];
    int t=threadIdx.x,rg=t>>5,cg=t&31;
    int row0=blockIdx.x*64;
    int xi=sni[row0+(t&63)];
    int si=st[row0+(t&63)];
    ull acc[4][4];
    ZACCU(acc);
    for(int half=0;half<2;half++){
        const float* Abase = half? (embS+(size_t)si*128) : (h+(size_t)xi*128);
        int koff=half*128;
        for(int kc=0;kc<128;kc+=32){
            { int rl=t&63,kg=t>>6;const float*src=Abase+kc+kg*8;
              float4 v0=*(const float4*)src,v1=*(const float4*)(src+4);int kb=kg*8;
              At[(kb+0)*ATS+rl]=v0.x;At[(kb+1)*ATS+rl]=v0.y;At[(kb+2)*ATS+rl]=v0.z;At[(kb+3)*ATS+rl]=v0.w;
              At[(kb+4)*ATS+rl]=v1.x;At[(kb+5)*ATS+rl]=v1.y;At[(kb+6)*ATS+rl]=v1.z;At[(kb+7)*ATS+rl]=v1.w;}
            { int j=t>>1,hh=t&1;const float*src=w1+(size_t)j*256+koff+kc+hh*16;
#pragma unroll
              for(int i=0;i<4;i++){float4 v=*(const float4*)(src+i*4);int kk=hh*16+i*4;
                  Bp[(kk+0)*128+j]=v.x;Bp[(kk+1)*128+j]=v.y;Bp[(kk+2)*128+j]=v.z;Bp[(kk+3)*128+j]=v.w;}}
            __syncthreads();
            f32gemm32(acc,At+rg*8,Bp+cg*4);
            __syncthreads();
        }
    }
#pragma unroll
    for(int c=0;c<4;c++){
        int j=cg*4+c;float bv=b1[j];
#pragma unroll
        for(int p=0;p<4;p++){
            int r=rg*8+2*p;
            Mt[j*ATS+r]  =lrelu(lo32(acc[p][c])+bv);
            Mt[j*ATS+r+1]=lrelu(hi32(acc[p][c])+bv);
        }
    }
    __syncthreads();
    ZACCU(acc);
    for(int kc=0;kc<128;kc+=32){
        { int j=t>>1,hh=t&1;const float*src=w2+(size_t)j*128+kc+hh*16;
#pragma unroll
          for(int i=0;i<4;i++){float4 v=*(const float4*)(src+i*4);int kk=hh*16+i*4;
              Bp[(kk+0)*128+j]=v.x;Bp[(kk+1)*128+j]=v.y;Bp[(kk+2)*128+j]=v.z;Bp[(kk+3)*128+j]=v.w;}}
        __syncthreads();
        f32gemm32(acc,Mt+kc*ATS+rg*8,Bp+cg*4);
        __syncthreads();
    }
#pragma unroll
    for(int c=0;c<4;c++){
        int j=cg*4+c;float bv=b2[j];
#pragma unroll
        for(int p=0;p<4;p++){
            int r=rg*8+2*p;
            Mt[j*ATS+r]  =lrelu(lo32(acc[p][c])+bv);
            Mt[j*ATS+r+1]=lrelu(hi32(acc[p][c])+bv);
        }
    }
    __syncthreads();
    ZACCU(acc);
    for(int kc=0;kc<128;kc+=32){
        { int j=t>>1,hh=t&1;
          if(j<OPS){const float*src=w3+(size_t)j*128+kc+hh*16;
#pragma unroll
              for(int i=0;i<4;i++){float4 v=*(const float4*)(src+i*4);int kk=hh*16+i*4;
                  Bp[(kk+0)*128+j]=v.x;Bp[(kk+1)*128+j]=v.y;Bp[(kk+2)*128+j]=v.z;Bp[(kk+3)*128+j]=v.w;}
          }else{
#pragma unroll
              for(int i=0;i<16;i++)Bp[(hh*16+i)*128+j]=0.f;}}
        __syncthreads();
        f32gemm32(acc,Mt+kc*ATS+rg*8,Bp+cg*4);
        __syncthreads();
    }
#pragma unroll
    for(int c=0;c<4;c++){
        int j=cg*4+c;if(j>=OPS)continue;
        float bv=b3[j];
#pragma unroll
        for(int p=0;p<4;p++){
            int r=row0+rg*8+2*p;
            out[(size_t)r*OPS+j]=lo32(acc[p][c])+bv;
            out[(size_t)(r+1)*OPS+j]=hi32(acc[p][c])+bv;
        }
    }
}

// ---------------- fused stop head: pool + MLP + dot ----------------
__global__ void __launch_bounds__(128)
k_stoph(const int* __restrict__ nb,const float* __restrict__ w1,const float* __restrict__ b1,
        const float* __restrict__ w2,const float* __restrict__ b2,float* __restrict__ out){
    __shared__ float gm[128], s1[128];
    int g=blockIdx.x,c=threadIdx.x;
    int lo=0,hi=NN;while(lo<hi){int m=(lo+hi)>>1;if(nb[m]<g)lo=m+1;else hi=m;}
    int s=lo;lo=0;hi=NN;while(lo<hi){int m=(lo+hi)>>1;if(nb[m]<=g)lo=m+1;else hi=m;}
    int e=lo;float sum=0.f;
    for(int r=s;r<e;r++)sum+=d_h[(size_t)r*128+c];
    gm[c]=sum/fmaxf((float)(e-s),1.f);
    __syncthreads();
    float a=b1[c];
    const float* wr=w1+(size_t)c*128;
    for(int k=0;k<128;k++)a+=gm[k]*wr[k];
    s1[c]=lrelu(a)*w2[c];
    __syncthreads();
    if(c<64)s1[c]+=s1[c+64];
    __syncthreads();
    if(c<32){
        float v=s1[c]+s1[c+32];
#pragma unroll
        for(int o=16;o>0;o>>=1)v+=__shfl_xor_sync(~0u,v,o);
        if(c==0)out[(size_t)NS*OPS+g]=v+b2[0];
    }
}

// ---------------- mma.sync fused conv step: gates in registers ----------
#define SB0H 0
#define SB0L 34816
#define SB1H 69632
#define SB1L 104448
#define SHH  139264
#define SHL  156672
#define SMH  174080
#define SML  191488
#define SBI  208896
#define SMT  212480
#define STRB 272
#define NTH  512

__device__ __forceinline__ void stageT(uint32_t sH,uint32_t sL,int tile,int tid){
    const char* gh=(const char*)(d_bwh+tile*16384);
    const char* gl=(const char*)(d_bwl+tile*16384);
#pragma unroll
    for(int q=0;q<4;q++){
        int i=tid+q*NTH, n=i>>4, c=i&15;
        CP16(sH+n*STRB+c*16, gh+n*256+c*16);
        CP16(sL+n*STRB+c*16, gl+n*256+c*16);
    }
    CPCOMMIT();
}

__device__ __forceinline__ void gemm_s(float acc[4][4],uint32_t atH,uint32_t atL,
                                       uint32_t bh,uint32_t bl,int bt){
#pragma unroll
    for(int kc=0;kc<8;kc++){
        uint32_t aH[4],aL[4];
        LDSM4(aH[0],aH[1],aH[2],aH[3],atH+kc*32);
        LDSM4(aL[0],aL[1],aL[2],aL[3],atL+kc*32);
#pragma unroll
        for(int jj=0;jj<2;jj++){
            uint32_t h0,h1,h2,h3,l0,l1,l2,l3;
            uint32_t off=jj*4352+kc*32+bt;
            LDSM4(h0,h1,h2,h3,bh+off);
            LDSM4(l0,l1,l2,l3,bl+off);
            MMA(acc[2*jj],  aH,h0,h1);
            MMA(acc[2*jj+1],aH,h2,h3);
            MMA(acc[2*jj],  aL,h0,h1);
            MMA(acc[2*jj+1],aL,h2,h3);
            MMA(acc[2*jj],  aH,l0,l1);
            MMA(acc[2*jj+1],aH,l2,l3);
        }
    }
}
#define ZACC4(acc) {_Pragma("unroll") for(int _n=0;_n<4;_n++){_Pragma("unroll") for(int _d=0;_d<4;_d++)(acc)[_n][_d]=0.f;}}

__global__ void __launch_bounds__(NTH,1)
k_step_mma(const float* __restrict__ hin, float* __restrict__ hout,
           const int* __restrict__ ei, const int* __restrict__ ea,
           const float* __restrict__ embBond,
           const float* __restrict__ cbias,
           const float* __restrict__ bih, const float* __restrict__ bhh){
    extern __shared__ char smem[];
    uint32_t sb=s2u(smem);
    float* sbias=(float*)(smem+SBI);
    int tid=threadIdx.x, w=tid>>5, lane=tid&31;
    int row0=blockIdx.x*64;
    int wr=w&3, cg=w>>2, nt0=cg*4;
    int bt=nt0*2176+((lane>>3)>>1)*2176+(lane&7)*STRB+((lane>>3)&1)*16;
    int rl=16*wr+(lane>>2);
    uint32_t atoff=(uint32_t)(16*wr+((lane>>3)&1)*8+(lane&7))*STRB+(uint32_t)(lane>>4)*16;
    uint32_t ahH=sb+SHH+atoff, ahL=sb+SHL+atoff;
    uint32_t amH=sb+SMH+atoff, amL=sb+SML+atoff;

    for(int i=tid;i<384;i+=NTH){sbias[i]=bih[i];sbias[384+i]=bhh[i];}
    if(tid<128)sbias[768+tid]=cbias[tid];

    stageT(sb+SB0H,sb+SB0L,0,tid);   // rootT

    {
        int r=tid>>3, c0=(tid&7)*16;
        const float* src=hin+(size_t)(row0+r)*D+c0;
        uint32_t base=(uint32_t)r*STRB+(uint32_t)c0*2;
#pragma unroll
        for(int i=0;i<4;i++){
            float4 v=*(const float4*)(src+i*4);
            uint32_t p0=pkbf(v.x,v.y), p1=pkbf(v.z,v.w);
            uint32_t q0=pkbf(v.x-upbf(p0,0),v.y-upbf(p0,1));
            uint32_t q1=pkbf(v.z-upbf(p1,0),v.w-upbf(p1,1));
            *(uint32_t*)(smem+SHH+base+i*8)  =p0;
            *(uint32_t*)(smem+SHH+base+i*8+4)=p1;
            *(uint32_t*)(smem+SHL+base+i*8)  =q0;
            *(uint32_t*)(smem+SHL+base+i*8+4)=q1;
        }
    }

#pragma unroll 1
    for(int q=0;q<4;q++){
        int n=row0+4*w+q;
        int s0=d_off[n],s1=d_off[n+1];
        float4 acc4=make_float4(0.f,0.f,0.f,0.f);
        for(int i=s0;i<s1;i++){
            int e=d_csr[i];
            int s=ei[e],a0=ea[2*e],a1=ea[2*e+1];
            float4 hv=*(const float4*)(hin+(size_t)s*D+lane*4);
            float4 b0=*(const float4*)(embBond+(size_t)a0*D+lane*4);
            float p=hv.x*b0.x+hv.y*b0.y+hv.z*b0.z+hv.w*b0.w;
#pragma unroll
            for(int o=16;o>0;o>>=1)p+=__shfl_xor_sync(~0u,p,o);
            float4 b1=*(const float4*)(embBond+(size_t)a1*D+lane*4);
            acc4.x+=p*b1.x;acc4.y+=p*b1.y;acc4.z+=p*b1.z;acc4.w+=p*b1.w;
        }
        float iv=d_invdeg[n];
        acc4.x*=iv;acc4.y*=iv;acc4.z*=iv;acc4.w*=iv;
        *(float4*)(d_agg+(size_t)n*D+lane*4)=acc4;
    }

    float acc[4][4];
    float gt[4][4];           // gate scratch in registers
    // ---- P1: conv = lrelu(h@root + agg + cbias) -> m tiles ----
    CPWAIT(); __syncthreads();
    stageT(sb+SB1H,sb+SB1L,1,tid);               // wih_r
    ZACC4(acc);
    gemm_s(acc,ahH,ahL,sb+SB0H,sb+SB0L,bt);
    {
#pragma unroll
        for(int n=0;n<4;n++){
            int colg=(nt0+n)*8+(lane&3)*2;
            float2 a0=*(const float2*)(d_agg+(size_t)(row0+rl)*D+colg);
            float2 a1=*(const float2*)(d_agg+(size_t)(row0+rl+8)*D+colg);
            float b0v=sbias[768+colg],b1v=sbias[768+colg+1];
            float m00=lrelu(acc[n][0]+a0.x+b0v), m01=lrelu(acc[n][1]+a0.y+b1v);
            float m10=lrelu(acc[n][2]+a1.x+b0v), m11=lrelu(acc[n][3]+a1.y+b1v);
            uint32_t p0=pkbf(m00,m01), p1=pkbf(m10,m11);
            uint32_t q0=pkbf(m00-upbf(p0,0),m01-upbf(p0,1));
            uint32_t q1=pkbf(m10-upbf(p1,0),m11-upbf(p1,1));
            *(uint32_t*)(smem+SMH+rl*STRB+colg*2)=p0;
            *(uint32_t*)(smem+SMH+(rl+8)*STRB+colg*2)=p1;
            *(uint32_t*)(smem+SML+rl*STRB+colg*2)=q0;
            *(uint32_t*)(smem+SML+(rl+8)*STRB+colg*2)=q1;
        }
    }
    // ---- P2: m@wih_r ----
    CPWAIT(); __syncthreads();
    stageT(sb+SB0H,sb+SB0L,4,tid);               // whh_r
    ZACC4(acc);
    gemm_s(acc,amH,amL,sb+SB1H,sb+SB1L,bt);
    // ---- P3: + h@whh_r -> r gate (regs) ----
    CPWAIT(); __syncthreads();
    stageT(sb+SB1H,sb+SB1L,6,tid);               // whh_n
    gemm_s(acc,ahH,ahL,sb+SB0H,sb+SB0L,bt);
#pragma unroll
    for(int n=0;n<4;n++)
#pragma unroll
    for(int dg=0;dg<4;dg++){
        int col=(nt0+n)*8+(lane&3)*2+(dg&1);
        gt[n][dg]=sigm(acc[n][dg]+sbias[col]+sbias[384+col]);
    }
    // ---- P4: h@whh_n -> gt = r*(hn+bhh_n) ----
    CPWAIT(); __syncthreads();
    stageT(sb+SB0H,sb+SB0L,3,tid);               // wih_n
    ZACC4(acc);
    gemm_s(acc,ahH,ahL,sb+SB1H,sb+SB1L,bt);
#pragma unroll
    for(int n=0;n<4;n++)
#pragma unroll
    for(int dg=0;dg<4;dg++){
        int col=(nt0+n)*8+(lane&3)*2+(dg&1);
        gt[n][dg]=gt[n][dg]*(acc[n][dg]+sbias[640+col]);
    }
    // ---- P5: m@wih_n -> gt = tanh(in+bih_n+gt) ----
    CPWAIT(); __syncthreads();
    stageT(sb+SB1H,sb+SB1L,2,tid);               // wih_z
    ZACC4(acc);
    gemm_s(acc,amH,amL,sb+SB0H,sb+SB0L,bt);
#pragma unroll
    for(int n=0;n<4;n++)
#pragma unroll
    for(int dg=0;dg<4;dg++){
        int col=(nt0+n)*8+(lane&3)*2+(dg&1);
        gt[n][dg]=tanhfast(acc[n][dg]+sbias[256+col]+gt[n][dg]);
    }
    // ---- P6: m@wih_z ----
    CPWAIT(); __syncthreads();
    stageT(sb+SB0H,sb+SB0L,5,tid);               // whh_z
    ZACC4(acc);
    gemm_s(acc,amH,amL,sb+SB1H,sb+SB1L,bt);
    // ---- P7: + h@whh_z -> z gate + update ----
    CPWAIT(); __syncthreads();
    gemm_s(acc,ahH,ahL,sb+SB0H,sb+SB0L,bt);
    {
        int rbase=row0+rl;
#pragma unroll
        for(int n=0;n<4;n++){
            int nt=nt0+n;
            float o[4];
#pragma unroll
            for(int dg=0;dg<4;dg++){
                int col=nt*8+(lane&3)*2+(dg&1);
                int r2=rl+(dg>>1)*8;
                float hv=__bfloat162float(*(__nv_bfloat16*)(smem+SHH+r2*STRB+col*2))
                        +__bfloat162float(*(__nv_bfloat16*)(smem+SHL+r2*STRB+col*2));
                float z=sigm(acc[n][dg]+sbias[128+col]+sbias[512+col]);
                float nv=gt[n][dg];
                o[dg]=(1.f-z)*nv+z*hv;
            }
            int c0=nt*8+(lane&3)*2;
            *(float2*)(hout+(size_t)rbase*D+c0)    =make_float2(o[0],o[1]);
            *(float2*)(hout+(size_t)(rbase+8)*D+c0)=make_float2(o[2],o[3]);
        }
    }
}

// ---------------- launch ----------------
extern "C" void kernel_launch(void* const* d_in,const int* in_sizes,int n_in,
                              void* d_out,int out_size){
    const int* x   =(const int*)d_in[0];
    const int* st  =(const int*)d_in[1];
    const int* ea  =(const int*)d_in[2];
    const int* ei  =(const int*)d_in[3];
    const int* sni =(const int*)d_in[4];
    const int* nb  =(const int*)d_in[5];
    const float* embB=(const float*)d_in[6];
    const float* embS=(const float*)d_in[7];
    const float* embBond=(const float*)d_in[8];
    const float* b2e_w1=(const float*)d_in[9],  *b2e_b1=(const float*)d_in[10];
    const float* b2e_w2=(const float*)d_in[11], *b2e_b2=(const float*)d_in[12];
    const float* conv_root=(const float*)d_in[13], *conv_bias=(const float*)d_in[14];
    const float* w_ih=(const float*)d_in[15], *w_hh=(const float*)d_in[16];
    const float* b_ih=(const float*)d_in[17], *b_hh=(const float*)d_in[18];
    const float* s2p_w1=(const float*)d_in[19], *s2p_b1=(const float*)d_in[20];
    const float* s2p_w2=(const float*)d_in[21], *s2p_b2=(const float*)d_in[22];
    const float* s2p_w3=(const float*)d_in[23], *s2p_b3=(const float*)d_in[24];
    const float* g2p_w1=(const float*)d_in[25], *g2p_b1=(const float*)d_in[26];
    const float* g2p_w2=(const float*)d_in[27], *g2p_b2=(const float*)d_in[28];
    float* out=(float*)d_out;

    void* p;
    cudaGetSymbolAddress(&p,d_h);   float* ph =(float*)p;
    cudaGetSymbolAddress(&p,d_h2);  float* ph2=(float*)p;

    static int attr_set=0;
    if(!attr_set){
        cudaFuncSetAttribute(k_step_mma,cudaFuncAttributeMaxDynamicSharedMemorySize,SMT);
        attr_set=1;
    }

    // 3 prologue launches -> step #1 stays at ncu slot 6
    k_prep0<<<448,256>>>(conv_root,w_ih,w_hh);
    k_csr  <<<CSRB,1024>>>(ei);
    k_b2e  <<<NN/64,256>>>(x,embB,b2e_w1,b2e_b1,b2e_w2,b2e_b2);

    for(int s=0;s<NSTEPS;s++){
        const float* hi=(s&1)?ph2:ph;
        float* ho=(s&1)?ph:ph2;
        k_step_mma<<<NN/64,NTH,SMT>>>(hi,ho,ei,ea,embBond,conv_bias,b_ih,b_hh);
    }

    // fused heads
    k_stem <<<NS/64,256>>>(sni,st,ph,embS,s2p_w1,s2p_b1,s2p_w2,s2p_b2,s2p_w3,s2p_b3,out);
    k_stoph<<<NG,128>>>(nb,g2p_w1,g2p_b1,g2p_w2,g2p_b2,out);
}